// round 1
// baseline (speedup 1.0000x reference)
#include <cuda_runtime.h>
#include <math.h>

// Problem dims
#define NB   2048
#define NH   16384
#define NE   64
#define DIN  384
#define NKD  128
#define NVD  128
#define NHD  256
#define NSPLIT_G 8
#define NSPLIT_K 8

// ---------------- scratch (device globals; no allocation allowed) ----------------
__device__ float g_k[NB*NKD];
__device__ float g_v[NB*NVD];
__device__ float g_h[NB*NHD];
__device__ float g_dpred[NB*NVD];
__device__ float g_dh[NB*NHD];
__device__ float g_gW1p[NSPLIT_G*NHD*NKD];
__device__ float g_gW2p[NSPLIT_G*NVD*NHD];
__device__ float g_gW1[NHD*NKD];
__device__ float g_gb1[NHD];
__device__ float g_gW2[NVD*NHD];
__device__ float g_gb2[NVD];
__device__ float g_nW1[NHD*NKD];
__device__ float g_nb1[NHD];
__device__ float g_nW2[NVD*NHD];
__device__ float g_nb2[NVD];
__device__ float g_h2[NB*NHD];
__device__ float g_ctx[NB*NVD];
__device__ float g_q[NB*DIN];
__device__ float g_kh[NH*DIN];
__device__ float g_S[33554432];           // 2048*16384 = 134 MB
__device__ float g_aop[NSPLIT_K*NB*DIN];  // split-K partials of attn@hist
__device__ float g_ao[NB*DIN];
__device__ float g_st[NB*NVD];
__device__ float g_theta[1];
__device__ float g_ectx[NVD];
__device__ float g_eg[1];

// ================= generic tiled GEMMs (fp32) =================
// C[M,N] = A[M,K] @ B[N,K]^T  (+bias[N], optional relu). Requires M%64==0, N%64==0, K%16==0.
template<bool BIAS, bool RELU>
__launch_bounds__(256)
__global__ void gemm_abT(const float* __restrict__ A, const float* __restrict__ Bm,
                         const float* __restrict__ bias, float* __restrict__ C,
                         int M, int N, int K)
{
    __shared__ float As[16][64];
    __shared__ float Bs[16][64];
    const int t  = threadIdx.x;
    const int tx = t & 15, ty = t >> 4;
    const int m0 = blockIdx.y * 64, n0 = blockIdx.x * 64;
    const int lr = t >> 2;              // 0..63
    const int lc = (t & 3) << 2;        // 0,4,8,12
    float acc[4][4] = {};
    const float* Ag = A  + (size_t)(m0 + lr) * K + lc;
    const float* Bg = Bm + (size_t)(n0 + lr) * K + lc;
    for (int k0 = 0; k0 < K; k0 += 16) {
        float4 a4 = *(const float4*)(Ag + k0);
        float4 b4 = *(const float4*)(Bg + k0);
        As[lc+0][lr]=a4.x; As[lc+1][lr]=a4.y; As[lc+2][lr]=a4.z; As[lc+3][lr]=a4.w;
        Bs[lc+0][lr]=b4.x; Bs[lc+1][lr]=b4.y; Bs[lc+2][lr]=b4.z; Bs[lc+3][lr]=b4.w;
        __syncthreads();
        #pragma unroll
        for (int kk = 0; kk < 16; kk++) {
            float4 av = *(const float4*)&As[kk][ty<<2];
            float4 bv = *(const float4*)&Bs[kk][tx<<2];
            acc[0][0]+=av.x*bv.x; acc[0][1]+=av.x*bv.y; acc[0][2]+=av.x*bv.z; acc[0][3]+=av.x*bv.w;
            acc[1][0]+=av.y*bv.x; acc[1][1]+=av.y*bv.y; acc[1][2]+=av.y*bv.z; acc[1][3]+=av.y*bv.w;
            acc[2][0]+=av.z*bv.x; acc[2][1]+=av.z*bv.y; acc[2][2]+=av.z*bv.z; acc[2][3]+=av.z*bv.w;
            acc[3][0]+=av.w*bv.x; acc[3][1]+=av.w*bv.y; acc[3][2]+=av.w*bv.z; acc[3][3]+=av.w*bv.w;
        }
        __syncthreads();
    }
    #pragma unroll
    for (int u = 0; u < 4; u++) {
        float4 o;
        float* oc = (float*)&o;
        #pragma unroll
        for (int v = 0; v < 4; v++) {
            float val = acc[u][v];
            if (BIAS) val += bias[n0 + (tx<<2) + v];
            if (RELU) val = fmaxf(val, 0.f);
            oc[v] = val;
        }
        *(float4*)&C[(size_t)(m0 + (ty<<2) + u) * N + n0 + (tx<<2)] = o;
    }
}

// C[M,N] = A[M,K] @ B[K,N]. Optional relu-mask (C=0 where mask<=0). gridDim.z splits K:
// block z handles k in [z*Kchunk, (z+1)*Kchunk), writes slab C + z*M*N (Kchunk%16==0).
template<bool MASK>
__launch_bounds__(256)
__global__ void gemm_ab(const float* __restrict__ A, const float* __restrict__ Bm,
                        const float* __restrict__ mask, float* __restrict__ C,
                        int M, int N, int K, int Kchunk)
{
    __shared__ float As[16][64];
    __shared__ float Bs[16][64];
    const int t  = threadIdx.x;
    const int tx = t & 15, ty = t >> 4;
    const int m0 = blockIdx.y * 64, n0 = blockIdx.x * 64;
    const int kbeg = blockIdx.z * Kchunk, kend = kbeg + Kchunk;
    const int lrA = t >> 2,  lcA = (t & 3)  << 2;   // A tile: 64 rows x 16 cols (transpose-store)
    const int lrB = t >> 4,  lcB = (t & 15) << 2;   // B tile: 16 rows x 64 cols (direct)
    float acc[4][4] = {};
    for (int k0 = kbeg; k0 < kend; k0 += 16) {
        float4 a4 = *(const float4*)&A [(size_t)(m0 + lrA) * K + k0 + lcA];
        float4 b4 = *(const float4*)&Bm[(size_t)(k0 + lrB) * N + n0 + lcB];
        As[lcA+0][lrA]=a4.x; As[lcA+1][lrA]=a4.y; As[lcA+2][lrA]=a4.z; As[lcA+3][lrA]=a4.w;
        *(float4*)&Bs[lrB][lcB] = b4;
        __syncthreads();
        #pragma unroll
        for (int kk = 0; kk < 16; kk++) {
            float4 av = *(const float4*)&As[kk][ty<<2];
            float4 bv = *(const float4*)&Bs[kk][tx<<2];
            acc[0][0]+=av.x*bv.x; acc[0][1]+=av.x*bv.y; acc[0][2]+=av.x*bv.z; acc[0][3]+=av.x*bv.w;
            acc[1][0]+=av.y*bv.x; acc[1][1]+=av.y*bv.y; acc[1][2]+=av.y*bv.z; acc[1][3]+=av.y*bv.w;
            acc[2][0]+=av.z*bv.x; acc[2][1]+=av.z*bv.y; acc[2][2]+=av.z*bv.z; acc[2][3]+=av.z*bv.w;
            acc[3][0]+=av.w*bv.x; acc[3][1]+=av.w*bv.y; acc[3][2]+=av.w*bv.z; acc[3][3]+=av.w*bv.w;
        }
        __syncthreads();
    }
    float* Co = C + (size_t)blockIdx.z * M * N;
    #pragma unroll
    for (int u = 0; u < 4; u++) {
        const int m = m0 + (ty<<2) + u;
        float4 o;
        float* oc = (float*)&o;
        #pragma unroll
        for (int v = 0; v < 4; v++) {
            float val = acc[u][v];
            if (MASK) val = (mask[(size_t)m * N + n0 + (tx<<2) + v] > 0.f) ? val : 0.f;
            oc[v] = val;
        }
        *(float4*)&Co[(size_t)m * N + n0 + (tx<<2)] = o;
    }
}

// C[M,N] = A[L,M]^T @ B[L,N], L-split over gridDim.z into partial slabs. L%16==0 per chunk.
__launch_bounds__(256)
__global__ void gemm_aTb(const float* __restrict__ A, const float* __restrict__ Bm,
                         float* __restrict__ Cpart, int L, int M, int N, int Lchunk)
{
    __shared__ float As[16][64];
    __shared__ float Bs[16][64];
    const int t  = threadIdx.x;
    const int tx = t & 15, ty = t >> 4;
    const int m0 = blockIdx.y * 64, n0 = blockIdx.x * 64;
    const int l0b = blockIdx.z * Lchunk;
    const int lr = t >> 4, lc4 = (t & 15) << 2;   // 16 x 64 tiles, both direct
    float acc[4][4] = {};
    for (int l0 = l0b; l0 < l0b + Lchunk; l0 += 16) {
        *(float4*)&As[lr][lc4] = *(const float4*)&A [(size_t)(l0 + lr) * M + m0 + lc4];
        *(float4*)&Bs[lr][lc4] = *(const float4*)&Bm[(size_t)(l0 + lr) * N + n0 + lc4];
        __syncthreads();
        #pragma unroll
        for (int kk = 0; kk < 16; kk++) {
            float4 av = *(const float4*)&As[kk][ty<<2];
            float4 bv = *(const float4*)&Bs[kk][tx<<2];
            acc[0][0]+=av.x*bv.x; acc[0][1]+=av.x*bv.y; acc[0][2]+=av.x*bv.z; acc[0][3]+=av.x*bv.w;
            acc[1][0]+=av.y*bv.x; acc[1][1]+=av.y*bv.y; acc[1][2]+=av.y*bv.z; acc[1][3]+=av.y*bv.w;
            acc[2][0]+=av.z*bv.x; acc[2][1]+=av.z*bv.y; acc[2][2]+=av.z*bv.z; acc[2][3]+=av.z*bv.w;
            acc[3][0]+=av.w*bv.x; acc[3][1]+=av.w*bv.y; acc[3][2]+=av.w*bv.z; acc[3][3]+=av.w*bv.w;
        }
        __syncthreads();
    }
    float* Co = Cpart + (size_t)blockIdx.z * M * N;
    #pragma unroll
    for (int u = 0; u < 4; u++) {
        float4 o;
        float* oc = (float*)&o;
        #pragma unroll
        for (int v = 0; v < 4; v++) oc[v] = acc[u][v];
        *(float4*)&Co[(size_t)(m0 + (ty<<2) + u) * N + n0 + (tx<<2)] = o;
    }
}

// ================= small kernels =================
__global__ void combine_k(const float* __restrict__ parts, float* __restrict__ out,
                          int len, int np)
{
    int i = blockIdx.x * 256 + threadIdx.x;
    if (i < len) {
        float s = 0.f;
        for (int p = 0; p < np; p++) s += parts[(size_t)p * len + i];
        out[i] = s;
    }
}

__global__ void colsum_k(const float* __restrict__ A, float* __restrict__ out, int rows, int N)
{
    int c = threadIdx.x;
    float s = 0.f;
    for (int r = 0; r < rows; r++) s += A[(size_t)r * N + c];
    out[c] = s;
}

__global__ void dpred_k(float* __restrict__ dp, const float* __restrict__ v, int n, float scale)
{
    int i = blockIdx.x * 256 + threadIdx.x;
    if (i < n) dp[i] = (dp[i] - v[i]) * scale;
}

__global__ void surprise_k()
{
    __shared__ float red[256];
    int t = threadIdx.x;
    float s = 0.f;
    for (int i = t; i < NHD*NKD; i += 256) { float g = g_gW1[i]; s += g*g; }
    for (int i = t; i < NHD;     i += 256) { float g = g_gb1[i]; s += g*g; }
    for (int i = t; i < NVD*NHD; i += 256) { float g = g_gW2[i]; s += g*g; }
    for (int i = t; i < NVD;     i += 256) { float g = g_gb2[i]; s += g*g; }
    red[t] = s; __syncthreads();
    for (int st = 128; st > 0; st >>= 1) { if (t < st) red[t] += red[t+st]; __syncthreads(); }
    if (t == 0) {
        float avg = sqrtf(red[0] * 0.25f);
        g_theta[0] = 0.1f / (1.f + expf(-avg));   // THETA * sigmoid(avg_surprise)
    }
}

__global__ void update_k(const float* __restrict__ mW1, const float* __restrict__ mb1,
                         const float* __restrict__ mW2, const float* __restrict__ mb2,
                         const float* __restrict__ bW1, const float* __restrict__ bb1,
                         const float* __restrict__ bW2, const float* __restrict__ bb2)
{
    int i = blockIdx.x * 256 + threadIdx.x;
    float et = g_theta[0];
    const int n1 = NHD*NKD, n2 = n1 + NHD, n3 = n2 + NVD*NHD, n4 = n3 + NVD;
    // new_p = (1-ALPHA)*p + ETA*buf - eff_theta*g = 0.9p + 0.9buf - et*g
    if (i < n1)       g_nW1[i]   = 0.9f*mW1[i]   + 0.9f*bW1[i]   - et*g_gW1[i];
    else if (i < n2) { int j=i-n1; g_nb1[j] = 0.9f*mb1[j] + 0.9f*bb1[j] - et*g_gb1[j]; }
    else if (i < n3) { int j=i-n2; g_nW2[j] = 0.9f*mW2[j] + 0.9f*bW2[j] - et*g_gW2[j]; }
    else if (i < n4) { int j=i-n3; g_nb2[j] = 0.9f*mb2[j] + 0.9f*bb2[j] - et*g_gb2[j]; }
}

__launch_bounds__(256)
__global__ void softmax_k()
{
    float* row = g_S + (size_t)blockIdx.x * NH;
    const int t = threadIdx.x;
    float v[64];
    float m = -1e30f;
    #pragma unroll
    for (int j = 0; j < 64; j++) { v[j] = row[t + 256*j]; m = fmaxf(m, v[j]); }
    __shared__ float red[256];
    red[t] = m; __syncthreads();
    #pragma unroll
    for (int s = 128; s > 0; s >>= 1) { if (t < s) red[t] = fmaxf(red[t], red[t+s]); __syncthreads(); }
    m = red[0]; __syncthreads();
    float l = 0.f;
    #pragma unroll
    for (int j = 0; j < 64; j++) { v[j] = __expf(v[j] - m); l += v[j]; }
    red[t] = l; __syncthreads();
    #pragma unroll
    for (int s = 128; s > 0; s >>= 1) { if (t < s) red[t] += red[t+s]; __syncthreads(); }
    float inv = 1.f / red[0];
    #pragma unroll
    for (int j = 0; j < 64; j++) row[t + 256*j] = v[j] * inv;
}

__global__ void entity_k(const float* __restrict__ ent, const float* __restrict__ Wep,
                         const float* __restrict__ bep, const float* __restrict__ Weg,
                         const float* __restrict__ beg)
{
    __shared__ float eavg[DIN];
    __shared__ float ectx[NVD];
    int t = threadIdx.x;   // 384 threads
    float s = 0.f;
    for (int e = 0; e < NE; e++) s += ent[e*DIN + t];
    eavg[t] = s * (1.f / NE);
    __syncthreads();
    if (t < NVD) {
        float c = bep[t];
        for (int d = 0; d < DIN; d++) c += eavg[d] * Wep[t*DIN + d];
        ectx[t] = c; g_ectx[t] = c;
    }
    __syncthreads();
    if (t == 0) {
        float g = beg[0];
        for (int j = 0; j < NVD; j++) g += ectx[j] * Weg[j];
        g_eg[0] = 1.f / (1.f + expf(-g));
    }
}

__global__ void fuse_k(const float* __restrict__ kvec, const float* __restrict__ Wg,
                       const float* __restrict__ bg, float* __restrict__ out)
{
    int b = blockIdx.x, i = threadIdx.x;   // 128 threads
    float p = g_ctx[b*NVD + i] + kvec[i];  // persistent_out
    float s = p * Wg[i];
    #pragma unroll
    for (int o = 16; o > 0; o >>= 1) s += __shfl_down_sync(0xffffffffu, s, o);
    __shared__ float wsum[4];
    __shared__ float gsh;
    if ((i & 31) == 0) wsum[i >> 5] = s;
    __syncthreads();
    if (i == 0) {
        float tot = wsum[0] + wsum[1] + wsum[2] + wsum[3] + bg[0];
        gsh = 1.f / (1.f + expf(-tot));
    }
    __syncthreads();
    float gate = gsh;
    float f = gate * p + (1.f - gate) * g_st[b*NVD + i];
    float eg = g_eg[0];
    out[b*NVD + i] = eg * g_ectx[i] + (1.f - eg) * f;
}

// ================= host =================
extern "C" void kernel_launch(void* const* d_in, const int* in_sizes, int n_in,
                              void* d_out, int out_size)
{
    const float* x     = (const float*)d_in[0];
    const float* hist  = (const float*)d_in[1];
    const float* ent   = (const float*)d_in[2];
    const float* W_K   = (const float*)d_in[3];
    const float* W_V   = (const float*)d_in[4];
    const float* mW1   = (const float*)d_in[5];
    const float* mb1   = (const float*)d_in[6];
    const float* mW2   = (const float*)d_in[7];
    const float* mb2   = (const float*)d_in[8];
    const float* bufW1 = (const float*)d_in[9];
    const float* bufb1 = (const float*)d_in[10];
    const float* bufW2 = (const float*)d_in[11];
    const float* bufb2 = (const float*)d_in[12];
    const float* kvec  = (const float*)d_in[13];
    const float* Wq    = (const float*)d_in[14];
    const float* Wk    = (const float*)d_in[15];
    const float* Wst   = (const float*)d_in[16];
    const float* bst   = (const float*)d_in[17];
    const float* Wg    = (const float*)d_in[18];
    const float* bg    = (const float*)d_in[19];
    // d_in[20..23] (Wgt,bgt,Wip,bip) only feed gating_loss -> dead, skipped
    const float* Wep   = (const float*)d_in[24];
    const float* bep   = (const float*)d_in[25];
    const float* Weg   = (const float*)d_in[26];
    const float* beg   = (const float*)d_in[27];
    float* out = (float*)d_out;

    float *pk,*pv,*ph,*pdp,*pdh,*pgW1p,*pgW2p,*pgW1,*pgb1,*pgW2,*pgb2;
    float *pnW1,*pnb1,*pnW2,*pnb2,*ph2,*pctx,*pq,*pkh,*pS,*paop,*pao,*pst;
    cudaGetSymbolAddress((void**)&pk,   g_k);
    cudaGetSymbolAddress((void**)&pv,   g_v);
    cudaGetSymbolAddress((void**)&ph,   g_h);
    cudaGetSymbolAddress((void**)&pdp,  g_dpred);
    cudaGetSymbolAddress((void**)&pdh,  g_dh);
    cudaGetSymbolAddress((void**)&pgW1p,g_gW1p);
    cudaGetSymbolAddress((void**)&pgW2p,g_gW2p);
    cudaGetSymbolAddress((void**)&pgW1, g_gW1);
    cudaGetSymbolAddress((void**)&pgb1, g_gb1);
    cudaGetSymbolAddress((void**)&pgW2, g_gW2);
    cudaGetSymbolAddress((void**)&pgb2, g_gb2);
    cudaGetSymbolAddress((void**)&pnW1, g_nW1);
    cudaGetSymbolAddress((void**)&pnb1, g_nb1);
    cudaGetSymbolAddress((void**)&pnW2, g_nW2);
    cudaGetSymbolAddress((void**)&pnb2, g_nb2);
    cudaGetSymbolAddress((void**)&ph2,  g_h2);
    cudaGetSymbolAddress((void**)&pctx, g_ctx);
    cudaGetSymbolAddress((void**)&pq,   g_q);
    cudaGetSymbolAddress((void**)&pkh,  g_kh);
    cudaGetSymbolAddress((void**)&pS,   g_S);
    cudaGetSymbolAddress((void**)&paop, g_aop);
    cudaGetSymbolAddress((void**)&pao,  g_ao);
    cudaGetSymbolAddress((void**)&pst,  g_st);

    // --- Titan memory: projections ---
    gemm_abT<false,false><<<dim3(NKD/64, NB/64), 256>>>(x, W_K, nullptr, pk, NB, NKD, DIN);
    gemm_abT<false,false><<<dim3(NVD/64, NB/64), 256>>>(x, W_V, nullptr, pv, NB, NVD, DIN);
    // forward mem net (old params)
    gemm_abT<true,true ><<<dim3(NHD/64, NB/64), 256>>>(pk, mW1, mb1, ph,  NB, NHD, NKD);
    gemm_abT<true,false><<<dim3(NVD/64, NB/64), 256>>>(ph, mW2, mb2, pdp, NB, NVD, NHD);
    // d_pred = 2*(pred - v)/(B*VD)
    dpred_k<<<(NB*NVD + 255)/256, 256>>>(pdp, pv, NB*NVD, 2.f / (float)(NB*NVD));
    // gW2 = d_pred^T @ h ; gb2 = colsum(d_pred)
    gemm_aTb<<<dim3(NHD/64, NVD/64, NSPLIT_G), 256>>>(pdp, ph, pgW2p, NB, NVD, NHD, NB/NSPLIT_G);
    combine_k<<<(NVD*NHD + 255)/256, 256>>>(pgW2p, pgW2, NVD*NHD, NSPLIT_G);
    colsum_k<<<1, NVD>>>(pdp, pgb2, NB, NVD);
    // dh = (d_pred @ W2) * (h > 0)
    gemm_ab<true><<<dim3(NHD/64, NB/64, 1), 256>>>(pdp, mW2, ph, pdh, NB, NHD, NVD, NVD);
    colsum_k<<<1, NHD>>>(pdh, pgb1, NB, NHD);
    // gW1 = dh^T @ k
    gemm_aTb<<<dim3(NKD/64, NHD/64, NSPLIT_G), 256>>>(pdh, pk, pgW1p, NB, NHD, NKD, NB/NSPLIT_G);
    combine_k<<<(NHD*NKD + 255)/256, 256>>>(pgW1p, pgW1, NHD*NKD, NSPLIT_G);
    // eff_theta, param update
    surprise_k<<<1, 256>>>();
    update_k<<<(NHD*NKD + NHD + NVD*NHD + NVD + 255)/256, 256>>>(mW1,mb1,mW2,mb2,bufW1,bufb1,bufW2,bufb2);
    // titan_context with updated params
    gemm_abT<true,true ><<<dim3(NHD/64, NB/64), 256>>>(pk,  pnW1, pnb1, ph2,  NB, NHD, NKD);
    gemm_abT<true,false><<<dim3(NVD/64, NB/64), 256>>>(ph2, pnW2, pnb2, pctx, NB, NVD, NHD);

    // --- attention ---
    gemm_abT<false,false><<<dim3(DIN/64, NB/64), 256>>>(x,    Wq, nullptr, pq,  NB, DIN, DIN);
    gemm_abT<false,false><<<dim3(DIN/64, NH/64), 256>>>(hist, Wk, nullptr, pkh, NH, DIN, DIN);
    gemm_abT<false,false><<<dim3(NH/64,  NB/64), 256>>>(pq,  pkh, nullptr, pS,  NB, NH,  DIN);
    softmax_k<<<NB, 256>>>();
    gemm_ab<false><<<dim3(DIN/64, NB/64, NSPLIT_K), 256>>>(pS, hist, nullptr, paop, NB, DIN, NH, NH/NSPLIT_K);
    combine_k<<<(NB*DIN + 255)/256, 256>>>(paop, pao, NB*DIN, NSPLIT_K);
    gemm_abT<true,false><<<dim3(NVD/64, NB/64), 256>>>(pao, Wst, bst, pst, NB, NVD, DIN);

    // --- entity path + fusion ---
    entity_k<<<1, DIN>>>(ent, Wep, bep, Weg, beg);
    fuse_k<<<NB, NVD>>>(kvec, Wg, bg, out);
}

// round 3
// speedup vs baseline: 1.9246x; 1.9246x over previous
#include <cuda_runtime.h>
#include <cuda_bf16.h>
#include <math.h>
#include <stdint.h>

// Problem dims
#define NB   2048
#define NH   16384
#define NE   64
#define DIN  384
#define NKD  128
#define NVD  128
#define NHD  256
#define NSPLIT_G 8
#define NSPLIT_AH 16

typedef __nv_bfloat16 bf16;

// ---------------- scratch (device globals; no allocation allowed) ----------------
__device__ float g_k[NB*NKD];
__device__ float g_v[NB*NVD];
__device__ float g_h[NB*NHD];
__device__ float g_dpred[NB*NVD];
__device__ float g_dh[NB*NHD];
__device__ float g_gW1p[NSPLIT_G*NHD*NKD];
__device__ float g_gW2p[NSPLIT_G*NVD*NHD];
__device__ float g_gW1[NHD*NKD];
__device__ float g_gb1[NHD];
__device__ float g_gW2[NVD*NHD];
__device__ float g_gb2[NVD];
__device__ float g_nW1[NHD*NKD];
__device__ float g_nb1[NHD];
__device__ float g_nW2[NVD*NHD];
__device__ float g_nb2[NVD];
__device__ float g_h2[NB*NHD];
__device__ float g_ctx[NB*NVD];
__device__ float g_S[33554432];            // 2048*16384 fp32
__device__ float g_aop[NSPLIT_AH*NB*DIN];  // split-K partials of attn@hist
__device__ float g_ao[NB*DIN];
__device__ float g_st[NB*NVD];
__device__ float g_theta[1];
__device__ float g_ectx[NVD];
__device__ float g_eg[1];
// bf16 split operands
__device__ bf16 g_xh[NB*DIN],   g_xl[NB*DIN];
__device__ bf16 g_Wqh[DIN*DIN], g_Wql[DIN*DIN];
__device__ bf16 g_Wkh[DIN*DIN], g_Wkl[DIN*DIN];
__device__ bf16 g_histh[NH*DIN], g_histl[NH*DIN];     // row-major [H,D]
__device__ bf16 g_histTh[DIN*NH], g_histTl[DIN*NH];   // transposed [D,H]
__device__ bf16 g_qh[NB*DIN],   g_ql[NB*DIN];
__device__ bf16 g_khh[NH*DIN],  g_khl[NH*DIN];
__device__ bf16 g_attnh[(size_t)NB*NH], g_attnl[(size_t)NB*NH];

// ================= HMMA (mma.sync) split-bf16 GEMM =================
// C[M,N] = Ah@Bh^T + Ah@Bl^T + Al@Bh^T  (fp32 accumulate in registers)
// A:[M,K] bf16 (hi,lo) row-major; B:[N,K] bf16 (hi,lo) row-major.
// CTA tile 128x128xK32, 256 threads (8 warps: 2m x 4n, warp tile 64x32).
// grid=(N/128, M/128, zsplits), Kchunk per z (Kchunk%32==0).
// WRITE_SPLIT=0: fp32 out to Cf + z*M*N ; WRITE_SPLIT=1: bf16 hi/lo (z==1).

#define TILE_B   10240            // 128 rows * 80B padded stride
#define STAGE_B  (4*TILE_B)       // Ah, Al, Bh, Bl
#define HM_SMEM  (2*STAGE_B)      // 81920

__device__ __forceinline__ uint32_t smem_u32(const void* p) {
    uint32_t a;
    asm("{ .reg .u64 t; cvta.to.shared.u64 t, %1; cvt.u32.u64 %0, t; }" : "=r"(a) : "l"(p));
    return a;
}
__device__ __forceinline__ void cp16(uint32_t s, const void* g) {
    asm volatile("cp.async.cg.shared.global [%0], [%1], 16;" :: "r"(s), "l"(g));
}
__device__ __forceinline__ void cp_commit() {
    asm volatile("cp.async.commit_group;" ::: "memory");
}
template<int N>
__device__ __forceinline__ void cp_wait() {
    asm volatile("cp.async.wait_group %0;" :: "n"(N) : "memory");
}
__device__ __forceinline__ void mma_bf16(float* c, uint32_t a0, uint32_t a1, uint32_t a2,
                                         uint32_t a3, uint32_t b0, uint32_t b1) {
    asm volatile(
        "mma.sync.aligned.m16n8k16.row.col.f32.bf16.bf16.f32 "
        "{%0,%1,%2,%3}, {%4,%5,%6,%7}, {%8,%9}, {%0,%1,%2,%3};"
        : "+f"(c[0]), "+f"(c[1]), "+f"(c[2]), "+f"(c[3])
        : "r"(a0), "r"(a1), "r"(a2), "r"(a3), "r"(b0), "r"(b1));
}

template<int WRITE_SPLIT>
__global__ void __launch_bounds__(256, 1) hmma_gemm(
    const bf16* __restrict__ Ah, const bf16* __restrict__ Al,
    const bf16* __restrict__ Bh, const bf16* __restrict__ Bl,
    float* __restrict__ Cf, bf16* __restrict__ Ch, bf16* __restrict__ Cl,
    int M, int N, int K, int Kchunk)
{
    extern __shared__ char smem[];
    const int tid = threadIdx.x, wid = tid >> 5, lid = tid & 31;
    const int wm = wid >> 2, wn = wid & 3;       // warp grid 2m x 4n
    const int g = lid >> 2, t = lid & 3;
    const int n0 = blockIdx.x * 128, m0 = blockIdx.y * 128;
    const int kbeg = blockIdx.z * Kchunk;
    const int iters = Kchunk / 32;

    const uint32_t sb = smem_u32(smem);
    const bf16* srcs[4] = { Ah, Al, Bh, Bl };
    const int   rows[4] = { m0, m0, n0, n0 };

    // thread t loads 2 16B chunks per tile per stage: idx = tid*2+i -> row=idx>>2, ch=idx&3
    auto load_stage = [&](int stage, int k0) {
        uint32_t base = sb + stage * STAGE_B;
        #pragma unroll
        for (int tile = 0; tile < 4; tile++) {
            const bf16* src = srcs[tile];
            const int br = rows[tile];
            #pragma unroll
            for (int i = 0; i < 2; i++) {
                int idx = tid * 2 + i;
                int row = idx >> 2, ch = idx & 3;
                cp16(base + tile*TILE_B + row*80 + ch*16,
                     src + (size_t)(br + row) * K + k0 + ch*8);
            }
        }
    };

    float acc[4][4][4];
    #pragma unroll
    for (int a = 0; a < 4; a++)
        #pragma unroll
        for (int b = 0; b < 4; b++)
            #pragma unroll
            for (int c = 0; c < 4; c++) acc[a][b][c] = 0.f;

    load_stage(0, kbeg);
    cp_commit();

    for (int it = 0; it < iters; it++) {
        if (it + 1 < iters) load_stage((it + 1) & 1, kbeg + (it + 1) * 32);
        cp_commit();
        cp_wait<1>();
        __syncthreads();

        const char* st = smem + (it & 1) * STAGE_B;
        const uint32_t* Ash = (const uint32_t*)(st);
        const uint32_t* Asl = (const uint32_t*)(st + TILE_B);
        const uint32_t* Bsh = (const uint32_t*)(st + 2*TILE_B);
        const uint32_t* Bsl = (const uint32_t*)(st + 3*TILE_B);

        #pragma unroll
        for (int kb = 0; kb < 2; kb++) {
            const int ko = kb * 8 + t;           // b32 offset in padded row (stride 20)
            uint32_t ah[4][4], al[4][4], bh[4][2], bl[4][2];
            #pragma unroll
            for (int mf = 0; mf < 4; mf++) {
                int r0 = (wm*64 + mf*16 + g) * 20;
                int r1 = r0 + 8 * 20;
                ah[mf][0] = Ash[r0 + ko]; ah[mf][1] = Ash[r1 + ko];
                ah[mf][2] = Ash[r0 + ko + 4]; ah[mf][3] = Ash[r1 + ko + 4];
                al[mf][0] = Asl[r0 + ko]; al[mf][1] = Asl[r1 + ko];
                al[mf][2] = Asl[r0 + ko + 4]; al[mf][3] = Asl[r1 + ko + 4];
            }
            #pragma unroll
            for (int nf = 0; nf < 4; nf++) {
                int rb = (wn*32 + nf*8 + g) * 20;
                bh[nf][0] = Bsh[rb + ko]; bh[nf][1] = Bsh[rb + ko + 4];
                bl[nf][0] = Bsl[rb + ko]; bl[nf][1] = Bsl[rb + ko + 4];
            }
            #pragma unroll
            for (int mf = 0; mf < 4; mf++)
                #pragma unroll
                for (int nf = 0; nf < 4; nf++) {
                    mma_bf16(acc[mf][nf], ah[mf][0], ah[mf][1], ah[mf][2], ah[mf][3],
                             bh[nf][0], bh[nf][1]);
                    mma_bf16(acc[mf][nf], ah[mf][0], ah[mf][1], ah[mf][2], ah[mf][3],
                             bl[nf][0], bl[nf][1]);
                    mma_bf16(acc[mf][nf], al[mf][0], al[mf][1], al[mf][2], al[mf][3],
                             bh[nf][0], bh[nf][1]);
                }
        }
        __syncthreads();
    }

    // epilogue: direct stores; lane holds (row g / g+8, cols 2t, 2t+1) per fragment
    #pragma unroll
    for (int mf = 0; mf < 4; mf++) {
        #pragma unroll
        for (int nf = 0; nf < 4; nf++) {
            int row0 = m0 + wm*64 + mf*16 + g;
            int col  = n0 + wn*32 + nf*8 + 2*t;
            float* c = acc[mf][nf];
            if (WRITE_SPLIT) {
                bf16 h0 = __float2bfloat16(c[0]);
                bf16 l0 = __float2bfloat16(c[0] - __bfloat162float(h0));
                bf16 h1 = __float2bfloat16(c[1]);
                bf16 l1 = __float2bfloat16(c[1] - __bfloat162float(h1));
                bf16 h2 = __float2bfloat16(c[2]);
                bf16 l2 = __float2bfloat16(c[2] - __bfloat162float(h2));
                bf16 h3 = __float2bfloat16(c[3]);
                bf16 l3 = __float2bfloat16(c[3] - __bfloat162float(h3));
                ushort2 u;
                u.x = *(unsigned short*)&h0; u.y = *(unsigned short*)&h1;
                *(ushort2*)&Ch[(size_t)row0 * N + col] = u;
                u.x = *(unsigned short*)&l0; u.y = *(unsigned short*)&l1;
                *(ushort2*)&Cl[(size_t)row0 * N + col] = u;
                u.x = *(unsigned short*)&h2; u.y = *(unsigned short*)&h3;
                *(ushort2*)&Ch[(size_t)(row0+8) * N + col] = u;
                u.x = *(unsigned short*)&l2; u.y = *(unsigned short*)&l3;
                *(ushort2*)&Cl[(size_t)(row0+8) * N + col] = u;
            } else {
                float* Co = Cf + (size_t)blockIdx.z * M * N;
                *(float2*)&Co[(size_t)row0 * N + col]     = make_float2(c[0], c[1]);
                *(float2*)&Co[(size_t)(row0+8) * N + col] = make_float2(c[2], c[3]);
            }
        }
    }
}

// ================= conversion kernels =================
__global__ void split_k(const float* __restrict__ in, bf16* __restrict__ hi,
                        bf16* __restrict__ lo, int n)
{
    int i = blockIdx.x * 256 + threadIdx.x;
    if (i < n) {
        float v = in[i];
        bf16 h = __float2bfloat16(v);
        hi[i] = h;
        lo[i] = __float2bfloat16(v - __bfloat162float(h));
    }
}

// hist[H][D] -> histT hi/lo [D][H]
__global__ void tsplit_k(const float* __restrict__ in, bf16* __restrict__ oh, bf16* __restrict__ ol)
{
    __shared__ float tile[32][33];
    int h0 = blockIdx.x * 32, d0 = blockIdx.y * 32;
    int tx = threadIdx.x, ty = threadIdx.y;   // 32 x 8
    #pragma unroll
    for (int j = 0; j < 32; j += 8)
        tile[ty + j][tx] = in[(size_t)(h0 + ty + j) * DIN + d0 + tx];
    __syncthreads();
    #pragma unroll
    for (int j = 0; j < 32; j += 8) {
        float v = tile[tx][ty + j];
        bf16 h = __float2bfloat16(v);
        size_t off = (size_t)(d0 + ty + j) * NH + h0 + tx;
        oh[off] = h;
        ol[off] = __float2bfloat16(v - __bfloat162float(h));
    }
}

// ================= FFMA GEMMs for the small chain =================
template<bool BIAS, bool RELU>
__launch_bounds__(256)
__global__ void gemm_abT(const float* __restrict__ A, const float* __restrict__ Bm,
                         const float* __restrict__ bias, float* __restrict__ C,
                         int M, int N, int K)
{
    __shared__ float As[16][64];
    __shared__ float Bs[16][64];
    const int t  = threadIdx.x;
    const int tx = t & 15, ty = t >> 4;
    const int m0 = blockIdx.y * 64, n0 = blockIdx.x * 64;
    const int lr = t >> 2;
    const int lc = (t & 3) << 2;
    float acc[4][4] = {};
    const float* Ag = A  + (size_t)(m0 + lr) * K + lc;
    const float* Bg = Bm + (size_t)(n0 + lr) * K + lc;
    for (int k0 = 0; k0 < K; k0 += 16) {
        float4 a4 = *(const float4*)(Ag + k0);
        float4 b4 = *(const float4*)(Bg + k0);
        As[lc+0][lr]=a4.x; As[lc+1][lr]=a4.y; As[lc+2][lr]=a4.z; As[lc+3][lr]=a4.w;
        Bs[lc+0][lr]=b4.x; Bs[lc+1][lr]=b4.y; Bs[lc+2][lr]=b4.z; Bs[lc+3][lr]=b4.w;
        __syncthreads();
        #pragma unroll
        for (int kk = 0; kk < 16; kk++) {
            float4 av = *(const float4*)&As[kk][ty<<2];
            float4 bv = *(const float4*)&Bs[kk][tx<<2];
            acc[0][0]+=av.x*bv.x; acc[0][1]+=av.x*bv.y; acc[0][2]+=av.x*bv.z; acc[0][3]+=av.x*bv.w;
            acc[1][0]+=av.y*bv.x; acc[1][1]+=av.y*bv.y; acc[1][2]+=av.y*bv.z; acc[1][3]+=av.y*bv.w;
            acc[2][0]+=av.z*bv.x; acc[2][1]+=av.z*bv.y; acc[2][2]+=av.z*bv.z; acc[2][3]+=av.z*bv.w;
            acc[3][0]+=av.w*bv.x; acc[3][1]+=av.w*bv.y; acc[3][2]+=av.w*bv.z; acc[3][3]+=av.w*bv.w;
        }
        __syncthreads();
    }
    #pragma unroll
    for (int u = 0; u < 4; u++) {
        float4 o;
        float* oc = (float*)&o;
        #pragma unroll
        for (int v = 0; v < 4; v++) {
            float val = acc[u][v];
            if (BIAS) val += bias[n0 + (tx<<2) + v];
            if (RELU) val = fmaxf(val, 0.f);
            oc[v] = val;
        }
        *(float4*)&C[(size_t)(m0 + (ty<<2) + u) * N + n0 + (tx<<2)] = o;
    }
}

template<bool MASK>
__launch_bounds__(256)
__global__ void gemm_ab(const float* __restrict__ A, const float* __restrict__ Bm,
                        const float* __restrict__ mask, float* __restrict__ C,
                        int M, int N, int K, int Kchunk)
{
    __shared__ float As[16][64];
    __shared__ float Bs[16][64];
    const int t  = threadIdx.x;
    const int tx = t & 15, ty = t >> 4;
    const int m0 = blockIdx.y * 64, n0 = blockIdx.x * 64;
    const int kbeg = blockIdx.z * Kchunk, kend = kbeg + Kchunk;
    const int lrA = t >> 2,  lcA = (t & 3)  << 2;
    const int lrB = t >> 4,  lcB = (t & 15) << 2;
    float acc[4][4] = {};
    for (int k0 = kbeg; k0 < kend; k0 += 16) {
        float4 a4 = *(const float4*)&A [(size_t)(m0 + lrA) * K + k0 + lcA];
        float4 b4 = *(const float4*)&Bm[(size_t)(k0 + lrB) * N + n0 + lcB];
        As[lcA+0][lrA]=a4.x; As[lcA+1][lrA]=a4.y; As[lcA+2][lrA]=a4.z; As[lcA+3][lrA]=a4.w;
        *(float4*)&Bs[lrB][lcB] = b4;
        __syncthreads();
        #pragma unroll
        for (int kk = 0; kk < 16; kk++) {
            float4 av = *(const float4*)&As[kk][ty<<2];
            float4 bv = *(const float4*)&Bs[kk][tx<<2];
            acc[0][0]+=av.x*bv.x; acc[0][1]+=av.x*bv.y; acc[0][2]+=av.x*bv.z; acc[0][3]+=av.x*bv.w;
            acc[1][0]+=av.y*bv.x; acc[1][1]+=av.y*bv.y; acc[1][2]+=av.y*bv.z; acc[1][3]+=av.y*bv.w;
            acc[2][0]+=av.z*bv.x; acc[2][1]+=av.z*bv.y; acc[2][2]+=av.z*bv.z; acc[2][3]+=av.z*bv.w;
            acc[3][0]+=av.w*bv.x; acc[3][1]+=av.w*bv.y; acc[3][2]+=av.w*bv.z; acc[3][3]+=av.w*bv.w;
        }
        __syncthreads();
    }
    float* Co = C + (size_t)blockIdx.z * M * N;
    #pragma unroll
    for (int u = 0; u < 4; u++) {
        const int m = m0 + (ty<<2) + u;
        float4 o;
        float* oc = (float*)&o;
        #pragma unroll
        for (int v = 0; v < 4; v++) {
            float val = acc[u][v];
            if (MASK) val = (mask[(size_t)m * N + n0 + (tx<<2) + v] > 0.f) ? val : 0.f;
            oc[v] = val;
        }
        *(float4*)&Co[(size_t)m * N + n0 + (tx<<2)] = o;
    }
}

__launch_bounds__(256)
__global__ void gemm_aTb(const float* __restrict__ A, const float* __restrict__ Bm,
                         float* __restrict__ Cpart, int L, int M, int N, int Lchunk)
{
    __shared__ float As[16][64];
    __shared__ float Bs[16][64];
    const int t  = threadIdx.x;
    const int tx = t & 15, ty = t >> 4;
    const int m0 = blockIdx.y * 64, n0 = blockIdx.x * 64;
    const int l0b = blockIdx.z * Lchunk;
    const int lr = t >> 4, lc4 = (t & 15) << 2;
    float acc[4][4] = {};
    for (int l0 = l0b; l0 < l0b + Lchunk; l0 += 16) {
        *(float4*)&As[lr][lc4] = *(const float4*)&A [(size_t)(l0 + lr) * M + m0 + lc4];
        *(float4*)&Bs[lr][lc4] = *(const float4*)&Bm[(size_t)(l0 + lr) * N + n0 + lc4];
        __syncthreads();
        #pragma unroll
        for (int kk = 0; kk < 16; kk++) {
            float4 av = *(const float4*)&As[kk][ty<<2];
            float4 bv = *(const float4*)&Bs[kk][tx<<2];
            acc[0][0]+=av.x*bv.x; acc[0][1]+=av.x*bv.y; acc[0][2]+=av.x*bv.z; acc[0][3]+=av.x*bv.w;
            acc[1][0]+=av.y*bv.x; acc[1][1]+=av.y*bv.y; acc[1][2]+=av.y*bv.z; acc[1][3]+=av.y*bv.w;
            acc[2][0]+=av.z*bv.x; acc[2][1]+=av.z*bv.y; acc[2][2]+=av.z*bv.z; acc[2][3]+=av.z*bv.w;
            acc[3][0]+=av.w*bv.x; acc[3][1]+=av.w*bv.y; acc[3][2]+=av.w*bv.z; acc[3][3]+=av.w*bv.w;
        }
        __syncthreads();
    }
    float* Co = Cpart + (size_t)blockIdx.z * M * N;
    #pragma unroll
    for (int u = 0; u < 4; u++) {
        float4 o;
        float* oc = (float*)&o;
        #pragma unroll
        for (int v = 0; v < 4; v++) oc[v] = acc[u][v];
        *(float4*)&Co[(size_t)(m0 + (ty<<2) + u) * N + n0 + (tx<<2)] = o;
    }
}

// ================= small kernels =================
__global__ void combine_k(const float* __restrict__ parts, float* __restrict__ out,
                          int len, int np)
{
    int i = blockIdx.x * 256 + threadIdx.x;
    if (i < len) {
        float s = 0.f;
        for (int p = 0; p < np; p++) s += parts[(size_t)p * len + i];
        out[i] = s;
    }
}

__global__ void colsum_k(const float* __restrict__ A, float* __restrict__ out, int rows, int N)
{
    int c = threadIdx.x;
    float s = 0.f;
    for (int r = 0; r < rows; r++) s += A[(size_t)r * N + c];
    out[c] = s;
}

__global__ void dpred_k(float* __restrict__ dp, const float* __restrict__ v, int n, float scale)
{
    int i = blockIdx.x * 256 + threadIdx.x;
    if (i < n) dp[i] = (dp[i] - v[i]) * scale;
}

__global__ void surprise_k()
{
    __shared__ float red[256];
    int t = threadIdx.x;
    float s = 0.f;
    for (int i = t; i < NHD*NKD; i += 256) { float g = g_gW1[i]; s += g*g; }
    for (int i = t; i < NHD;     i += 256) { float g = g_gb1[i]; s += g*g; }
    for (int i = t; i < NVD*NHD; i += 256) { float g = g_gW2[i]; s += g*g; }
    for (int i = t; i < NVD;     i += 256) { float g = g_gb2[i]; s += g*g; }
    red[t] = s; __syncthreads();
    for (int st = 128; st > 0; st >>= 1) { if (t < st) red[t] += red[t+st]; __syncthreads(); }
    if (t == 0) {
        float avg = sqrtf(red[0] * 0.25f);
        g_theta[0] = 0.1f / (1.f + expf(-avg));
    }
}

__global__ void update_k(const float* __restrict__ mW1, const float* __restrict__ mb1,
                         const float* __restrict__ mW2, const float* __restrict__ mb2,
                         const float* __restrict__ bW1, const float* __restrict__ bb1,
                         const float* __restrict__ bW2, const float* __restrict__ bb2)
{
    int i = blockIdx.x * 256 + threadIdx.x;
    float et = g_theta[0];
    const int n1 = NHD*NKD, n2 = n1 + NHD, n3 = n2 + NVD*NHD, n4 = n3 + NVD;
    if (i < n1)       g_nW1[i]   = 0.9f*mW1[i]   + 0.9f*bW1[i]   - et*g_gW1[i];
    else if (i < n2) { int j=i-n1; g_nb1[j] = 0.9f*mb1[j] + 0.9f*bb1[j] - et*g_gb1[j]; }
    else if (i < n3) { int j=i-n2; g_nW2[j] = 0.9f*mW2[j] + 0.9f*bW2[j] - et*g_gW2[j]; }
    else if (i < n4) { int j=i-n3; g_nb2[j] = 0.9f*mb2[j] + 0.9f*bb2[j] - et*g_gb2[j]; }
}

// softmax over rows of g_S; emits attn hi/lo bf16 directly
__launch_bounds__(256)
__global__ void softmax_k()
{
    const float* row = g_S + (size_t)blockIdx.x * NH;
    bf16* oh = g_attnh + (size_t)blockIdx.x * NH;
    bf16* ol = g_attnl + (size_t)blockIdx.x * NH;
    const int t = threadIdx.x;
    float v[64];
    float m = -1e30f;
    #pragma unroll
    for (int j = 0; j < 64; j++) { v[j] = row[t + 256*j]; m = fmaxf(m, v[j]); }
    __shared__ float red[256];
    red[t] = m; __syncthreads();
    #pragma unroll
    for (int s = 128; s > 0; s >>= 1) { if (t < s) red[t] = fmaxf(red[t], red[t+s]); __syncthreads(); }
    m = red[0]; __syncthreads();
    float l = 0.f;
    #pragma unroll
    for (int j = 0; j < 64; j++) { v[j] = __expf(v[j] - m); l += v[j]; }
    red[t] = l; __syncthreads();
    #pragma unroll
    for (int s = 128; s > 0; s >>= 1) { if (t < s) red[t] += red[t+s]; __syncthreads(); }
    float inv = 1.f / red[0];
    #pragma unroll
    for (int j = 0; j < 64; j++) {
        float a = v[j] * inv;
        bf16 h = __float2bfloat16(a);
        oh[t + 256*j] = h;
        ol[t + 256*j] = __float2bfloat16(a - __bfloat162float(h));
    }
}

__global__ void entity_k(const float* __restrict__ ent, const float* __restrict__ Wep,
                         const float* __restrict__ bep, const float* __restrict__ Weg,
                         const float* __restrict__ beg)
{
    __shared__ float eavg[DIN];
    __shared__ float ectx[NVD];
    int t = threadIdx.x;
    float s = 0.f;
    for (int e = 0; e < NE; e++) s += ent[e*DIN + t];
    eavg[t] = s * (1.f / NE);
    __syncthreads();
    if (t < NVD) {
        float c = bep[t];
        for (int d = 0; d < DIN; d++) c += eavg[d] * Wep[t*DIN + d];
        ectx[t] = c; g_ectx[t] = c;
    }
    __syncthreads();
    if (t == 0) {
        float g = beg[0];
        for (int j = 0; j < NVD; j++) g += ectx[j] * Weg[j];
        g_eg[0] = 1.f / (1.f + expf(-g));
    }
}

__global__ void fuse_k(const float* __restrict__ kvec, const float* __restrict__ Wg,
                       const float* __restrict__ bg, float* __restrict__ out)
{
    int b = blockIdx.x, i = threadIdx.x;
    float p = g_ctx[b*NVD + i] + kvec[i];
    float s = p * Wg[i];
    #pragma unroll
    for (int o = 16; o > 0; o >>= 1) s += __shfl_down_sync(0xffffffffu, s, o);
    __shared__ float wsum[4];
    __shared__ float gsh;
    if ((i & 31) == 0) wsum[i >> 5] = s;
    __syncthreads();
    if (i == 0) {
        float tot = wsum[0] + wsum[1] + wsum[2] + wsum[3] + bg[0];
        gsh = 1.f / (1.f + expf(-tot));
    }
    __syncthreads();
    float gate = gsh;
    float f = gate * p + (1.f - gate) * g_st[b*NVD + i];
    float eg = g_eg[0];
    out[b*NVD + i] = eg * g_ectx[i] + (1.f - eg) * f;
}

// ================= host =================
extern "C" void kernel_launch(void* const* d_in, const int* in_sizes, int n_in,
                              void* d_out, int out_size)
{
    const float* x     = (const float*)d_in[0];
    const float* hist  = (const float*)d_in[1];
    const float* ent   = (const float*)d_in[2];
    const float* W_K   = (const float*)d_in[3];
    const float* W_V   = (const float*)d_in[4];
    const float* mW1   = (const float*)d_in[5];
    const float* mb1   = (const float*)d_in[6];
    const float* mW2   = (const float*)d_in[7];
    const float* mb2   = (const float*)d_in[8];
    const float* bufW1 = (const float*)d_in[9];
    const float* bufb1 = (const float*)d_in[10];
    const float* bufW2 = (const float*)d_in[11];
    const float* bufb2 = (const float*)d_in[12];
    const float* kvec  = (const float*)d_in[13];
    const float* Wq    = (const float*)d_in[14];
    const float* Wk    = (const float*)d_in[15];
    const float* Wst   = (const float*)d_in[16];
    const float* bst   = (const float*)d_in[17];
    const float* Wg    = (const float*)d_in[18];
    const float* bg    = (const float*)d_in[19];
    // d_in[20..23] dead (gating_loss only)
    const float* Wep   = (const float*)d_in[24];
    const float* bep   = (const float*)d_in[25];
    const float* Weg   = (const float*)d_in[26];
    const float* beg   = (const float*)d_in[27];
    float* out = (float*)d_out;

    static bool attr_done = false;
    if (!attr_done) {
        cudaFuncSetAttribute(hmma_gemm<0>, cudaFuncAttributeMaxDynamicSharedMemorySize, HM_SMEM);
        cudaFuncSetAttribute(hmma_gemm<1>, cudaFuncAttributeMaxDynamicSharedMemorySize, HM_SMEM);
        attr_done = true;
    }

    float *pk,*pv,*ph,*pdp,*pdh,*pgW1p,*pgW2p,*pgW1,*pgb1,*pgW2,*pgb2;
    float *pnW1,*pnb1,*pnW2,*pnb2,*ph2,*pctx,*pS,*paop,*pao,*pst;
    bf16 *pxh,*pxl,*pWqh,*pWql,*pWkh,*pWkl,*phh,*phl,*phTh,*phTl,*pqh,*pql,*pkhh,*pkhl,*pah,*pal;
    cudaGetSymbolAddress((void**)&pk,   g_k);
    cudaGetSymbolAddress((void**)&pv,   g_v);
    cudaGetSymbolAddress((void**)&ph,   g_h);
    cudaGetSymbolAddress((void**)&pdp,  g_dpred);
    cudaGetSymbolAddress((void**)&pdh,  g_dh);
    cudaGetSymbolAddress((void**)&pgW1p,g_gW1p);
    cudaGetSymbolAddress((void**)&pgW2p,g_gW2p);
    cudaGetSymbolAddress((void**)&pgW1, g_gW1);
    cudaGetSymbolAddress((void**)&pgb1, g_gb1);
    cudaGetSymbolAddress((void**)&pgW2, g_gW2);
    cudaGetSymbolAddress((void**)&pgb2, g_gb2);
    cudaGetSymbolAddress((void**)&pnW1, g_nW1);
    cudaGetSymbolAddress((void**)&pnb1, g_nb1);
    cudaGetSymbolAddress((void**)&pnW2, g_nW2);
    cudaGetSymbolAddress((void**)&pnb2, g_nb2);
    cudaGetSymbolAddress((void**)&ph2,  g_h2);
    cudaGetSymbolAddress((void**)&pctx, g_ctx);
    cudaGetSymbolAddress((void**)&pS,   g_S);
    cudaGetSymbolAddress((void**)&paop, g_aop);
    cudaGetSymbolAddress((void**)&pao,  g_ao);
    cudaGetSymbolAddress((void**)&pst,  g_st);
    cudaGetSymbolAddress((void**)&pxh,  g_xh);
    cudaGetSymbolAddress((void**)&pxl,  g_xl);
    cudaGetSymbolAddress((void**)&pWqh, g_Wqh);
    cudaGetSymbolAddress((void**)&pWql, g_Wql);
    cudaGetSymbolAddress((void**)&pWkh, g_Wkh);
    cudaGetSymbolAddress((void**)&pWkl, g_Wkl);
    cudaGetSymbolAddress((void**)&phh,  g_histh);
    cudaGetSymbolAddress((void**)&phl,  g_histl);
    cudaGetSymbolAddress((void**)&phTh, g_histTh);
    cudaGetSymbolAddress((void**)&phTl, g_histTl);
    cudaGetSymbolAddress((void**)&pqh,  g_qh);
    cudaGetSymbolAddress((void**)&pql,  g_ql);
    cudaGetSymbolAddress((void**)&pkhh, g_khh);
    cudaGetSymbolAddress((void**)&pkhl, g_khl);
    cudaGetSymbolAddress((void**)&pah,  g_attnh);
    cudaGetSymbolAddress((void**)&pal,  g_attnl);

    // --- conversions for tensor-core path ---
    split_k<<<(NB*DIN + 255)/256, 256>>>(x,    pxh,  pxl,  NB*DIN);
    split_k<<<(DIN*DIN + 255)/256, 256>>>(Wq,  pWqh, pWql, DIN*DIN);
    split_k<<<(DIN*DIN + 255)/256, 256>>>(Wk,  pWkh, pWkl, DIN*DIN);
    split_k<<<(NH*DIN + 255)/256, 256>>>(hist, phh,  phl,  NH*DIN);
    tsplit_k<<<dim3(NH/32, DIN/32), dim3(32,8)>>>(hist, phTh, phTl);

    // --- Titan memory (FFMA, small) ---
    gemm_abT<false,false><<<dim3(NKD/64, NB/64), 256>>>(x, W_K, nullptr, pk, NB, NKD, DIN);
    gemm_abT<false,false><<<dim3(NVD/64, NB/64), 256>>>(x, W_V, nullptr, pv, NB, NVD, DIN);
    gemm_abT<true,true ><<<dim3(NHD/64, NB/64), 256>>>(pk, mW1, mb1, ph,  NB, NHD, NKD);
    gemm_abT<true,false><<<dim3(NVD/64, NB/64), 256>>>(ph, mW2, mb2, pdp, NB, NVD, NHD);
    dpred_k<<<(NB*NVD + 255)/256, 256>>>(pdp, pv, NB*NVD, 2.f / (float)(NB*NVD));
    gemm_aTb<<<dim3(NHD/64, NVD/64, NSPLIT_G), 256>>>(pdp, ph, pgW2p, NB, NVD, NHD, NB/NSPLIT_G);
    combine_k<<<(NVD*NHD + 255)/256, 256>>>(pgW2p, pgW2, NVD*NHD, NSPLIT_G);
    colsum_k<<<1, NVD>>>(pdp, pgb2, NB, NVD);
    gemm_ab<true><<<dim3(NHD/64, NB/64, 1), 256>>>(pdp, mW2, ph, pdh, NB, NHD, NVD, NVD);
    colsum_k<<<1, NHD>>>(pdh, pgb1, NB, NHD);
    gemm_aTb<<<dim3(NKD/64, NHD/64, NSPLIT_G), 256>>>(pdh, pk, pgW1p, NB, NHD, NKD, NB/NSPLIT_G);
    combine_k<<<(NHD*NKD + 255)/256, 256>>>(pgW1p, pgW1, NHD*NKD, NSPLIT_G);
    surprise_k<<<1, 256>>>();
    update_k<<<(NHD*NKD + NHD + NVD*NHD + NVD + 255)/256, 256>>>(mW1,mb1,mW2,mb2,bufW1,bufb1,bufW2,bufb2);
    gemm_abT<true,true ><<<dim3(NHD/64, NB/64), 256>>>(pk,  pnW1, pnb1, ph2,  NB, NHD, NKD);
    gemm_abT<true,false><<<dim3(NVD/64, NB/64), 256>>>(ph2, pnW2, pnb2, pctx, NB, NVD, NHD);

    // --- attention (mma.sync split-bf16) ---
    // q = x @ Wq^T  -> split bf16
    hmma_gemm<1><<<dim3(DIN/128, NB/128, 1), 256, HM_SMEM>>>(
        pxh, pxl, pWqh, pWql, nullptr, pqh, pql, NB, DIN, DIN, DIN);
    // kh = hist @ Wk^T -> split bf16
    hmma_gemm<1><<<dim3(DIN/128, NH/128, 1), 256, HM_SMEM>>>(
        phh, phl, pWkh, pWkl, nullptr, pkhh, pkhl, NH, DIN, DIN, DIN);
    // S = q @ kh^T -> fp32
    hmma_gemm<0><<<dim3(NH/128, NB/128, 1), 256, HM_SMEM>>>(
        pqh, pql, pkhh, pkhl, pS, nullptr, nullptr, NB, NH, DIN, DIN);
    softmax_k<<<NB, 256>>>();
    // attn @ hist -> fp32 partial slabs (split-K), combine
    hmma_gemm<0><<<dim3(DIN/128, NB/128, NSPLIT_AH), 256, HM_SMEM>>>(
        pah, pal, phTh, phTl, paop, nullptr, nullptr, NB, DIN, NH, NH/NSPLIT_AH);
    combine_k<<<(NB*DIN + 255)/256, 256>>>(paop, pao, NB*DIN, NSPLIT_AH);
    gemm_abT<true,false><<<dim3(NVD/64, NB/64), 256>>>(pao, Wst, bst, pst, NB, NVD, DIN);

    // --- entity path + fusion ---
    entity_k<<<1, DIN>>>(ent, Wep, bep, Weg, beg);
    fuse_k<<<NB, NVD>>>(kvec, Wg, bg, out);
}

// round 4
// speedup vs baseline: 2.1228x; 1.1030x over previous
#include <cuda_runtime.h>
#include <cuda_bf16.h>
#include <math.h>
#include <stdint.h>

// Problem dims
#define NB   2048
#define NH   16384
#define NE   64
#define DIN  384
#define NKD  128
#define NVD  128
#define NHD  256
#define NSPLIT_G 8
#define NSPLIT_AH 16

typedef __nv_bfloat16 bf16;

// ---------------- scratch (device globals) ----------------
__device__ float g_k[NB*NKD];
__device__ float g_v[NB*NVD];
__device__ float g_h[NB*NHD];
__device__ float g_dpred[NB*NVD];
__device__ float g_dh[NB*NHD];
__device__ float g_gW1p[NSPLIT_G*NHD*NKD];
__device__ float g_gW2p[NSPLIT_G*NVD*NHD];
__device__ float g_gW1[NHD*NKD];
__device__ float g_gb1[NHD];
__device__ float g_gW2[NVD*NHD];
__device__ float g_gb2[NVD];
__device__ float g_nW1[NHD*NKD];
__device__ float g_nb1[NHD];
__device__ float g_nW2[NVD*NHD];
__device__ float g_nb2[NVD];
__device__ float g_h2[NB*NHD];
__device__ float g_ctx[NB*NVD];
__device__ float g_S[33554432];            // 2048*16384 fp32
__device__ float g_aop[NSPLIT_AH*NB*DIN];
__device__ float g_ao[NB*DIN];
__device__ float g_st[NB*NVD];
__device__ float g_theta[1];
__device__ float g_ectx[NVD];
__device__ float g_eg[1];
// bf16 split operands
__device__ bf16 g_xh[NB*DIN],   g_xl[NB*DIN];
__device__ bf16 g_Wqh[DIN*DIN], g_Wql[DIN*DIN];
__device__ bf16 g_Wkh[DIN*DIN], g_Wkl[DIN*DIN];
__device__ bf16 g_histh[NH*DIN], g_histl[NH*DIN];
__device__ bf16 g_histTh[DIN*NH], g_histTl[DIN*NH];
__device__ bf16 g_qh[NB*DIN],   g_ql[NB*DIN];
__device__ bf16 g_khh[NH*DIN],  g_khl[NH*DIN];
__device__ bf16 g_attnh[(size_t)NB*NH], g_attnl[(size_t)NB*NH];

// ================= HMMA (mma.sync) split-bf16 GEMM =================
// C[M,N] = Ah@Bh^T + Ah@Bl^T + Al@Bh^T  (fp32 reg accumulate)
// CTA tile 128x128xK32, 256 threads (8 warps: 2m x 4n, warp tile 64x32).
// 3-stage cp.async pipeline, ldmatrix fragment loads.

#define TILE_B   10240            // 128 rows * 80B padded stride
#define STAGE_B  (4*TILE_B)       // Ah, Al, Bh, Bl
#define NSTAGE   3
#define HM_SMEM  (NSTAGE*STAGE_B) // 122880

__device__ __forceinline__ uint32_t smem_u32(const void* p) {
    uint32_t a;
    asm("{ .reg .u64 t; cvta.to.shared.u64 t, %1; cvt.u32.u64 %0, t; }" : "=r"(a) : "l"(p));
    return a;
}
__device__ __forceinline__ void cp16(uint32_t s, const void* g) {
    asm volatile("cp.async.cg.shared.global [%0], [%1], 16;" :: "r"(s), "l"(g));
}
__device__ __forceinline__ void cp_commit() {
    asm volatile("cp.async.commit_group;" ::: "memory");
}
template<int N>
__device__ __forceinline__ void cp_wait() {
    asm volatile("cp.async.wait_group %0;" :: "n"(N) : "memory");
}
__device__ __forceinline__ void ldsm4(uint32_t* r, uint32_t addr) {
    asm volatile("ldmatrix.sync.aligned.m8n8.x4.shared.b16 {%0,%1,%2,%3}, [%4];"
                 : "=r"(r[0]), "=r"(r[1]), "=r"(r[2]), "=r"(r[3]) : "r"(addr));
}
__device__ __forceinline__ void ldsm2(uint32_t* r, uint32_t addr) {
    asm volatile("ldmatrix.sync.aligned.m8n8.x2.shared.b16 {%0,%1}, [%2];"
                 : "=r"(r[0]), "=r"(r[1]) : "r"(addr));
}
__device__ __forceinline__ void mma_bf16(float* c, const uint32_t* a, const uint32_t* b) {
    asm volatile(
        "mma.sync.aligned.m16n8k16.row.col.f32.bf16.bf16.f32 "
        "{%0,%1,%2,%3}, {%4,%5,%6,%7}, {%8,%9}, {%0,%1,%2,%3};"
        : "+f"(c[0]), "+f"(c[1]), "+f"(c[2]), "+f"(c[3])
        : "r"(a[0]), "r"(a[1]), "r"(a[2]), "r"(a[3]), "r"(b[0]), "r"(b[1]));
}

template<int WRITE_SPLIT>
__global__ void __launch_bounds__(256, 1) hmma_gemm(
    const bf16* __restrict__ Ah, const bf16* __restrict__ Al,
    const bf16* __restrict__ Bh, const bf16* __restrict__ Bl,
    float* __restrict__ Cf, bf16* __restrict__ Ch, bf16* __restrict__ Cl,
    int M, int N, int K, int Kchunk)
{
    extern __shared__ char smem[];
    const int tid = threadIdx.x, wid = tid >> 5, lid = tid & 31;
    const int wm = wid >> 2, wn = wid & 3;
    const int g = lid >> 2, t = lid & 3;
    const int n0 = blockIdx.x * 128, m0 = blockIdx.y * 128;
    const int kbeg = blockIdx.z * Kchunk;
    const int iters = Kchunk / 32;

    const uint32_t sb = smem_u32(smem);
    const bf16* srcs[4] = { Ah, Al, Bh, Bl };
    const int   rows[4] = { m0, m0, n0, n0 };

    // ldmatrix stage-relative offsets
    const uint32_t a_off = (uint32_t)((wm*64 + (lid & 15)) * 80 + (lid >> 4) * 16);
    const uint32_t b_off = (uint32_t)((wn*32 + (lid & 7))  * 80 + ((lid >> 3) & 1) * 16);

    auto load_stage = [&](int stage, int k0) {
        uint32_t base = sb + stage * STAGE_B;
        #pragma unroll
        for (int tile = 0; tile < 4; tile++) {
            const bf16* src = srcs[tile];
            const int br = rows[tile];
            #pragma unroll
            for (int i = 0; i < 2; i++) {
                int idx = tid * 2 + i;
                int row = idx >> 2, ch = idx & 3;
                cp16(base + tile*TILE_B + row*80 + ch*16,
                     src + (size_t)(br + row) * K + k0 + ch*8);
            }
        }
    };

    float acc[4][4][4];
    #pragma unroll
    for (int a = 0; a < 4; a++)
        #pragma unroll
        for (int b = 0; b < 4; b++)
            #pragma unroll
            for (int c = 0; c < 4; c++) acc[a][b][c] = 0.f;

    load_stage(0, kbeg);
    cp_commit();
    if (iters > 1) load_stage(1, kbeg + 32);
    cp_commit();

    for (int it = 0; it < iters; it++) {
        cp_wait<1>();
        __syncthreads();
        if (it + 2 < iters) load_stage((it + 2) % NSTAGE, kbeg + (it + 2) * 32);
        cp_commit();

        const uint32_t stb = sb + (it % NSTAGE) * STAGE_B;
        #pragma unroll
        for (int kb = 0; kb < 2; kb++) {
            const uint32_t ko = kb * 32;
            uint32_t ah[4][4], al[4][4], bh[4][2], bl[4][2];
            #pragma unroll
            for (int mf = 0; mf < 4; mf++) {
                ldsm4(ah[mf], stb +            a_off + mf*(16*80) + ko);
                ldsm4(al[mf], stb + TILE_B   + a_off + mf*(16*80) + ko);
            }
            #pragma unroll
            for (int nf = 0; nf < 4; nf++) {
                ldsm2(bh[nf], stb + 2*TILE_B + b_off + nf*(8*80) + ko);
                ldsm2(bl[nf], stb + 3*TILE_B + b_off + nf*(8*80) + ko);
            }
            #pragma unroll
            for (int mf = 0; mf < 4; mf++)
                #pragma unroll
                for (int nf = 0; nf < 4; nf++) {
                    mma_bf16(acc[mf][nf], ah[mf], bh[nf]);
                    mma_bf16(acc[mf][nf], ah[mf], bl[nf]);
                    mma_bf16(acc[mf][nf], al[mf], bh[nf]);
                }
        }
        __syncthreads();
    }

    #pragma unroll
    for (int mf = 0; mf < 4; mf++) {
        #pragma unroll
        for (int nf = 0; nf < 4; nf++) {
            int row0 = m0 + wm*64 + mf*16 + g;
            int col  = n0 + wn*32 + nf*8 + 2*t;
            float* c = acc[mf][nf];
            if (WRITE_SPLIT) {
                bf16 h0 = __float2bfloat16(c[0]);
                bf16 l0 = __float2bfloat16(c[0] - __bfloat162float(h0));
                bf16 h1 = __float2bfloat16(c[1]);
                bf16 l1 = __float2bfloat16(c[1] - __bfloat162float(h1));
                bf16 h2 = __float2bfloat16(c[2]);
                bf16 l2 = __float2bfloat16(c[2] - __bfloat162float(h2));
                bf16 h3 = __float2bfloat16(c[3]);
                bf16 l3 = __float2bfloat16(c[3] - __bfloat162float(h3));
                ushort2 u;
                u.x = *(unsigned short*)&h0; u.y = *(unsigned short*)&h1;
                *(ushort2*)&Ch[(size_t)row0 * N + col] = u;
                u.x = *(unsigned short*)&l0; u.y = *(unsigned short*)&l1;
                *(ushort2*)&Cl[(size_t)row0 * N + col] = u;
                u.x = *(unsigned short*)&h2; u.y = *(unsigned short*)&h3;
                *(ushort2*)&Ch[(size_t)(row0+8) * N + col] = u;
                u.x = *(unsigned short*)&l2; u.y = *(unsigned short*)&l3;
                *(ushort2*)&Cl[(size_t)(row0+8) * N + col] = u;
            } else {
                float* Co = Cf + (size_t)blockIdx.z * M * N;
                *(float2*)&Co[(size_t)row0 * N + col]     = make_float2(c[0], c[1]);
                *(float2*)&Co[(size_t)(row0+8) * N + col] = make_float2(c[2], c[3]);
            }
        }
    }
}

// ================= conversion kernels =================
__global__ void split_k(const float* __restrict__ in, bf16* __restrict__ hi,
                        bf16* __restrict__ lo, int n)
{
    int i = blockIdx.x * 256 + threadIdx.x;
    if (i < n) {
        float v = in[i];
        bf16 h = __float2bfloat16(v);
        hi[i] = h;
        lo[i] = __float2bfloat16(v - __bfloat162float(h));
    }
}

__global__ void tsplit_k(const float* __restrict__ in, bf16* __restrict__ oh, bf16* __restrict__ ol)
{
    __shared__ float tile[32][33];
    int h0 = blockIdx.x * 32, d0 = blockIdx.y * 32;
    int tx = threadIdx.x, ty = threadIdx.y;
    #pragma unroll
    for (int j = 0; j < 32; j += 8)
        tile[ty + j][tx] = in[(size_t)(h0 + ty + j) * DIN + d0 + tx];
    __syncthreads();
    #pragma unroll
    for (int j = 0; j < 32; j += 8) {
        float v = tile[tx][ty + j];
        bf16 h = __float2bfloat16(v);
        size_t off = (size_t)(d0 + ty + j) * NH + h0 + tx;
        oh[off] = h;
        ol[off] = __float2bfloat16(v - __bfloat162float(h));
    }
}

// ================= FFMA GEMMs (titan chain) =================
template<bool BIAS, bool RELU, bool DPRED>
__launch_bounds__(256)
__global__ void gemm_abT(const float* __restrict__ A, const float* __restrict__ Bm,
                         const float* __restrict__ bias, const float* __restrict__ Vm,
                         float dscale, float* __restrict__ C,
                         int M, int N, int K)
{
    __shared__ float As[16][64];
    __shared__ float Bs[16][64];
    const int t  = threadIdx.x;
    const int tx = t & 15, ty = t >> 4;
    const int m0 = blockIdx.y * 64, n0 = blockIdx.x * 64;
    const int lr = t >> 2;
    const int lc = (t & 3) << 2;
    float acc[4][4] = {};
    const float* Ag = A  + (size_t)(m0 + lr) * K + lc;
    const float* Bg = Bm + (size_t)(n0 + lr) * K + lc;
    for (int k0 = 0; k0 < K; k0 += 16) {
        float4 a4 = *(const float4*)(Ag + k0);
        float4 b4 = *(const float4*)(Bg + k0);
        As[lc+0][lr]=a4.x; As[lc+1][lr]=a4.y; As[lc+2][lr]=a4.z; As[lc+3][lr]=a4.w;
        Bs[lc+0][lr]=b4.x; Bs[lc+1][lr]=b4.y; Bs[lc+2][lr]=b4.z; Bs[lc+3][lr]=b4.w;
        __syncthreads();
        #pragma unroll
        for (int kk = 0; kk < 16; kk++) {
            float4 av = *(const float4*)&As[kk][ty<<2];
            float4 bv = *(const float4*)&Bs[kk][tx<<2];
            acc[0][0]+=av.x*bv.x; acc[0][1]+=av.x*bv.y; acc[0][2]+=av.x*bv.z; acc[0][3]+=av.x*bv.w;
            acc[1][0]+=av.y*bv.x; acc[1][1]+=av.y*bv.y; acc[1][2]+=av.y*bv.z; acc[1][3]+=av.y*bv.w;
            acc[2][0]+=av.z*bv.x; acc[2][1]+=av.z*bv.y; acc[2][2]+=av.z*bv.z; acc[2][3]+=av.z*bv.w;
            acc[3][0]+=av.w*bv.x; acc[3][1]+=av.w*bv.y; acc[3][2]+=av.w*bv.z; acc[3][3]+=av.w*bv.w;
        }
        __syncthreads();
    }
    #pragma unroll
    for (int u = 0; u < 4; u++) {
        const int m = m0 + (ty<<2) + u;
        float4 o;
        float* oc = (float*)&o;
        #pragma unroll
        for (int v = 0; v < 4; v++) {
            const int n = n0 + (tx<<2) + v;
            float val = acc[u][v];
            if (BIAS) val += bias[n];
            if (RELU) val = fmaxf(val, 0.f);
            if (DPRED) val = (val - Vm[(size_t)m * N + n]) * dscale;
            oc[v] = val;
        }
        *(float4*)&C[(size_t)m * N + n0 + (tx<<2)] = o;
    }
}

template<bool MASK>
__launch_bounds__(256)
__global__ void gemm_ab(const float* __restrict__ A, const float* __restrict__ Bm,
                        const float* __restrict__ mask, float* __restrict__ C,
                        int M, int N, int K, int Kchunk)
{
    __shared__ float As[16][64];
    __shared__ float Bs[16][64];
    const int t  = threadIdx.x;
    const int tx = t & 15, ty = t >> 4;
    const int m0 = blockIdx.y * 64, n0 = blockIdx.x * 64;
    const int kbeg = blockIdx.z * Kchunk, kend = kbeg + Kchunk;
    const int lrA = t >> 2,  lcA = (t & 3)  << 2;
    const int lrB = t >> 4,  lcB = (t & 15) << 2;
    float acc[4][4] = {};
    for (int k0 = kbeg; k0 < kend; k0 += 16) {
        float4 a4 = *(const float4*)&A [(size_t)(m0 + lrA) * K + k0 + lcA];
        float4 b4 = *(const float4*)&Bm[(size_t)(k0 + lrB) * N + n0 + lcB];
        As[lcA+0][lrA]=a4.x; As[lcA+1][lrA]=a4.y; As[lcA+2][lrA]=a4.z; As[lcA+3][lrA]=a4.w;
        *(float4*)&Bs[lrB][lcB] = b4;
        __syncthreads();
        #pragma unroll
        for (int kk = 0; kk < 16; kk++) {
            float4 av = *(const float4*)&As[kk][ty<<2];
            float4 bv = *(const float4*)&Bs[kk][tx<<2];
            acc[0][0]+=av.x*bv.x; acc[0][1]+=av.x*bv.y; acc[0][2]+=av.x*bv.z; acc[0][3]+=av.x*bv.w;
            acc[1][0]+=av.y*bv.x; acc[1][1]+=av.y*bv.y; acc[1][2]+=av.y*bv.z; acc[1][3]+=av.y*bv.w;
            acc[2][0]+=av.z*bv.x; acc[2][1]+=av.z*bv.y; acc[2][2]+=av.z*bv.z; acc[2][3]+=av.z*bv.w;
            acc[3][0]+=av.w*bv.x; acc[3][1]+=av.w*bv.y; acc[3][2]+=av.w*bv.z; acc[3][3]+=av.w*bv.w;
        }
        __syncthreads();
    }
    float* Co = C + (size_t)blockIdx.z * M * N;
    #pragma unroll
    for (int u = 0; u < 4; u++) {
        const int m = m0 + (ty<<2) + u;
        float4 o;
        float* oc = (float*)&o;
        #pragma unroll
        for (int v = 0; v < 4; v++) {
            float val = acc[u][v];
            if (MASK) val = (mask[(size_t)m * N + n0 + (tx<<2) + v] > 0.f) ? val : 0.f;
            oc[v] = val;
        }
        *(float4*)&Co[(size_t)m * N + n0 + (tx<<2)] = o;
    }
}

__launch_bounds__(256)
__global__ void gemm_aTb(const float* __restrict__ A, const float* __restrict__ Bm,
                         float* __restrict__ Cpart, int L, int M, int N, int Lchunk)
{
    __shared__ float As[16][64];
    __shared__ float Bs[16][64];
    const int t  = threadIdx.x;
    const int tx = t & 15, ty = t >> 4;
    const int m0 = blockIdx.y * 64, n0 = blockIdx.x * 64;
    const int l0b = blockIdx.z * Lchunk;
    const int lr = t >> 4, lc4 = (t & 15) << 2;
    float acc[4][4] = {};
    for (int l0 = l0b; l0 < l0b + Lchunk; l0 += 16) {
        *(float4*)&As[lr][lc4] = *(const float4*)&A [(size_t)(l0 + lr) * M + m0 + lc4];
        *(float4*)&Bs[lr][lc4] = *(const float4*)&Bm[(size_t)(l0 + lr) * N + n0 + lc4];
        __syncthreads();
        #pragma unroll
        for (int kk = 0; kk < 16; kk++) {
            float4 av = *(const float4*)&As[kk][ty<<2];
            float4 bv = *(const float4*)&Bs[kk][tx<<2];
            acc[0][0]+=av.x*bv.x; acc[0][1]+=av.x*bv.y; acc[0][2]+=av.x*bv.z; acc[0][3]+=av.x*bv.w;
            acc[1][0]+=av.y*bv.x; acc[1][1]+=av.y*bv.y; acc[1][2]+=av.y*bv.z; acc[1][3]+=av.y*bv.w;
            acc[2][0]+=av.z*bv.x; acc[2][1]+=av.z*bv.y; acc[2][2]+=av.z*bv.z; acc[2][3]+=av.z*bv.w;
            acc[3][0]+=av.w*bv.x; acc[3][1]+=av.w*bv.y; acc[3][2]+=av.w*bv.z; acc[3][3]+=av.w*bv.w;
        }
        __syncthreads();
    }
    float* Co = Cpart + (size_t)blockIdx.z * M * N;
    #pragma unroll
    for (int u = 0; u < 4; u++) {
        float4 o;
        float* oc = (float*)&o;
        #pragma unroll
        for (int v = 0; v < 4; v++) oc[v] = acc[u][v];
        *(float4*)&Co[(size_t)(m0 + (ty<<2) + u) * N + n0 + (tx<<2)] = o;
    }
}

// ================= small kernels =================
__global__ void combine_k(const float* __restrict__ parts, float* __restrict__ out,
                          int len, int np)
{
    int i = blockIdx.x * 256 + threadIdx.x;
    if (i < len) {
        float s = 0.f;
        for (int p = 0; p < np; p++) s += parts[(size_t)p * len + i];
        out[i] = s;
    }
}

__global__ void colsum_k(const float* __restrict__ A, float* __restrict__ out, int rows, int N)
{
    int c = threadIdx.x;
    float s = 0.f;
    for (int r = 0; r < rows; r++) s += A[(size_t)r * N + c];
    out[c] = s;
}

__global__ void surprise_k()
{
    __shared__ float red[256];
    int t = threadIdx.x;
    float s = 0.f;
    for (int i = t; i < NHD*NKD; i += 256) { float g = g_gW1[i]; s += g*g; }
    for (int i = t; i < NHD;     i += 256) { float g = g_gb1[i]; s += g*g; }
    for (int i = t; i < NVD*NHD; i += 256) { float g = g_gW2[i]; s += g*g; }
    for (int i = t; i < NVD;     i += 256) { float g = g_gb2[i]; s += g*g; }
    red[t] = s; __syncthreads();
    for (int st = 128; st > 0; st >>= 1) { if (t < st) red[t] += red[t+st]; __syncthreads(); }
    if (t == 0) {
        float avg = sqrtf(red[0] * 0.25f);
        g_theta[0] = 0.1f / (1.f + expf(-avg));
    }
}

__global__ void update_k(const float* __restrict__ mW1, const float* __restrict__ mb1,
                         const float* __restrict__ mW2, const float* __restrict__ mb2,
                         const float* __restrict__ bW1, const float* __restrict__ bb1,
                         const float* __restrict__ bW2, const float* __restrict__ bb2)
{
    int i = blockIdx.x * 256 + threadIdx.x;
    float et = g_theta[0];
    const int n1 = NHD*NKD, n2 = n1 + NHD, n3 = n2 + NVD*NHD, n4 = n3 + NVD;
    if (i < n1)       g_nW1[i]   = 0.9f*mW1[i]   + 0.9f*bW1[i]   - et*g_gW1[i];
    else if (i < n2) { int j=i-n1; g_nb1[j] = 0.9f*mb1[j] + 0.9f*bb1[j] - et*g_gb1[j]; }
    else if (i < n3) { int j=i-n2; g_nW2[j] = 0.9f*mW2[j] + 0.9f*bW2[j] - et*g_gW2[j]; }
    else if (i < n4) { int j=i-n3; g_nb2[j] = 0.9f*mb2[j] + 0.9f*bb2[j] - et*g_gb2[j]; }
}

__launch_bounds__(256)
__global__ void softmax_k()
{
    const float* row = g_S + (size_t)blockIdx.x * NH;
    bf16* oh = g_attnh + (size_t)blockIdx.x * NH;
    bf16* ol = g_attnl + (size_t)blockIdx.x * NH;
    const int t = threadIdx.x;
    float v[64];
    float m = -1e30f;
    #pragma unroll
    for (int j = 0; j < 64; j++) { v[j] = row[t + 256*j]; m = fmaxf(m, v[j]); }
    __shared__ float red[256];
    red[t] = m; __syncthreads();
    #pragma unroll
    for (int s = 128; s > 0; s >>= 1) { if (t < s) red[t] = fmaxf(red[t], red[t+s]); __syncthreads(); }
    m = red[0]; __syncthreads();
    float l = 0.f;
    #pragma unroll
    for (int j = 0; j < 64; j++) { v[j] = __expf(v[j] - m); l += v[j]; }
    red[t] = l; __syncthreads();
    #pragma unroll
    for (int s = 128; s > 0; s >>= 1) { if (t < s) red[t] += red[t+s]; __syncthreads(); }
    float inv = 1.f / red[0];
    #pragma unroll
    for (int j = 0; j < 64; j++) {
        float a = v[j] * inv;
        bf16 h = __float2bfloat16(a);
        oh[t + 256*j] = h;
        ol[t + 256*j] = __float2bfloat16(a - __bfloat162float(h));
    }
}

__global__ void entity_k(const float* __restrict__ ent, const float* __restrict__ Wep,
                         const float* __restrict__ bep, const float* __restrict__ Weg,
                         const float* __restrict__ beg)
{
    __shared__ float eavg[DIN];
    __shared__ float ectx[NVD];
    int t = threadIdx.x;
    float s = 0.f;
    for (int e = 0; e < NE; e++) s += ent[e*DIN + t];
    eavg[t] = s * (1.f / NE);
    __syncthreads();
    if (t < NVD) {
        float c = bep[t];
        for (int d = 0; d < DIN; d++) c += eavg[d] * Wep[t*DIN + d];
        ectx[t] = c; g_ectx[t] = c;
    }
    __syncthreads();
    if (t == 0) {
        float g = beg[0];
        for (int j = 0; j < NVD; j++) g += ectx[j] * Weg[j];
        g_eg[0] = 1.f / (1.f + expf(-g));
    }
}

__global__ void fuse_k(const float* __restrict__ kvec, const float* __restrict__ Wg,
                       const float* __restrict__ bg, float* __restrict__ out)
{
    int b = blockIdx.x, i = threadIdx.x;
    float p = g_ctx[b*NVD + i] + kvec[i];
    float s = p * Wg[i];
    #pragma unroll
    for (int o = 16; o > 0; o >>= 1) s += __shfl_down_sync(0xffffffffu, s, o);
    __shared__ float wsum[4];
    __shared__ float gsh;
    if ((i & 31) == 0) wsum[i >> 5] = s;
    __syncthreads();
    if (i == 0) {
        float tot = wsum[0] + wsum[1] + wsum[2] + wsum[3] + bg[0];
        gsh = 1.f / (1.f + expf(-tot));
    }
    __syncthreads();
    float gate = gsh;
    float f = gate * p + (1.f - gate) * g_st[b*NVD + i];
    float eg = g_eg[0];
    out[b*NVD + i] = eg * g_ectx[i] + (1.f - eg) * f;
}

// ================= host =================
extern "C" void kernel_launch(void* const* d_in, const int* in_sizes, int n_in,
                              void* d_out, int out_size)
{
    const float* x     = (const float*)d_in[0];
    const float* hist  = (const float*)d_in[1];
    const float* ent   = (const float*)d_in[2];
    const float* W_K   = (const float*)d_in[3];
    const float* W_V   = (const float*)d_in[4];
    const float* mW1   = (const float*)d_in[5];
    const float* mb1   = (const float*)d_in[6];
    const float* mW2   = (const float*)d_in[7];
    const float* mb2   = (const float*)d_in[8];
    const float* bufW1 = (const float*)d_in[9];
    const float* bufb1 = (const float*)d_in[10];
    const float* bufW2 = (const float*)d_in[11];
    const float* bufb2 = (const float*)d_in[12];
    const float* kvec  = (const float*)d_in[13];
    const float* Wq    = (const float*)d_in[14];
    const float* Wk    = (const float*)d_in[15];
    const float* Wst   = (const float*)d_in[16];
    const float* bst   = (const float*)d_in[17];
    const float* Wg    = (const float*)d_in[18];
    const float* bg    = (const float*)d_in[19];
    // d_in[20..23] dead (gating_loss only)
    const float* Wep   = (const float*)d_in[24];
    const float* bep   = (const float*)d_in[25];
    const float* Weg   = (const float*)d_in[26];
    const float* beg   = (const float*)d_in[27];
    float* out = (float*)d_out;

    static bool init_done = false;
    static cudaStream_t s2;
    static cudaEvent_t ev_fork, ev_join;
    if (!init_done) {
        cudaFuncSetAttribute(hmma_gemm<0>, cudaFuncAttributeMaxDynamicSharedMemorySize, HM_SMEM);
        cudaFuncSetAttribute(hmma_gemm<1>, cudaFuncAttributeMaxDynamicSharedMemorySize, HM_SMEM);
        cudaStreamCreateWithFlags(&s2, cudaStreamNonBlocking);
        cudaEventCreateWithFlags(&ev_fork, cudaEventDisableTiming);
        cudaEventCreateWithFlags(&ev_join, cudaEventDisableTiming);
        init_done = true;
    }

    float *pk,*pv,*ph,*pdp,*pdh,*pgW1p,*pgW2p,*pgW1,*pgb1,*pgW2,*pgb2;
    float *pnW1,*pnb1,*pnW2,*pnb2,*ph2,*pctx,*pS,*paop,*pao,*pst;
    bf16 *pxh,*pxl,*pWqh,*pWql,*pWkh,*pWkl,*phh,*phl,*phTh,*phTl,*pqh,*pql,*pkhh,*pkhl,*pah,*pal;
    cudaGetSymbolAddress((void**)&pk,   g_k);
    cudaGetSymbolAddress((void**)&pv,   g_v);
    cudaGetSymbolAddress((void**)&ph,   g_h);
    cudaGetSymbolAddress((void**)&pdp,  g_dpred);
    cudaGetSymbolAddress((void**)&pdh,  g_dh);
    cudaGetSymbolAddress((void**)&pgW1p,g_gW1p);
    cudaGetSymbolAddress((void**)&pgW2p,g_gW2p);
    cudaGetSymbolAddress((void**)&pgW1, g_gW1);
    cudaGetSymbolAddress((void**)&pgb1, g_gb1);
    cudaGetSymbolAddress((void**)&pgW2, g_gW2);
    cudaGetSymbolAddress((void**)&pgb2, g_gb2);
    cudaGetSymbolAddress((void**)&pnW1, g_nW1);
    cudaGetSymbolAddress((void**)&pnb1, g_nb1);
    cudaGetSymbolAddress((void**)&pnW2, g_nW2);
    cudaGetSymbolAddress((void**)&pnb2, g_nb2);
    cudaGetSymbolAddress((void**)&ph2,  g_h2);
    cudaGetSymbolAddress((void**)&pctx, g_ctx);
    cudaGetSymbolAddress((void**)&pS,   g_S);
    cudaGetSymbolAddress((void**)&paop, g_aop);
    cudaGetSymbolAddress((void**)&pao,  g_ao);
    cudaGetSymbolAddress((void**)&pst,  g_st);
    cudaGetSymbolAddress((void**)&pxh,  g_xh);
    cudaGetSymbolAddress((void**)&pxl,  g_xl);
    cudaGetSymbolAddress((void**)&pWqh, g_Wqh);
    cudaGetSymbolAddress((void**)&pWql, g_Wql);
    cudaGetSymbolAddress((void**)&pWkh, g_Wkh);
    cudaGetSymbolAddress((void**)&pWkl, g_Wkl);
    cudaGetSymbolAddress((void**)&phh,  g_histh);
    cudaGetSymbolAddress((void**)&phl,  g_histl);
    cudaGetSymbolAddress((void**)&phTh, g_histTh);
    cudaGetSymbolAddress((void**)&phTl, g_histTl);
    cudaGetSymbolAddress((void**)&pqh,  g_qh);
    cudaGetSymbolAddress((void**)&pql,  g_ql);
    cudaGetSymbolAddress((void**)&pkhh, g_khh);
    cudaGetSymbolAddress((void**)&pkhl, g_khl);
    cudaGetSymbolAddress((void**)&pah,  g_attnh);
    cudaGetSymbolAddress((void**)&pal,  g_attnl);

    // fork second stream for the independent titan/entity chain
    cudaEventRecord(ev_fork, 0);
    cudaStreamWaitEvent(s2, ev_fork, 0);

    // ===== stream s2: Titan memory chain + entity path (fp32 FFMA) =====
    gemm_abT<false,false,false><<<dim3(NKD/64, NB/64), 256, 0, s2>>>(
        x, W_K, nullptr, nullptr, 0.f, pk, NB, NKD, DIN);
    gemm_abT<false,false,false><<<dim3(NVD/64, NB/64), 256, 0, s2>>>(
        x, W_V, nullptr, nullptr, 0.f, pv, NB, NVD, DIN);
    gemm_abT<true,true,false><<<dim3(NHD/64, NB/64), 256, 0, s2>>>(
        pk, mW1, mb1, nullptr, 0.f, ph, NB, NHD, NKD);
    // pred + fold dpred = (pred - v) * 2/(B*VD)
    gemm_abT<true,false,true><<<dim3(NVD/64, NB/64), 256, 0, s2>>>(
        ph, mW2, mb2, pv, 2.f / (float)(NB*NVD), pdp, NB, NVD, NHD);
    gemm_aTb<<<dim3(NHD/64, NVD/64, NSPLIT_G), 256, 0, s2>>>(pdp, ph, pgW2p, NB, NVD, NHD, NB/NSPLIT_G);
    combine_k<<<(NVD*NHD + 255)/256, 256, 0, s2>>>(pgW2p, pgW2, NVD*NHD, NSPLIT_G);
    colsum_k<<<1, NVD, 0, s2>>>(pdp, pgb2, NB, NVD);
    gemm_ab<true><<<dim3(NHD/64, NB/64, 1), 256, 0, s2>>>(pdp, mW2, ph, pdh, NB, NHD, NVD, NVD);
    colsum_k<<<1, NHD, 0, s2>>>(pdh, pgb1, NB, NHD);
    gemm_aTb<<<dim3(NKD/64, NHD/64, NSPLIT_G), 256, 0, s2>>>(pdh, pk, pgW1p, NB, NHD, NKD, NB/NSPLIT_G);
    combine_k<<<(NHD*NKD + 255)/256, 256, 0, s2>>>(pgW1p, pgW1, NHD*NKD, NSPLIT_G);
    surprise_k<<<1, 256, 0, s2>>>();
    update_k<<<(NHD*NKD + NHD + NVD*NHD + NVD + 255)/256, 256, 0, s2>>>(
        mW1, mb1, mW2, mb2, bufW1, bufb1, bufW2, bufb2);
    gemm_abT<true,true,false><<<dim3(NHD/64, NB/64), 256, 0, s2>>>(
        pk, pnW1, pnb1, nullptr, 0.f, ph2, NB, NHD, NKD);
    gemm_abT<true,false,false><<<dim3(NVD/64, NB/64), 256, 0, s2>>>(
        ph2, pnW2, pnb2, nullptr, 0.f, pctx, NB, NVD, NHD);
    entity_k<<<1, DIN, 0, s2>>>(ent, Wep, bep, Weg, beg);
    cudaEventRecord(ev_join, s2);

    // ===== default stream: attention tensor path =====
    split_k<<<(NB*DIN + 255)/256, 256>>>(x,    pxh,  pxl,  NB*DIN);
    split_k<<<(DIN*DIN + 255)/256, 256>>>(Wq,  pWqh, pWql, DIN*DIN);
    split_k<<<(DIN*DIN + 255)/256, 256>>>(Wk,  pWkh, pWkl, DIN*DIN);
    split_k<<<(NH*DIN + 255)/256, 256>>>(hist, phh,  phl,  NH*DIN);
    tsplit_k<<<dim3(NH/32, DIN/32), dim3(32,8)>>>(hist, phTh, phTl);

    hmma_gemm<1><<<dim3(DIN/128, NB/128, 1), 256, HM_SMEM>>>(
        pxh, pxl, pWqh, pWql, nullptr, pqh, pql, NB, DIN, DIN, DIN);
    hmma_gemm<1><<<dim3(DIN/128, NH/128, 1), 256, HM_SMEM>>>(
        phh, phl, pWkh, pWkl, nullptr, pkhh, pkhl, NH, DIN, DIN, DIN);
    hmma_gemm<0><<<dim3(NH/128, NB/128, 1), 256, HM_SMEM>>>(
        pqh, pql, pkhh, pkhl, pS, nullptr, nullptr, NB, NH, DIN, DIN);
    softmax_k<<<NB, 256>>>();
    hmma_gemm<0><<<dim3(DIN/128, NB/128, NSPLIT_AH), 256, HM_SMEM>>>(
        pah, pal, phTh, phTl, paop, nullptr, nullptr, NB, DIN, NH, NH/NSPLIT_AH);
    combine_k<<<(NB*DIN + 255)/256, 256>>>(paop, pao, NB*DIN, NSPLIT_AH);
    gemm_abT<true,false,false><<<dim3(NVD/64, NB/64), 256>>>(
        pao, Wst, bst, nullptr, 0.f, pst, NB, NVD, DIN);

    // join + fuse
    cudaStreamWaitEvent(0, ev_join, 0);
    fuse_k<<<NB, NVD>>>(kvec, Wg, bg, out);
}

// round 5
// speedup vs baseline: 2.8173x; 1.3271x over previous
#include <cuda_runtime.h>
#include <cuda_bf16.h>
#include <math.h>
#include <stdint.h>

// Problem dims
#define NB   2048
#define NH   16384
#define NE   64
#define DIN  384
#define NKD  128
#define NVD  128
#define NHD  256
#define NSPLIT_G 8
#define NSPLIT_AH 16

typedef __nv_bfloat16 bf16;

// ---------------- scratch (device globals) ----------------
__device__ float g_k[NB*NKD];
__device__ float g_v[NB*NVD];
__device__ float g_h[NB*NHD];
__device__ float g_dpred[NB*NVD];
__device__ float g_dh[NB*NHD];
__device__ float g_gW1p[NSPLIT_G*NHD*NKD];
__device__ float g_gW2p[NSPLIT_G*NVD*NHD];
__device__ float g_gW1[NHD*NKD];
__device__ float g_gb1[NHD];
__device__ float g_gW2[NVD*NHD];
__device__ float g_gb2[NVD];
__device__ float g_nW1[NHD*NKD];
__device__ float g_nb1[NHD];
__device__ float g_nW2[NVD*NHD];
__device__ float g_nb2[NVD];
__device__ float g_h2[NB*NHD];
__device__ float g_ctx[NB*NVD];
__device__ float g_S[33554432];            // 2048*16384 fp32
__device__ float g_aop[NSPLIT_AH*NB*NVD];  // split-K partials of attn@hwT
__device__ float g_st[NB*NVD];
__device__ float g_theta[1];
__device__ float g_ectx[NVD];
__device__ float g_eg[1];
// bf16 split operands
__device__ bf16 g_xh[NB*DIN],   g_xl[NB*DIN];
__device__ bf16 g_Wqh[DIN*DIN], g_Wql[DIN*DIN];
__device__ bf16 g_Wkh[DIN*DIN], g_Wkl[DIN*DIN];
__device__ bf16 g_Wsth[NVD*DIN], g_Wstl[NVD*DIN];
__device__ bf16 g_histh[NH*DIN], g_histl[NH*DIN];
__device__ bf16 g_hwTh[(size_t)NVD*NH], g_hwTl[(size_t)NVD*NH];  // (Wst @ hist^T)
__device__ bf16 g_qh[NB*DIN],   g_ql[NB*DIN];
__device__ bf16 g_khh[NH*DIN],  g_khl[NH*DIN];
__device__ bf16 g_attnh[(size_t)NB*NH], g_attnl[(size_t)NB*NH];

// ================= HMMA (mma.sync) split-bf16 GEMM =================
// C[M,N] = Ah@Bh^T + Ah@Bl^T + Al@Bh^T  (fp32 reg accumulate)
// CTA tile 128x128xK32, 512 threads (16 warps: 4m x 4n, warp tile 32x32).
// 2-stage cp.async pipeline, ldmatrix fragment loads, 80B padded SMEM rows.

#define TILE_B   10240            // 128 rows * 80B padded stride
#define STAGE_B  (4*TILE_B)       // Ah, Al, Bh, Bl
#define HM_SMEM  (2*STAGE_B)      // 81920

__device__ __forceinline__ uint32_t smem_u32(const void* p) {
    uint32_t a;
    asm("{ .reg .u64 t; cvta.to.shared.u64 t, %1; cvt.u32.u64 %0, t; }" : "=r"(a) : "l"(p));
    return a;
}
__device__ __forceinline__ void cp16(uint32_t s, const void* g) {
    asm volatile("cp.async.cg.shared.global [%0], [%1], 16;" :: "r"(s), "l"(g));
}
__device__ __forceinline__ void cp_commit() {
    asm volatile("cp.async.commit_group;" ::: "memory");
}
template<int N>
__device__ __forceinline__ void cp_wait() {
    asm volatile("cp.async.wait_group %0;" :: "n"(N) : "memory");
}
__device__ __forceinline__ void ldsm4(uint32_t* r, uint32_t addr) {
    asm volatile("ldmatrix.sync.aligned.m8n8.x4.shared.b16 {%0,%1,%2,%3}, [%4];"
                 : "=r"(r[0]), "=r"(r[1]), "=r"(r[2]), "=r"(r[3]) : "r"(addr));
}
__device__ __forceinline__ void ldsm2(uint32_t* r, uint32_t addr) {
    asm volatile("ldmatrix.sync.aligned.m8n8.x2.shared.b16 {%0,%1}, [%2];"
                 : "=r"(r[0]), "=r"(r[1]) : "r"(addr));
}
__device__ __forceinline__ void mma_bf16(float* c, const uint32_t* a, const uint32_t* b) {
    asm volatile(
        "mma.sync.aligned.m16n8k16.row.col.f32.bf16.bf16.f32 "
        "{%0,%1,%2,%3}, {%4,%5,%6,%7}, {%8,%9}, {%0,%1,%2,%3};"
        : "+f"(c[0]), "+f"(c[1]), "+f"(c[2]), "+f"(c[3])
        : "r"(a[0]), "r"(a[1]), "r"(a[2]), "r"(a[3]), "r"(b[0]), "r"(b[1]));
}

template<int WRITE_SPLIT>
__global__ void __launch_bounds__(512, 1) hmma_gemm(
    const bf16* __restrict__ Ah, const bf16* __restrict__ Al,
    const bf16* __restrict__ Bh, const bf16* __restrict__ Bl,
    float* __restrict__ Cf, bf16* __restrict__ Ch, bf16* __restrict__ Cl,
    int M, int N, int K, int Kchunk)
{
    extern __shared__ char smem[];
    const int tid = threadIdx.x, wid = tid >> 5, lid = tid & 31;
    const int wm = wid >> 2, wn = wid & 3;   // 4m x 4n warps, warp tile 32x32
    const int g = lid >> 2, t = lid & 3;
    const int n0 = blockIdx.x * 128, m0 = blockIdx.y * 128;
    const int kbeg = blockIdx.z * Kchunk;
    const int iters = Kchunk / 32;

    const uint32_t sb = smem_u32(smem);
    const bf16* srcs[4] = { Ah, Al, Bh, Bl };
    const int   rows[4] = { m0, m0, n0, n0 };

    // ldmatrix stage-relative offsets
    const uint32_t a_off = (uint32_t)((wm*32 + (lid & 15)) * 80 + (lid >> 4) * 16);
    const uint32_t b_off = (uint32_t)((wn*32 + (lid & 7))  * 80 + ((lid >> 3) & 1) * 16);

    // one 16B chunk per tile per thread per stage (512 thr = 128 rows x 4 chunks)
    const int l_row = tid >> 2, l_ch = tid & 3;

    auto load_stage = [&](int stage, int k0) {
        uint32_t base = sb + stage * STAGE_B + l_row*80 + l_ch*16;
        size_t goff = (size_t)l_row * K + k0 + l_ch*8;
        #pragma unroll
        for (int tile = 0; tile < 4; tile++)
            cp16(base + tile*TILE_B, srcs[tile] + (size_t)rows[tile]*K + goff);
    };

    float acc[2][4][4];
    #pragma unroll
    for (int a = 0; a < 2; a++)
        #pragma unroll
        for (int b = 0; b < 4; b++)
            #pragma unroll
            for (int c = 0; c < 4; c++) acc[a][b][c] = 0.f;

    load_stage(0, kbeg);
    cp_commit();

    for (int it = 0; it < iters; it++) {
        if (it + 1 < iters) load_stage((it + 1) & 1, kbeg + (it + 1) * 32);
        cp_commit();
        cp_wait<1>();
        __syncthreads();

        const uint32_t stb = sb + (it & 1) * STAGE_B;
        #pragma unroll
        for (int kb = 0; kb < 2; kb++) {
            const uint32_t ko = kb * 32;
            uint32_t ah[2][4], al[2][4], bh[4][2], bl[4][2];
            #pragma unroll
            for (int mf = 0; mf < 2; mf++) {
                ldsm4(ah[mf], stb +          a_off + mf*(16*80) + ko);
                ldsm4(al[mf], stb + TILE_B + a_off + mf*(16*80) + ko);
            }
            #pragma unroll
            for (int nf = 0; nf < 4; nf++) {
                ldsm2(bh[nf], stb + 2*TILE_B + b_off + nf*(8*80) + ko);
                ldsm2(bl[nf], stb + 3*TILE_B + b_off + nf*(8*80) + ko);
            }
            #pragma unroll
            for (int mf = 0; mf < 2; mf++)
                #pragma unroll
                for (int nf = 0; nf < 4; nf++) {
                    mma_bf16(acc[mf][nf], ah[mf], bh[nf]);
                    mma_bf16(acc[mf][nf], ah[mf], bl[nf]);
                    mma_bf16(acc[mf][nf], al[mf], bh[nf]);
                }
        }
        __syncthreads();
    }

    #pragma unroll
    for (int mf = 0; mf < 2; mf++) {
        #pragma unroll
        for (int nf = 0; nf < 4; nf++) {
            int row0 = m0 + wm*32 + mf*16 + g;
            int col  = n0 + wn*32 + nf*8 + 2*t;
            float* c = acc[mf][nf];
            if (WRITE_SPLIT) {
                bf16 h0 = __float2bfloat16(c[0]);
                bf16 l0 = __float2bfloat16(c[0] - __bfloat162float(h0));
                bf16 h1 = __float2bfloat16(c[1]);
                bf16 l1 = __float2bfloat16(c[1] - __bfloat162float(h1));
                bf16 h2 = __float2bfloat16(c[2]);
                bf16 l2 = __float2bfloat16(c[2] - __bfloat162float(h2));
                bf16 h3 = __float2bfloat16(c[3]);
                bf16 l3 = __float2bfloat16(c[3] - __bfloat162float(h3));
                ushort2 u;
                u.x = *(unsigned short*)&h0; u.y = *(unsigned short*)&h1;
                *(ushort2*)&Ch[(size_t)row0 * N + col] = u;
                u.x = *(unsigned short*)&l0; u.y = *(unsigned short*)&l1;
                *(ushort2*)&Cl[(size_t)row0 * N + col] = u;
                u.x = *(unsigned short*)&h2; u.y = *(unsigned short*)&h3;
                *(ushort2*)&Ch[(size_t)(row0+8) * N + col] = u;
                u.x = *(unsigned short*)&l2; u.y = *(unsigned short*)&l3;
                *(ushort2*)&Cl[(size_t)(row0+8) * N + col] = u;
            } else {
                float* Co = Cf + (size_t)blockIdx.z * M * N;
                *(float2*)&Co[(size_t)row0 * N + col]     = make_float2(c[0], c[1]);
                *(float2*)&Co[(size_t)(row0+8) * N + col] = make_float2(c[2], c[3]);
            }
        }
    }
}

// ================= conversion kernel =================
__global__ void split_k(const float* __restrict__ in, bf16* __restrict__ hi,
                        bf16* __restrict__ lo, int n)
{
    int i = blockIdx.x * 256 + threadIdx.x;
    if (i < n) {
        float v = in[i];
        bf16 h = __float2bfloat16(v);
        hi[i] = h;
        lo[i] = __float2bfloat16(v - __bfloat162float(h));
    }
}

// ================= FFMA GEMMs (titan chain) =================
template<bool BIAS, bool RELU, bool DPRED>
__launch_bounds__(256)
__global__ void gemm_abT(const float* __restrict__ A, const float* __restrict__ Bm,
                         const float* __restrict__ bias, const float* __restrict__ Vm,
                         float dscale, float* __restrict__ C,
                         int M, int N, int K)
{
    __shared__ float As[16][64];
    __shared__ float Bs[16][64];
    const int t  = threadIdx.x;
    const int tx = t & 15, ty = t >> 4;
    const int m0 = blockIdx.y * 64, n0 = blockIdx.x * 64;
    const int lr = t >> 2;
    const int lc = (t & 3) << 2;
    float acc[4][4] = {};
    const float* Ag = A  + (size_t)(m0 + lr) * K + lc;
    const float* Bg = Bm + (size_t)(n0 + lr) * K + lc;
    for (int k0 = 0; k0 < K; k0 += 16) {
        float4 a4 = *(const float4*)(Ag + k0);
        float4 b4 = *(const float4*)(Bg + k0);
        As[lc+0][lr]=a4.x; As[lc+1][lr]=a4.y; As[lc+2][lr]=a4.z; As[lc+3][lr]=a4.w;
        Bs[lc+0][lr]=b4.x; Bs[lc+1][lr]=b4.y; Bs[lc+2][lr]=b4.z; Bs[lc+3][lr]=b4.w;
        __syncthreads();
        #pragma unroll
        for (int kk = 0; kk < 16; kk++) {
            float4 av = *(const float4*)&As[kk][ty<<2];
            float4 bv = *(const float4*)&Bs[kk][tx<<2];
            acc[0][0]+=av.x*bv.x; acc[0][1]+=av.x*bv.y; acc[0][2]+=av.x*bv.z; acc[0][3]+=av.x*bv.w;
            acc[1][0]+=av.y*bv.x; acc[1][1]+=av.y*bv.y; acc[1][2]+=av.y*bv.z; acc[1][3]+=av.y*bv.w;
            acc[2][0]+=av.z*bv.x; acc[2][1]+=av.z*bv.y; acc[2][2]+=av.z*bv.z; acc[2][3]+=av.z*bv.w;
            acc[3][0]+=av.w*bv.x; acc[3][1]+=av.w*bv.y; acc[3][2]+=av.w*bv.z; acc[3][3]+=av.w*bv.w;
        }
        __syncthreads();
    }
    #pragma unroll
    for (int u = 0; u < 4; u++) {
        const int m = m0 + (ty<<2) + u;
        float4 o;
        float* oc = (float*)&o;
        #pragma unroll
        for (int v = 0; v < 4; v++) {
            const int n = n0 + (tx<<2) + v;
            float val = acc[u][v];
            if (BIAS) val += bias[n];
            if (RELU) val = fmaxf(val, 0.f);
            if (DPRED) val = (val - Vm[(size_t)m * N + n]) * dscale;
            oc[v] = val;
        }
        *(float4*)&C[(size_t)m * N + n0 + (tx<<2)] = o;
    }
}

template<bool MASK>
__launch_bounds__(256)
__global__ void gemm_ab(const float* __restrict__ A, const float* __restrict__ Bm,
                        const float* __restrict__ mask, float* __restrict__ C,
                        int M, int N, int K, int Kchunk)
{
    __shared__ float As[16][64];
    __shared__ float Bs[16][64];
    const int t  = threadIdx.x;
    const int tx = t & 15, ty = t >> 4;
    const int m0 = blockIdx.y * 64, n0 = blockIdx.x * 64;
    const int kbeg = blockIdx.z * Kchunk, kend = kbeg + Kchunk;
    const int lrA = t >> 2,  lcA = (t & 3)  << 2;
    const int lrB = t >> 4,  lcB = (t & 15) << 2;
    float acc[4][4] = {};
    for (int k0 = kbeg; k0 < kend; k0 += 16) {
        float4 a4 = *(const float4*)&A [(size_t)(m0 + lrA) * K + k0 + lcA];
        float4 b4 = *(const float4*)&Bm[(size_t)(k0 + lrB) * N + n0 + lcB];
        As[lcA+0][lrA]=a4.x; As[lcA+1][lrA]=a4.y; As[lcA+2][lrA]=a4.z; As[lcA+3][lrA]=a4.w;
        *(float4*)&Bs[lrB][lcB] = b4;
        __syncthreads();
        #pragma unroll
        for (int kk = 0; kk < 16; kk++) {
            float4 av = *(const float4*)&As[kk][ty<<2];
            float4 bv = *(const float4*)&Bs[kk][tx<<2];
            acc[0][0]+=av.x*bv.x; acc[0][1]+=av.x*bv.y; acc[0][2]+=av.x*bv.z; acc[0][3]+=av.x*bv.w;
            acc[1][0]+=av.y*bv.x; acc[1][1]+=av.y*bv.y; acc[1][2]+=av.y*bv.z; acc[1][3]+=av.y*bv.w;
            acc[2][0]+=av.z*bv.x; acc[2][1]+=av.z*bv.y; acc[2][2]+=av.z*bv.z; acc[2][3]+=av.z*bv.w;
            acc[3][0]+=av.w*bv.x; acc[3][1]+=av.w*bv.y; acc[3][2]+=av.w*bv.z; acc[3][3]+=av.w*bv.w;
        }
        __syncthreads();
    }
    float* Co = C + (size_t)blockIdx.z * M * N;
    #pragma unroll
    for (int u = 0; u < 4; u++) {
        const int m = m0 + (ty<<2) + u;
        float4 o;
        float* oc = (float*)&o;
        #pragma unroll
        for (int v = 0; v < 4; v++) {
            float val = acc[u][v];
            if (MASK) val = (mask[(size_t)m * N + n0 + (tx<<2) + v] > 0.f) ? val : 0.f;
            oc[v] = val;
        }
        *(float4*)&Co[(size_t)m * N + n0 + (tx<<2)] = o;
    }
}

__launch_bounds__(256)
__global__ void gemm_aTb(const float* __restrict__ A, const float* __restrict__ Bm,
                         float* __restrict__ Cpart, int L, int M, int N, int Lchunk)
{
    __shared__ float As[16][64];
    __shared__ float Bs[16][64];
    const int t  = threadIdx.x;
    const int tx = t & 15, ty = t >> 4;
    const int m0 = blockIdx.y * 64, n0 = blockIdx.x * 64;
    const int l0b = blockIdx.z * Lchunk;
    const int lr = t >> 4, lc4 = (t & 15) << 2;
    float acc[4][4] = {};
    for (int l0 = l0b; l0 < l0b + Lchunk; l0 += 16) {
        *(float4*)&As[lr][lc4] = *(const float4*)&A [(size_t)(l0 + lr) * M + m0 + lc4];
        *(float4*)&Bs[lr][lc4] = *(const float4*)&Bm[(size_t)(l0 + lr) * N + n0 + lc4];
        __syncthreads();
        #pragma unroll
        for (int kk = 0; kk < 16; kk++) {
            float4 av = *(const float4*)&As[kk][ty<<2];
            float4 bv = *(const float4*)&Bs[kk][tx<<2];
            acc[0][0]+=av.x*bv.x; acc[0][1]+=av.x*bv.y; acc[0][2]+=av.x*bv.z; acc[0][3]+=av.x*bv.w;
            acc[1][0]+=av.y*bv.x; acc[1][1]+=av.y*bv.y; acc[1][2]+=av.y*bv.z; acc[1][3]+=av.y*bv.w;
            acc[2][0]+=av.z*bv.x; acc[2][1]+=av.z*bv.y; acc[2][2]+=av.z*bv.z; acc[2][3]+=av.z*bv.w;
            acc[3][0]+=av.w*bv.x; acc[3][1]+=av.w*bv.y; acc[3][2]+=av.w*bv.z; acc[3][3]+=av.w*bv.w;
        }
        __syncthreads();
    }
    float* Co = Cpart + (size_t)blockIdx.z * M * N;
    #pragma unroll
    for (int u = 0; u < 4; u++) {
        float4 o;
        float* oc = (float*)&o;
        #pragma unroll
        for (int v = 0; v < 4; v++) oc[v] = acc[u][v];
        *(float4*)&Co[(size_t)(m0 + (ty<<2) + u) * N + n0 + (tx<<2)] = o;
    }
}

// ================= small kernels =================
__global__ void combine_k(const float* __restrict__ parts, float* __restrict__ out,
                          int len, int np)
{
    int i = blockIdx.x * 256 + threadIdx.x;
    if (i < len) {
        float s = 0.f;
        for (int p = 0; p < np; p++) s += parts[(size_t)p * len + i];
        out[i] = s;
    }
}

__global__ void colsum_k(const float* __restrict__ A, float* __restrict__ out, int rows, int N)
{
    int c = threadIdx.x;
    float s = 0.f;
    for (int r = 0; r < rows; r++) s += A[(size_t)r * N + c];
    out[c] = s;
}

__global__ void surprise_k()
{
    __shared__ float red[256];
    int t = threadIdx.x;
    float s = 0.f;
    for (int i = t; i < NHD*NKD; i += 256) { float g = g_gW1[i]; s += g*g; }
    for (int i = t; i < NHD;     i += 256) { float g = g_gb1[i]; s += g*g; }
    for (int i = t; i < NVD*NHD; i += 256) { float g = g_gW2[i]; s += g*g; }
    for (int i = t; i < NVD;     i += 256) { float g = g_gb2[i]; s += g*g; }
    red[t] = s; __syncthreads();
    for (int st = 128; st > 0; st >>= 1) { if (t < st) red[t] += red[t+st]; __syncthreads(); }
    if (t == 0) {
        float avg = sqrtf(red[0] * 0.25f);
        g_theta[0] = 0.1f / (1.f + expf(-avg));
    }
}

__global__ void update_k(const float* __restrict__ mW1, const float* __restrict__ mb1,
                         const float* __restrict__ mW2, const float* __restrict__ mb2,
                         const float* __restrict__ bW1, const float* __restrict__ bb1,
                         const float* __restrict__ bW2, const float* __restrict__ bb2)
{
    int i = blockIdx.x * 256 + threadIdx.x;
    float et = g_theta[0];
    const int n1 = NHD*NKD, n2 = n1 + NHD, n3 = n2 + NVD*NHD, n4 = n3 + NVD;
    if (i < n1)       g_nW1[i]   = 0.9f*mW1[i]   + 0.9f*bW1[i]   - et*g_gW1[i];
    else if (i < n2) { int j=i-n1; g_nb1[j] = 0.9f*mb1[j] + 0.9f*bb1[j] - et*g_gb1[j]; }
    else if (i < n3) { int j=i-n2; g_nW2[j] = 0.9f*mW2[j] + 0.9f*bW2[j] - et*g_gW2[j]; }
    else if (i < n4) { int j=i-n3; g_nb2[j] = 0.9f*mb2[j] + 0.9f*bb2[j] - et*g_gb2[j]; }
}

__launch_bounds__(256)
__global__ void softmax_k()
{
    const float* row = g_S + (size_t)blockIdx.x * NH;
    bf16* oh = g_attnh + (size_t)blockIdx.x * NH;
    bf16* ol = g_attnl + (size_t)blockIdx.x * NH;
    const int t = threadIdx.x;
    float v[64];
    float m = -1e30f;
    #pragma unroll
    for (int j = 0; j < 64; j++) { v[j] = row[t + 256*j]; m = fmaxf(m, v[j]); }
    __shared__ float red[256];
    red[t] = m; __syncthreads();
    #pragma unroll
    for (int s = 128; s > 0; s >>= 1) { if (t < s) red[t] = fmaxf(red[t], red[t+s]); __syncthreads(); }
    m = red[0]; __syncthreads();
    float l = 0.f;
    #pragma unroll
    for (int j = 0; j < 64; j++) { v[j] = __expf(v[j] - m); l += v[j]; }
    red[t] = l; __syncthreads();
    #pragma unroll
    for (int s = 128; s > 0; s >>= 1) { if (t < s) red[t] += red[t+s]; __syncthreads(); }
    float inv = 1.f / red[0];
    #pragma unroll
    for (int j = 0; j < 64; j++) {
        float a = v[j] * inv;
        bf16 h = __float2bfloat16(a);
        oh[t + 256*j] = h;
        ol[t + 256*j] = __float2bfloat16(a - __bfloat162float(h));
    }
}

__global__ void entity_k(const float* __restrict__ ent, const float* __restrict__ Wep,
                         const float* __restrict__ bep, const float* __restrict__ Weg,
                         const float* __restrict__ beg)
{
    __shared__ float eavg[DIN];
    __shared__ float ectx[NVD];
    int t = threadIdx.x;
    float s = 0.f;
    for (int e = 0; e < NE; e++) s += ent[e*DIN + t];
    eavg[t] = s * (1.f / NE);
    __syncthreads();
    if (t < NVD) {
        float c = bep[t];
        for (int d = 0; d < DIN; d++) c += eavg[d] * Wep[t*DIN + d];
        ectx[t] = c; g_ectx[t] = c;
    }
    __syncthreads();
    if (t == 0) {
        float g = beg[0];
        for (int j = 0; j < NVD; j++) g += ectx[j] * Weg[j];
        g_eg[0] = 1.f / (1.f + expf(-g));
    }
}

__global__ void fuse_k(const float* __restrict__ kvec, const float* __restrict__ Wg,
                       const float* __restrict__ bg, const float* __restrict__ bst,
                       float* __restrict__ out)
{
    int b = blockIdx.x, i = threadIdx.x;
    float p = g_ctx[b*NVD + i] + kvec[i];
    float s = p * Wg[i];
    #pragma unroll
    for (int o = 16; o > 0; o >>= 1) s += __shfl_down_sync(0xffffffffu, s, o);
    __shared__ float wsum[4];
    __shared__ float gsh;
    if ((i & 31) == 0) wsum[i >> 5] = s;
    __syncthreads();
    if (i == 0) {
        float tot = wsum[0] + wsum[1] + wsum[2] + wsum[3] + bg[0];
        gsh = 1.f / (1.f + expf(-tot));
    }
    __syncthreads();
    float gate = gsh;
    float st = g_st[b*NVD + i] + bst[i];
    float f = gate * p + (1.f - gate) * st;
    float eg = g_eg[0];
    out[b*NVD + i] = eg * g_ectx[i] + (1.f - eg) * f;
}

// ================= host =================
extern "C" void kernel_launch(void* const* d_in, const int* in_sizes, int n_in,
                              void* d_out, int out_size)
{
    const float* x     = (const float*)d_in[0];
    const float* hist  = (const float*)d_in[1];
    const float* ent   = (const float*)d_in[2];
    const float* W_K   = (const float*)d_in[3];
    const float* W_V   = (const float*)d_in[4];
    const float* mW1   = (const float*)d_in[5];
    const float* mb1   = (const float*)d_in[6];
    const float* mW2   = (const float*)d_in[7];
    const float* mb2   = (const float*)d_in[8];
    const float* bufW1 = (const float*)d_in[9];
    const float* bufb1 = (const float*)d_in[10];
    const float* bufW2 = (const float*)d_in[11];
    const float* bufb2 = (const float*)d_in[12];
    const float* kvec  = (const float*)d_in[13];
    const float* Wq    = (const float*)d_in[14];
    const float* Wk    = (const float*)d_in[15];
    const float* Wst   = (const float*)d_in[16];
    const float* bst   = (const float*)d_in[17];
    const float* Wg    = (const float*)d_in[18];
    const float* bg    = (const float*)d_in[19];
    // d_in[20..23] dead (gating_loss only)
    const float* Wep   = (const float*)d_in[24];
    const float* bep   = (const float*)d_in[25];
    const float* Weg   = (const float*)d_in[26];
    const float* beg   = (const float*)d_in[27];
    float* out = (float*)d_out;

    static bool init_done = false;
    static cudaStream_t s2;
    static cudaEvent_t ev_fork, ev_join;
    if (!init_done) {
        cudaFuncSetAttribute(hmma_gemm<0>, cudaFuncAttributeMaxDynamicSharedMemorySize, HM_SMEM);
        cudaFuncSetAttribute(hmma_gemm<1>, cudaFuncAttributeMaxDynamicSharedMemorySize, HM_SMEM);
        cudaStreamCreateWithFlags(&s2, cudaStreamNonBlocking);
        cudaEventCreateWithFlags(&ev_fork, cudaEventDisableTiming);
        cudaEventCreateWithFlags(&ev_join, cudaEventDisableTiming);
        init_done = true;
    }

    float *pk,*pv,*ph,*pdp,*pdh,*pgW1p,*pgW2p,*pgW1,*pgb1,*pgW2,*pgb2;
    float *pnW1,*pnb1,*pnW2,*pnb2,*ph2,*pctx,*pS,*paop,*pst;
    bf16 *pxh,*pxl,*pWqh,*pWql,*pWkh,*pWkl,*pWsth,*pWstl,*phh,*phl;
    bf16 *phwTh,*phwTl,*pqh,*pql,*pkhh,*pkhl,*pah,*pal;
    cudaGetSymbolAddress((void**)&pk,   g_k);
    cudaGetSymbolAddress((void**)&pv,   g_v);
    cudaGetSymbolAddress((void**)&ph,   g_h);
    cudaGetSymbolAddress((void**)&pdp,  g_dpred);
    cudaGetSymbolAddress((void**)&pdh,  g_dh);
    cudaGetSymbolAddress((void**)&pgW1p,g_gW1p);
    cudaGetSymbolAddress((void**)&pgW2p,g_gW2p);
    cudaGetSymbolAddress((void**)&pgW1, g_gW1);
    cudaGetSymbolAddress((void**)&pgb1, g_gb1);
    cudaGetSymbolAddress((void**)&pgW2, g_gW2);
    cudaGetSymbolAddress((void**)&pgb2, g_gb2);
    cudaGetSymbolAddress((void**)&pnW1, g_nW1);
    cudaGetSymbolAddress((void**)&pnb1, g_nb1);
    cudaGetSymbolAddress((void**)&pnW2, g_nW2);
    cudaGetSymbolAddress((void**)&pnb2, g_nb2);
    cudaGetSymbolAddress((void**)&ph2,  g_h2);
    cudaGetSymbolAddress((void**)&pctx, g_ctx);
    cudaGetSymbolAddress((void**)&pS,   g_S);
    cudaGetSymbolAddress((void**)&paop, g_aop);
    cudaGetSymbolAddress((void**)&pst,  g_st);
    cudaGetSymbolAddress((void**)&pxh,  g_xh);
    cudaGetSymbolAddress((void**)&pxl,  g_xl);
    cudaGetSymbolAddress((void**)&pWqh, g_Wqh);
    cudaGetSymbolAddress((void**)&pWql, g_Wql);
    cudaGetSymbolAddress((void**)&pWkh, g_Wkh);
    cudaGetSymbolAddress((void**)&pWkl, g_Wkl);
    cudaGetSymbolAddress((void**)&pWsth,g_Wsth);
    cudaGetSymbolAddress((void**)&pWstl,g_Wstl);
    cudaGetSymbolAddress((void**)&phh,  g_histh);
    cudaGetSymbolAddress((void**)&phl,  g_histl);
    cudaGetSymbolAddress((void**)&phwTh,g_hwTh);
    cudaGetSymbolAddress((void**)&phwTl,g_hwTl);
    cudaGetSymbolAddress((void**)&pqh,  g_qh);
    cudaGetSymbolAddress((void**)&pql,  g_ql);
    cudaGetSymbolAddress((void**)&pkhh, g_khh);
    cudaGetSymbolAddress((void**)&pkhl, g_khl);
    cudaGetSymbolAddress((void**)&pah,  g_attnh);
    cudaGetSymbolAddress((void**)&pal,  g_attnl);

    // fork second stream for the independent titan/entity chain
    cudaEventRecord(ev_fork, 0);
    cudaStreamWaitEvent(s2, ev_fork, 0);

    // ===== stream s2: Titan memory chain + entity path (fp32 FFMA) =====
    gemm_abT<false,false,false><<<dim3(NKD/64, NB/64), 256, 0, s2>>>(
        x, W_K, nullptr, nullptr, 0.f, pk, NB, NKD, DIN);
    gemm_abT<false,false,false><<<dim3(NVD/64, NB/64), 256, 0, s2>>>(
        x, W_V, nullptr, nullptr, 0.f, pv, NB, NVD, DIN);
    gemm_abT<true,true,false><<<dim3(NHD/64, NB/64), 256, 0, s2>>>(
        pk, mW1, mb1, nullptr, 0.f, ph, NB, NHD, NKD);
    gemm_abT<true,false,true><<<dim3(NVD/64, NB/64), 256, 0, s2>>>(
        ph, mW2, mb2, pv, 2.f / (float)(NB*NVD), pdp, NB, NVD, NHD);
    gemm_aTb<<<dim3(NHD/64, NVD/64, NSPLIT_G), 256, 0, s2>>>(pdp, ph, pgW2p, NB, NVD, NHD, NB/NSPLIT_G);
    combine_k<<<(NVD*NHD + 255)/256, 256, 0, s2>>>(pgW2p, pgW2, NVD*NHD, NSPLIT_G);
    colsum_k<<<1, NVD, 0, s2>>>(pdp, pgb2, NB, NVD);
    gemm_ab<true><<<dim3(NHD/64, NB/64, 1), 256, 0, s2>>>(pdp, mW2, ph, pdh, NB, NHD, NVD, NVD);
    colsum_k<<<1, NHD, 0, s2>>>(pdh, pgb1, NB, NHD);
    gemm_aTb<<<dim3(NKD/64, NHD/64, NSPLIT_G), 256, 0, s2>>>(pdh, pk, pgW1p, NB, NHD, NKD, NB/NSPLIT_G);
    combine_k<<<(NHD*NKD + 255)/256, 256, 0, s2>>>(pgW1p, pgW1, NHD*NKD, NSPLIT_G);
    surprise_k<<<1, 256, 0, s2>>>();
    update_k<<<(NHD*NKD + NHD + NVD*NHD + NVD + 255)/256, 256, 0, s2>>>(
        mW1, mb1, mW2, mb2, bufW1, bufb1, bufW2, bufb2);
    gemm_abT<true,true,false><<<dim3(NHD/64, NB/64), 256, 0, s2>>>(
        pk, pnW1, pnb1, nullptr, 0.f, ph2, NB, NHD, NKD);
    gemm_abT<true,false,false><<<dim3(NVD/64, NB/64), 256, 0, s2>>>(
        ph2, pnW2, pnb2, nullptr, 0.f, pctx, NB, NVD, NHD);
    entity_k<<<1, DIN, 0, s2>>>(ent, Wep, bep, Weg, beg);
    cudaEventRecord(ev_join, s2);

    // ===== default stream: attention tensor path =====
    split_k<<<(NB*DIN + 255)/256, 256>>>(x,    pxh,  pxl,  NB*DIN);
    split_k<<<(DIN*DIN + 255)/256, 256>>>(Wq,  pWqh, pWql, DIN*DIN);
    split_k<<<(DIN*DIN + 255)/256, 256>>>(Wk,  pWkh, pWkl, DIN*DIN);
    split_k<<<(NVD*DIN + 255)/256, 256>>>(Wst, pWsth,pWstl,NVD*DIN);
    split_k<<<(NH*DIN + 255)/256, 256>>>(hist, phh,  phl,  NH*DIN);

    // q = x @ Wq^T  -> split bf16
    hmma_gemm<1><<<dim3(DIN/128, NB/128, 1), 512, HM_SMEM>>>(
        pxh, pxl, pWqh, pWql, nullptr, pqh, pql, NB, DIN, DIN, DIN);
    // hwT = Wst @ hist^T  -> split bf16, [NVD, NH]
    hmma_gemm<1><<<dim3(NH/128, NVD/128, 1), 512, HM_SMEM>>>(
        pWsth, pWstl, phh, phl, nullptr, phwTh, phwTl, NVD, NH, DIN, DIN);
    // kh = hist @ Wk^T -> split bf16
    hmma_gemm<1><<<dim3(DIN/128, NH/128, 1), 512, HM_SMEM>>>(
        phh, phl, pWkh, pWkl, nullptr, pkhh, pkhl, NH, DIN, DIN, DIN);
    // S = q @ kh^T -> fp32
    hmma_gemm<0><<<dim3(NH/128, NB/128, 1), 512, HM_SMEM>>>(
        pqh, pql, pkhh, pkhl, pS, nullptr, nullptr, NB, NH, DIN, DIN);
    softmax_k<<<NB, 256>>>();
    // st(raw) = attn @ hwT^T -> fp32 partial slabs (split-K over NH), combine
    hmma_gemm<0><<<dim3(NVD/128, NB/128, NSPLIT_AH), 512, HM_SMEM>>>(
        pah, pal, phwTh, phwTl, paop, nullptr, nullptr, NB, NVD, NH, NH/NSPLIT_AH);
    combine_k<<<(NB*NVD + 255)/256, 256>>>(paop, pst, NB*NVD, NSPLIT_AH);

    // join + fuse (adds bst to st inside)
    cudaStreamWaitEvent(0, ev_join, 0);
    fuse_k<<<NB, NVD>>>(kvec, Wg, bg, bst, out);
}

// round 6
// speedup vs baseline: 3.0979x; 1.0996x over previous
#include <cuda_runtime.h>
#include <cuda_bf16.h>
#include <math.h>
#include <stdint.h>

// Problem dims
#define NB   2048
#define NH   16384
#define NE   64
#define DIN  384
#define NKD  128
#define NVD  128
#define NHD  256
#define NSPLIT_G 8
#define NSPLIT_AH 16

typedef __nv_bfloat16 bf16;

// ---------------- scratch (device globals) ----------------
__device__ float g_k[NB*NKD];
__device__ float g_v[NB*NVD];
__device__ float g_h[NB*NHD];
__device__ float g_dpred[NB*NVD];
__device__ float g_dh[NB*NHD];
__device__ float g_gW1p[NSPLIT_G*NHD*NKD];
__device__ float g_gW2p[NSPLIT_G*NVD*NHD];
__device__ float g_gW1[NHD*NKD];
__device__ float g_gb1[NHD];
__device__ float g_gW2[NVD*NHD];
__device__ float g_gb2[NVD];
__device__ float g_nW1[NHD*NKD];
__device__ float g_nb1[NHD];
__device__ float g_nW2[NVD*NHD];
__device__ float g_nb2[NVD];
__device__ float g_h2[NB*NHD];
__device__ float g_ctx[NB*NVD];
__device__ float g_S[33554432];            // 2048*16384 fp32
__device__ float g_aop[NSPLIT_AH*NB*NVD];
__device__ float g_st[NB*NVD];
__device__ float g_WT[DIN*DIN];            // W'^T = Wk^T @ Wq (fp32)
__device__ float g_theta[1];
__device__ float g_ectx[NVD];
__device__ float g_eg[1];
// bf16 split operands
__device__ bf16 g_xh[NB*DIN],   g_xl[NB*DIN];
__device__ bf16 g_WTh[DIN*DIN], g_WTl[DIN*DIN];
__device__ bf16 g_Wsth[NVD*DIN], g_Wstl[NVD*DIN];
__device__ bf16 g_histh[NH*DIN], g_histl[NH*DIN];
__device__ bf16 g_hwTh[(size_t)NVD*NH], g_hwTl[(size_t)NVD*NH];  // (Wst @ hist^T)
__device__ bf16 g_qh[NB*DIN],   g_ql[NB*DIN];                    // q' = x @ W'
__device__ bf16 g_attnh[(size_t)NB*NH], g_attnl[(size_t)NB*NH];

// ================= HMMA (mma.sync) split-bf16 GEMM =================
// C[M,N] = Ah@Bh^T + Ah@Bl^T + Al@Bh^T  (fp32 reg accumulate)
// CTA tile 128x128xK32, 512 threads (16 warps: 4m x 4n, warp tile 32x32).
// 2-stage cp.async pipeline, ldmatrix fragment loads, 80B padded SMEM rows.
// MMA issue order is TERM-MAJOR: 8 independent accumulators between reuses.

#define TILE_B   10240            // 128 rows * 80B padded stride
#define STAGE_B  (4*TILE_B)       // Ah, Al, Bh, Bl
#define HM_SMEM  (2*STAGE_B)      // 81920

__device__ __forceinline__ uint32_t smem_u32(const void* p) {
    uint32_t a;
    asm("{ .reg .u64 t; cvta.to.shared.u64 t, %1; cvt.u32.u64 %0, t; }" : "=r"(a) : "l"(p));
    return a;
}
__device__ __forceinline__ void cp16(uint32_t s, const void* g) {
    asm volatile("cp.async.cg.shared.global [%0], [%1], 16;" :: "r"(s), "l"(g));
}
__device__ __forceinline__ void cp_commit() {
    asm volatile("cp.async.commit_group;" ::: "memory");
}
template<int N>
__device__ __forceinline__ void cp_wait() {
    asm volatile("cp.async.wait_group %0;" :: "n"(N) : "memory");
}
__device__ __forceinline__ void ldsm4(uint32_t* r, uint32_t addr) {
    asm volatile("ldmatrix.sync.aligned.m8n8.x4.shared.b16 {%0,%1,%2,%3}, [%4];"
                 : "=r"(r[0]), "=r"(r[1]), "=r"(r[2]), "=r"(r[3]) : "r"(addr));
}
__device__ __forceinline__ void ldsm2(uint32_t* r, uint32_t addr) {
    asm volatile("ldmatrix.sync.aligned.m8n8.x2.shared.b16 {%0,%1}, [%2];"
                 : "=r"(r[0]), "=r"(r[1]) : "r"(addr));
}
__device__ __forceinline__ void mma_bf16(float* c, const uint32_t* a, const uint32_t* b) {
    asm volatile(
        "mma.sync.aligned.m16n8k16.row.col.f32.bf16.bf16.f32 "
        "{%0,%1,%2,%3}, {%4,%5,%6,%7}, {%8,%9}, {%0,%1,%2,%3};"
        : "+f"(c[0]), "+f"(c[1]), "+f"(c[2]), "+f"(c[3])
        : "r"(a[0]), "r"(a[1]), "r"(a[2]), "r"(a[3]), "r"(b[0]), "r"(b[1]));
}

template<int WRITE_SPLIT>
__global__ void __launch_bounds__(512, 1) hmma_gemm(
    const bf16* __restrict__ Ah, const bf16* __restrict__ Al,
    const bf16* __restrict__ Bh, const bf16* __restrict__ Bl,
    float* __restrict__ Cf, bf16* __restrict__ Ch, bf16* __restrict__ Cl,
    int M, int N, int K, int Kchunk)
{
    extern __shared__ char smem[];
    const int tid = threadIdx.x, wid = tid >> 5, lid = tid & 31;
    const int wm = wid >> 2, wn = wid & 3;   // 4m x 4n warps, warp tile 32x32
    const int g = lid >> 2, t = lid & 3;
    const int n0 = blockIdx.x * 128, m0 = blockIdx.y * 128;
    const int kbeg = blockIdx.z * Kchunk;
    const int iters = Kchunk / 32;

    const uint32_t sb = smem_u32(smem);
    const bf16* srcs[4] = { Ah, Al, Bh, Bl };
    const int   rows[4] = { m0, m0, n0, n0 };

    const uint32_t a_off = (uint32_t)((wm*32 + (lid & 15)) * 80 + (lid >> 4) * 16);
    const uint32_t b_off = (uint32_t)((wn*32 + (lid & 7))  * 80 + ((lid >> 3) & 1) * 16);

    const int l_row = tid >> 2, l_ch = tid & 3;

    auto load_stage = [&](int stage, int k0) {
        uint32_t base = sb + stage * STAGE_B + l_row*80 + l_ch*16;
        size_t goff = (size_t)l_row * K + k0 + l_ch*8;
        #pragma unroll
        for (int tile = 0; tile < 4; tile++)
            cp16(base + tile*TILE_B, srcs[tile] + (size_t)rows[tile]*K + goff);
    };

    float acc[2][4][4];
    #pragma unroll
    for (int a = 0; a < 2; a++)
        #pragma unroll
        for (int b = 0; b < 4; b++)
            #pragma unroll
            for (int c = 0; c < 4; c++) acc[a][b][c] = 0.f;

    load_stage(0, kbeg);
    cp_commit();

    for (int it = 0; it < iters; it++) {
        if (it + 1 < iters) load_stage((it + 1) & 1, kbeg + (it + 1) * 32);
        cp_commit();
        cp_wait<1>();
        __syncthreads();

        const uint32_t stb = sb + (it & 1) * STAGE_B;
        #pragma unroll
        for (int kb = 0; kb < 2; kb++) {
            const uint32_t ko = kb * 32;
            uint32_t ah[2][4], al[2][4], bh[4][2], bl[4][2];
            #pragma unroll
            for (int mf = 0; mf < 2; mf++) {
                ldsm4(ah[mf], stb +          a_off + mf*(16*80) + ko);
                ldsm4(al[mf], stb + TILE_B + a_off + mf*(16*80) + ko);
            }
            #pragma unroll
            for (int nf = 0; nf < 4; nf++) {
                ldsm2(bh[nf], stb + 2*TILE_B + b_off + nf*(8*80) + ko);
                ldsm2(bl[nf], stb + 3*TILE_B + b_off + nf*(8*80) + ko);
            }
            // term-major: 8 independent accs between same-acc reuse
            #pragma unroll
            for (int mf = 0; mf < 2; mf++)
                #pragma unroll
                for (int nf = 0; nf < 4; nf++)
                    mma_bf16(acc[mf][nf], ah[mf], bh[nf]);
            #pragma unroll
            for (int mf = 0; mf < 2; mf++)
                #pragma unroll
                for (int nf = 0; nf < 4; nf++)
                    mma_bf16(acc[mf][nf], ah[mf], bl[nf]);
            #pragma unroll
            for (int mf = 0; mf < 2; mf++)
                #pragma unroll
                for (int nf = 0; nf < 4; nf++)
                    mma_bf16(acc[mf][nf], al[mf], bh[nf]);
        }
        __syncthreads();
    }

    #pragma unroll
    for (int mf = 0; mf < 2; mf++) {
        #pragma unroll
        for (int nf = 0; nf < 4; nf++) {
            int row0 = m0 + wm*32 + mf*16 + g;
            int col  = n0 + wn*32 + nf*8 + 2*t;
            float* c = acc[mf][nf];
            if (WRITE_SPLIT) {
                bf16 h0 = __float2bfloat16(c[0]);
                bf16 l0 = __float2bfloat16(c[0] - __bfloat162float(h0));
                bf16 h1 = __float2bfloat16(c[1]);
                bf16 l1 = __float2bfloat16(c[1] - __bfloat162float(h1));
                bf16 h2 = __float2bfloat16(c[2]);
                bf16 l2 = __float2bfloat16(c[2] - __bfloat162float(h2));
                bf16 h3 = __float2bfloat16(c[3]);
                bf16 l3 = __float2bfloat16(c[3] - __bfloat162float(h3));
                ushort2 u;
                u.x = *(unsigned short*)&h0; u.y = *(unsigned short*)&h1;
                *(ushort2*)&Ch[(size_t)row0 * N + col] = u;
                u.x = *(unsigned short*)&l0; u.y = *(unsigned short*)&l1;
                *(ushort2*)&Cl[(size_t)row0 * N + col] = u;
                u.x = *(unsigned short*)&h2; u.y = *(unsigned short*)&h3;
                *(ushort2*)&Ch[(size_t)(row0+8) * N + col] = u;
                u.x = *(unsigned short*)&l2; u.y = *(unsigned short*)&l3;
                *(ushort2*)&Cl[(size_t)(row0+8) * N + col] = u;
            } else {
                float* Co = Cf + (size_t)blockIdx.z * M * N;
                *(float2*)&Co[(size_t)row0 * N + col]     = make_float2(c[0], c[1]);
                *(float2*)&Co[(size_t)(row0+8) * N + col] = make_float2(c[2], c[3]);
            }
        }
    }
}

// ================= conversion kernel =================
__global__ void split_k(const float* __restrict__ in, bf16* __restrict__ hi,
                        bf16* __restrict__ lo, int n)
{
    int i = blockIdx.x * 256 + threadIdx.x;
    if (i < n) {
        float v = in[i];
        bf16 h = __float2bfloat16(v);
        hi[i] = h;
        lo[i] = __float2bfloat16(v - __bfloat162float(h));
    }
}

// ================= FFMA GEMMs (titan chain + W'T) =================
template<bool BIAS, bool RELU, bool DPRED>
__launch_bounds__(256)
__global__ void gemm_abT(const float* __restrict__ A, const float* __restrict__ Bm,
                         const float* __restrict__ bias, const float* __restrict__ Vm,
                         float dscale, float* __restrict__ C,
                         int M, int N, int K)
{
    __shared__ float As[16][64];
    __shared__ float Bs[16][64];
    const int t  = threadIdx.x;
    const int tx = t & 15, ty = t >> 4;
    const int m0 = blockIdx.y * 64, n0 = blockIdx.x * 64;
    const int lr = t >> 2;
    const int lc = (t & 3) << 2;
    float acc[4][4] = {};
    const float* Ag = A  + (size_t)(m0 + lr) * K + lc;
    const float* Bg = Bm + (size_t)(n0 + lr) * K + lc;
    for (int k0 = 0; k0 < K; k0 += 16) {
        float4 a4 = *(const float4*)(Ag + k0);
        float4 b4 = *(const float4*)(Bg + k0);
        As[lc+0][lr]=a4.x; As[lc+1][lr]=a4.y; As[lc+2][lr]=a4.z; As[lc+3][lr]=a4.w;
        Bs[lc+0][lr]=b4.x; Bs[lc+1][lr]=b4.y; Bs[lc+2][lr]=b4.z; Bs[lc+3][lr]=b4.w;
        __syncthreads();
        #pragma unroll
        for (int kk = 0; kk < 16; kk++) {
            float4 av = *(const float4*)&As[kk][ty<<2];
            float4 bv = *(const float4*)&Bs[kk][tx<<2];
            acc[0][0]+=av.x*bv.x; acc[0][1]+=av.x*bv.y; acc[0][2]+=av.x*bv.z; acc[0][3]+=av.x*bv.w;
            acc[1][0]+=av.y*bv.x; acc[1][1]+=av.y*bv.y; acc[1][2]+=av.y*bv.z; acc[1][3]+=av.y*bv.w;
            acc[2][0]+=av.z*bv.x; acc[2][1]+=av.z*bv.y; acc[2][2]+=av.z*bv.z; acc[2][3]+=av.z*bv.w;
            acc[3][0]+=av.w*bv.x; acc[3][1]+=av.w*bv.y; acc[3][2]+=av.w*bv.z; acc[3][3]+=av.w*bv.w;
        }
        __syncthreads();
    }
    #pragma unroll
    for (int u = 0; u < 4; u++) {
        const int m = m0 + (ty<<2) + u;
        float4 o;
        float* oc = (float*)&o;
        #pragma unroll
        for (int v = 0; v < 4; v++) {
            const int n = n0 + (tx<<2) + v;
            float val = acc[u][v];
            if (BIAS) val += bias[n];
            if (RELU) val = fmaxf(val, 0.f);
            if (DPRED) val = (val - Vm[(size_t)m * N + n]) * dscale;
            oc[v] = val;
        }
        *(float4*)&C[(size_t)m * N + n0 + (tx<<2)] = o;
    }
}

template<bool MASK>
__launch_bounds__(256)
__global__ void gemm_ab(const float* __restrict__ A, const float* __restrict__ Bm,
                        const float* __restrict__ mask, float* __restrict__ C,
                        int M, int N, int K, int Kchunk)
{
    __shared__ float As[16][64];
    __shared__ float Bs[16][64];
    const int t  = threadIdx.x;
    const int tx = t & 15, ty = t >> 4;
    const int m0 = blockIdx.y * 64, n0 = blockIdx.x * 64;
    const int kbeg = blockIdx.z * Kchunk, kend = kbeg + Kchunk;
    const int lrA = t >> 2,  lcA = (t & 3)  << 2;
    const int lrB = t >> 4,  lcB = (t & 15) << 2;
    float acc[4][4] = {};
    for (int k0 = kbeg; k0 < kend; k0 += 16) {
        float4 a4 = *(const float4*)&A [(size_t)(m0 + lrA) * K + k0 + lcA];
        float4 b4 = *(const float4*)&Bm[(size_t)(k0 + lrB) * N + n0 + lcB];
        As[lcA+0][lrA]=a4.x; As[lcA+1][lrA]=a4.y; As[lcA+2][lrA]=a4.z; As[lcA+3][lrA]=a4.w;
        *(float4*)&Bs[lrB][lcB] = b4;
        __syncthreads();
        #pragma unroll
        for (int kk = 0; kk < 16; kk++) {
            float4 av = *(const float4*)&As[kk][ty<<2];
            float4 bv = *(const float4*)&Bs[kk][tx<<2];
            acc[0][0]+=av.x*bv.x; acc[0][1]+=av.x*bv.y; acc[0][2]+=av.x*bv.z; acc[0][3]+=av.x*bv.w;
            acc[1][0]+=av.y*bv.x; acc[1][1]+=av.y*bv.y; acc[1][2]+=av.y*bv.z; acc[1][3]+=av.y*bv.w;
            acc[2][0]+=av.z*bv.x; acc[2][1]+=av.z*bv.y; acc[2][2]+=av.z*bv.z; acc[2][3]+=av.z*bv.w;
            acc[3][0]+=av.w*bv.x; acc[3][1]+=av.w*bv.y; acc[3][2]+=av.w*bv.z; acc[3][3]+=av.w*bv.w;
        }
        __syncthreads();
    }
    float* Co = C + (size_t)blockIdx.z * M * N;
    #pragma unroll
    for (int u = 0; u < 4; u++) {
        const int m = m0 + (ty<<2) + u;
        float4 o;
        float* oc = (float*)&o;
        #pragma unroll
        for (int v = 0; v < 4; v++) {
            float val = acc[u][v];
            if (MASK) val = (mask[(size_t)m * N + n0 + (tx<<2) + v] > 0.f) ? val : 0.f;
            oc[v] = val;
        }
        *(float4*)&Co[(size_t)m * N + n0 + (tx<<2)] = o;
    }
}

__launch_bounds__(256)
__global__ void gemm_aTb(const float* __restrict__ A, const float* __restrict__ Bm,
                         float* __restrict__ Cpart, int L, int M, int N, int Lchunk)
{
    __shared__ float As[16][64];
    __shared__ float Bs[16][64];
    const int t  = threadIdx.x;
    const int tx = t & 15, ty = t >> 4;
    const int m0 = blockIdx.y * 64, n0 = blockIdx.x * 64;
    const int l0b = blockIdx.z * Lchunk;
    const int lr = t >> 4, lc4 = (t & 15) << 2;
    float acc[4][4] = {};
    for (int l0 = l0b; l0 < l0b + Lchunk; l0 += 16) {
        *(float4*)&As[lr][lc4] = *(const float4*)&A [(size_t)(l0 + lr) * M + m0 + lc4];
        *(float4*)&Bs[lr][lc4] = *(const float4*)&Bm[(size_t)(l0 + lr) * N + n0 + lc4];
        __syncthreads();
        #pragma unroll
        for (int kk = 0; kk < 16; kk++) {
            float4 av = *(const float4*)&As[kk][ty<<2];
            float4 bv = *(const float4*)&Bs[kk][tx<<2];
            acc[0][0]+=av.x*bv.x; acc[0][1]+=av.x*bv.y; acc[0][2]+=av.x*bv.z; acc[0][3]+=av.x*bv.w;
            acc[1][0]+=av.y*bv.x; acc[1][1]+=av.y*bv.y; acc[1][2]+=av.y*bv.z; acc[1][3]+=av.y*bv.w;
            acc[2][0]+=av.z*bv.x; acc[2][1]+=av.z*bv.y; acc[2][2]+=av.z*bv.z; acc[2][3]+=av.z*bv.w;
            acc[3][0]+=av.w*bv.x; acc[3][1]+=av.w*bv.y; acc[3][2]+=av.w*bv.z; acc[3][3]+=av.w*bv.w;
        }
        __syncthreads();
    }
    float* Co = Cpart + (size_t)blockIdx.z * M * N;
    #pragma unroll
    for (int u = 0; u < 4; u++) {
        float4 o;
        float* oc = (float*)&o;
        #pragma unroll
        for (int v = 0; v < 4; v++) oc[v] = acc[u][v];
        *(float4*)&Co[(size_t)(m0 + (ty<<2) + u) * N + n0 + (tx<<2)] = o;
    }
}

// ================= small kernels =================
__global__ void combine_k(const float* __restrict__ parts, float* __restrict__ out,
                          int len, int np)
{
    int i = blockIdx.x * 256 + threadIdx.x;
    if (i < len) {
        float s = 0.f;
        for (int p = 0; p < np; p++) s += parts[(size_t)p * len + i];
        out[i] = s;
    }
}

__global__ void colsum_k(const float* __restrict__ A, float* __restrict__ out, int rows, int N)
{
    int c = threadIdx.x;
    float s = 0.f;
    for (int r = 0; r < rows; r++) s += A[(size_t)r * N + c];
    out[c] = s;
}

__global__ void surprise_k()
{
    __shared__ float red[256];
    int t = threadIdx.x;
    float s = 0.f;
    for (int i = t; i < NHD*NKD; i += 256) { float g = g_gW1[i]; s += g*g; }
    for (int i = t; i < NHD;     i += 256) { float g = g_gb1[i]; s += g*g; }
    for (int i = t; i < NVD*NHD; i += 256) { float g = g_gW2[i]; s += g*g; }
    for (int i = t; i < NVD;     i += 256) { float g = g_gb2[i]; s += g*g; }
    red[t] = s; __syncthreads();
    for (int st = 128; st > 0; st >>= 1) { if (t < st) red[t] += red[t+st]; __syncthreads(); }
    if (t == 0) {
        float avg = sqrtf(red[0] * 0.25f);
        g_theta[0] = 0.1f / (1.f + expf(-avg));
    }
}

__global__ void update_k(const float* __restrict__ mW1, const float* __restrict__ mb1,
                         const float* __restrict__ mW2, const float* __restrict__ mb2,
                         const float* __restrict__ bW1, const float* __restrict__ bb1,
                         const float* __restrict__ bW2, const float* __restrict__ bb2)
{
    int i = blockIdx.x * 256 + threadIdx.x;
    float et = g_theta[0];
    const int n1 = NHD*NKD, n2 = n1 + NHD, n3 = n2 + NVD*NHD, n4 = n3 + NVD;
    if (i < n1)       g_nW1[i]   = 0.9f*mW1[i]   + 0.9f*bW1[i]   - et*g_gW1[i];
    else if (i < n2) { int j=i-n1; g_nb1[j] = 0.9f*mb1[j] + 0.9f*bb1[j] - et*g_gb1[j]; }
    else if (i < n3) { int j=i-n2; g_nW2[j] = 0.9f*mW2[j] + 0.9f*bW2[j] - et*g_gW2[j]; }
    else if (i < n4) { int j=i-n3; g_nb2[j] = 0.9f*mb2[j] + 0.9f*bb2[j] - et*g_gb2[j]; }
}

__launch_bounds__(256)
__global__ void softmax_k()
{
    const float* row = g_S + (size_t)blockIdx.x * NH;
    bf16* oh = g_attnh + (size_t)blockIdx.x * NH;
    bf16* ol = g_attnl + (size_t)blockIdx.x * NH;
    const int t = threadIdx.x;
    float v[64];
    float m = -1e30f;
    #pragma unroll
    for (int j = 0; j < 64; j++) { v[j] = row[t + 256*j]; m = fmaxf(m, v[j]); }
    __shared__ float red[256];
    red[t] = m; __syncthreads();
    #pragma unroll
    for (int s = 128; s > 0; s >>= 1) { if (t < s) red[t] = fmaxf(red[t], red[t+s]); __syncthreads(); }
    m = red[0]; __syncthreads();
    float l = 0.f;
    #pragma unroll
    for (int j = 0; j < 64; j++) { v[j] = __expf(v[j] - m); l += v[j]; }
    red[t] = l; __syncthreads();
    #pragma unroll
    for (int s = 128; s > 0; s >>= 1) { if (t < s) red[t] += red[t+s]; __syncthreads(); }
    float inv = 1.f / red[0];
    #pragma unroll
    for (int j = 0; j < 64; j++) {
        float a = v[j] * inv;
        bf16 h = __float2bfloat16(a);
        oh[t + 256*j] = h;
        ol[t + 256*j] = __float2bfloat16(a - __bfloat162float(h));
    }
}

__global__ void entity_k(const float* __restrict__ ent, const float* __restrict__ Wep,
                         const float* __restrict__ bep, const float* __restrict__ Weg,
                         const float* __restrict__ beg)
{
    __shared__ float eavg[DIN];
    __shared__ float ectx[NVD];
    int t = threadIdx.x;
    float s = 0.f;
    for (int e = 0; e < NE; e++) s += ent[e*DIN + t];
    eavg[t] = s * (1.f / NE);
    __syncthreads();
    if (t < NVD) {
        float c = bep[t];
        for (int d = 0; d < DIN; d++) c += eavg[d] * Wep[t*DIN + d];
        ectx[t] = c; g_ectx[t] = c;
    }
    __syncthreads();
    if (t == 0) {
        float g = beg[0];
        for (int j = 0; j < NVD; j++) g += ectx[j] * Weg[j];
        g_eg[0] = 1.f / (1.f + expf(-g));
    }
}

__global__ void fuse_k(const float* __restrict__ kvec, const float* __restrict__ Wg,
                       const float* __restrict__ bg, const float* __restrict__ bst,
                       float* __restrict__ out)
{
    int b = blockIdx.x, i = threadIdx.x;
    float p = g_ctx[b*NVD + i] + kvec[i];
    float s = p * Wg[i];
    #pragma unroll
    for (int o = 16; o > 0; o >>= 1) s += __shfl_down_sync(0xffffffffu, s, o);
    __shared__ float wsum[4];
    __shared__ float gsh;
    if ((i & 31) == 0) wsum[i >> 5] = s;
    __syncthreads();
    if (i == 0) {
        float tot = wsum[0] + wsum[1] + wsum[2] + wsum[3] + bg[0];
        gsh = 1.f / (1.f + expf(-tot));
    }
    __syncthreads();
    float gate = gsh;
    float st = g_st[b*NVD + i] + bst[i];
    float f = gate * p + (1.f - gate) * st;
    float eg = g_eg[0];
    out[b*NVD + i] = eg * g_ectx[i] + (1.f - eg) * f;
}

// ================= host =================
extern "C" void kernel_launch(void* const* d_in, const int* in_sizes, int n_in,
                              void* d_out, int out_size)
{
    const float* x     = (const float*)d_in[0];
    const float* hist  = (const float*)d_in[1];
    const float* ent   = (const float*)d_in[2];
    const float* W_K   = (const float*)d_in[3];
    const float* W_V   = (const float*)d_in[4];
    const float* mW1   = (const float*)d_in[5];
    const float* mb1   = (const float*)d_in[6];
    const float* mW2   = (const float*)d_in[7];
    const float* mb2   = (const float*)d_in[8];
    const float* bufW1 = (const float*)d_in[9];
    const float* bufb1 = (const float*)d_in[10];
    const float* bufW2 = (const float*)d_in[11];
    const float* bufb2 = (const float*)d_in[12];
    const float* kvec  = (const float*)d_in[13];
    const float* Wq    = (const float*)d_in[14];
    const float* Wk    = (const float*)d_in[15];
    const float* Wst   = (const float*)d_in[16];
    const float* bst   = (const float*)d_in[17];
    const float* Wg    = (const float*)d_in[18];
    const float* bg    = (const float*)d_in[19];
    // d_in[20..23] dead (gating_loss only)
    const float* Wep   = (const float*)d_in[24];
    const float* bep   = (const float*)d_in[25];
    const float* Weg   = (const float*)d_in[26];
    const float* beg   = (const float*)d_in[27];
    float* out = (float*)d_out;

    static bool init_done = false;
    static cudaStream_t s2;
    static cudaEvent_t ev_fork, ev_join;
    if (!init_done) {
        cudaFuncSetAttribute(hmma_gemm<0>, cudaFuncAttributeMaxDynamicSharedMemorySize, HM_SMEM);
        cudaFuncSetAttribute(hmma_gemm<1>, cudaFuncAttributeMaxDynamicSharedMemorySize, HM_SMEM);
        cudaStreamCreateWithFlags(&s2, cudaStreamNonBlocking);
        cudaEventCreateWithFlags(&ev_fork, cudaEventDisableTiming);
        cudaEventCreateWithFlags(&ev_join, cudaEventDisableTiming);
        init_done = true;
    }

    float *pk,*pv,*ph,*pdp,*pdh,*pgW1p,*pgW2p,*pgW1,*pgb1,*pgW2,*pgb2;
    float *pnW1,*pnb1,*pnW2,*pnb2,*ph2,*pctx,*pS,*paop,*pst,*pWT;
    bf16 *pxh,*pxl,*pWTh,*pWTl,*pWsth,*pWstl,*phh,*phl;
    bf16 *phwTh,*phwTl,*pqh,*pql,*pah,*pal;
    cudaGetSymbolAddress((void**)&pk,   g_k);
    cudaGetSymbolAddress((void**)&pv,   g_v);
    cudaGetSymbolAddress((void**)&ph,   g_h);
    cudaGetSymbolAddress((void**)&pdp,  g_dpred);
    cudaGetSymbolAddress((void**)&pdh,  g_dh);
    cudaGetSymbolAddress((void**)&pgW1p,g_gW1p);
    cudaGetSymbolAddress((void**)&pgW2p,g_gW2p);
    cudaGetSymbolAddress((void**)&pgW1, g_gW1);
    cudaGetSymbolAddress((void**)&pgb1, g_gb1);
    cudaGetSymbolAddress((void**)&pgW2, g_gW2);
    cudaGetSymbolAddress((void**)&pgb2, g_gb2);
    cudaGetSymbolAddress((void**)&pnW1, g_nW1);
    cudaGetSymbolAddress((void**)&pnb1, g_nb1);
    cudaGetSymbolAddress((void**)&pnW2, g_nW2);
    cudaGetSymbolAddress((void**)&pnb2, g_nb2);
    cudaGetSymbolAddress((void**)&ph2,  g_h2);
    cudaGetSymbolAddress((void**)&pctx, g_ctx);
    cudaGetSymbolAddress((void**)&pS,   g_S);
    cudaGetSymbolAddress((void**)&paop, g_aop);
    cudaGetSymbolAddress((void**)&pst,  g_st);
    cudaGetSymbolAddress((void**)&pWT,  g_WT);
    cudaGetSymbolAddress((void**)&pxh,  g_xh);
    cudaGetSymbolAddress((void**)&pxl,  g_xl);
    cudaGetSymbolAddress((void**)&pWTh, g_WTh);
    cudaGetSymbolAddress((void**)&pWTl, g_WTl);
    cudaGetSymbolAddress((void**)&pWsth,g_Wsth);
    cudaGetSymbolAddress((void**)&pWstl,g_Wstl);
    cudaGetSymbolAddress((void**)&phh,  g_histh);
    cudaGetSymbolAddress((void**)&phl,  g_histl);
    cudaGetSymbolAddress((void**)&phwTh,g_hwTh);
    cudaGetSymbolAddress((void**)&phwTl,g_hwTl);
    cudaGetSymbolAddress((void**)&pqh,  g_qh);
    cudaGetSymbolAddress((void**)&pql,  g_ql);
    cudaGetSymbolAddress((void**)&pah,  g_attnh);
    cudaGetSymbolAddress((void**)&pal,  g_attnl);

    // fork second stream for the independent titan/entity chain
    cudaEventRecord(ev_fork, 0);
    cudaStreamWaitEvent(s2, ev_fork, 0);

    // ===== stream s2: Titan memory chain + entity path (fp32 FFMA) =====
    gemm_abT<false,false,false><<<dim3(NKD/64, NB/64), 256, 0, s2>>>(
        x, W_K, nullptr, nullptr, 0.f, pk, NB, NKD, DIN);
    gemm_abT<false,false,false><<<dim3(NVD/64, NB/64), 256, 0, s2>>>(
        x, W_V, nullptr, nullptr, 0.f, pv, NB, NVD, DIN);
    gemm_abT<true,true,false><<<dim3(NHD/64, NB/64), 256, 0, s2>>>(
        pk, mW1, mb1, nullptr, 0.f, ph, NB, NHD, NKD);
    gemm_abT<true,false,true><<<dim3(NVD/64, NB/64), 256, 0, s2>>>(
        ph, mW2, mb2, pv, 2.f / (float)(NB*NVD), pdp, NB, NVD, NHD);
    gemm_aTb<<<dim3(NHD/64, NVD/64, NSPLIT_G), 256, 0, s2>>>(pdp, ph, pgW2p, NB, NVD, NHD, NB/NSPLIT_G);
    combine_k<<<(NVD*NHD + 255)/256, 256, 0, s2>>>(pgW2p, pgW2, NVD*NHD, NSPLIT_G);
    colsum_k<<<1, NVD, 0, s2>>>(pdp, pgb2, NB, NVD);
    gemm_ab<true><<<dim3(NHD/64, NB/64, 1), 256, 0, s2>>>(pdp, mW2, ph, pdh, NB, NHD, NVD, NVD);
    colsum_k<<<1, NHD, 0, s2>>>(pdh, pgb1, NB, NHD);
    gemm_aTb<<<dim3(NKD/64, NHD/64, NSPLIT_G), 256, 0, s2>>>(pdh, pk, pgW1p, NB, NHD, NKD, NB/NSPLIT_G);
    combine_k<<<(NHD*NKD + 255)/256, 256, 0, s2>>>(pgW1p, pgW1, NHD*NKD, NSPLIT_G);
    surprise_k<<<1, 256, 0, s2>>>();
    update_k<<<(NHD*NKD + NHD + NVD*NHD + NVD + 255)/256, 256, 0, s2>>>(
        mW1, mb1, mW2, mb2, bufW1, bufb1, bufW2, bufb2);
    gemm_abT<true,true,false><<<dim3(NHD/64, NB/64), 256, 0, s2>>>(
        pk, pnW1, pnb1, nullptr, 0.f, ph2, NB, NHD, NKD);
    gemm_abT<true,false,false><<<dim3(NVD/64, NB/64), 256, 0, s2>>>(
        ph2, pnW2, pnb2, nullptr, 0.f, pctx, NB, NVD, NHD);
    entity_k<<<1, DIN, 0, s2>>>(ent, Wep, bep, Weg, beg);
    cudaEventRecord(ev_join, s2);

    // ===== default stream: attention tensor path =====
    // W'^T = Wk^T @ Wq  (so hmma's B^T = W' and q' = x @ W')
    gemm_aTb<<<dim3(DIN/64, DIN/64, 1), 256>>>(Wk, Wq, pWT, DIN, DIN, DIN, DIN);
    split_k<<<(DIN*DIN + 255)/256, 256>>>(pWT, pWTh, pWTl, DIN*DIN);
    split_k<<<(NB*DIN + 255)/256, 256>>>(x,    pxh,  pxl,  NB*DIN);
    split_k<<<(NVD*DIN + 255)/256, 256>>>(Wst, pWsth,pWstl,NVD*DIN);
    split_k<<<(NH*DIN + 255)/256, 256>>>(hist, phh,  phl,  NH*DIN);

    // q' = x @ W'  -> split bf16
    hmma_gemm<1><<<dim3(DIN/128, NB/128, 1), 512, HM_SMEM>>>(
        pxh, pxl, pWTh, pWTl, nullptr, pqh, pql, NB, DIN, DIN, DIN);
    // hwT = Wst @ hist^T  -> split bf16, [NVD, NH]
    hmma_gemm<1><<<dim3(NH/128, NVD/128, 1), 512, HM_SMEM>>>(
        pWsth, pWstl, phh, phl, nullptr, phwTh, phwTl, NVD, NH, DIN, DIN);
    // S = q' @ hist^T -> fp32
    hmma_gemm<0><<<dim3(NH/128, NB/128, 1), 512, HM_SMEM>>>(
        pqh, pql, phh, phl, pS, nullptr, nullptr, NB, NH, DIN, DIN);
    softmax_k<<<NB, 256>>>();
    // st(raw) = attn @ hwT^T -> fp32 partial slabs (split-K over NH), combine
    hmma_gemm<0><<<dim3(NVD/128, NB/128, NSPLIT_AH), 512, HM_SMEM>>>(
        pah, pal, phwTh, phwTl, paop, nullptr, nullptr, NB, NVD, NH, NH/NSPLIT_AH);
    combine_k<<<(NB*NVD + 255)/256, 256>>>(paop, pst, NB*NVD, NSPLIT_AH);

    // join + fuse (adds bst to st inside)
    cudaStreamWaitEvent(0, ev_join, 0);
    fuse_k<<<NB, NVD>>>(kvec, Wg, bg, bst, out);
}

// round 7
// speedup vs baseline: 3.1021x; 1.0014x over previous
#include <cuda_runtime.h>
#include <cuda_bf16.h>
#include <cuda_fp16.h>
#include <math.h>
#include <stdint.h>

// Problem dims
#define NB   2048
#define NH   16384
#define NE   64
#define DIN  384
#define NKD  128
#define NVD  128
#define NHD  256
#define NSPLIT_G 8
#define NSPLIT_AH 16

typedef __nv_bfloat16 bf16;
typedef __half fp16;

// ---------------- scratch (device globals) ----------------
__device__ float g_k[NB*NKD];
__device__ float g_v[NB*NVD];
__device__ float g_h[NB*NHD];
__device__ float g_dpred[NB*NVD];
__device__ float g_dh[NB*NHD];
__device__ float g_gW1p[NSPLIT_G*NHD*NKD];
__device__ float g_gW2p[NSPLIT_G*NVD*NHD];
__device__ float g_gW1[NHD*NKD];
__device__ float g_gb1[NHD];
__device__ float g_gW2[NVD*NHD];
__device__ float g_gb2[NVD];
__device__ float g_nW1[NHD*NKD];
__device__ float g_nb1[NHD];
__device__ float g_nW2[NVD*NHD];
__device__ float g_nb2[NVD];
__device__ float g_h2[NB*NHD];
__device__ float g_ctx[NB*NVD];
__device__ float g_S[33554432];            // 2048*16384 fp32
__device__ float g_aop[NSPLIT_AH*NB*NVD];
__device__ float g_st[NB*NVD];
__device__ float g_WT[DIN*DIN];            // W'^T = Wk^T @ Wq (fp32)
__device__ float g_theta[1];
__device__ float g_ectx[NVD];
__device__ float g_eg[1];
// split operands
__device__ bf16 g_xh[NB*DIN],   g_xl[NB*DIN];
__device__ bf16 g_WTh[DIN*DIN], g_WTl[DIN*DIN];
__device__ bf16 g_Wsth[NVD*DIN], g_Wstl[NVD*DIN];
__device__ bf16 g_histh[NH*DIN], g_histl[NH*DIN];
__device__ fp16 g_hwTh[(size_t)NVD*NH], g_hwTl[(size_t)NVD*NH];  // (Wst @ hist^T) fp16 split
__device__ bf16 g_qh[NB*DIN],   g_ql[NB*DIN];                    // q' = x @ W'
__device__ fp16 g_attnP[(size_t)NB*NH];                          // P fp16 (unsplit)

// ================= HMMA (mma.sync) GEMM =================
// AMODE 0: C = Ah@Bh^T + Ah@Bl^T + Al@Bh^T (bf16 3-term)
// AMODE 1: C = A@Bh^T + A@Bl^T            (fp16 2-term, A unsplit)
// WMODE 0: fp32 -> Cf + z*M*N; 1: bf16 hi/lo; 2: fp16 hi/lo
// CTA tile 128x128xK32, 512 threads (16 warps: 4m x 4n, warp tile 32x32),
// 2-stage cp.async, ldmatrix, 80B padded rows, term-major MMA order.

#define TILE_B   10240
#define STAGE_B  (4*TILE_B)
#define HM_SMEM  (2*STAGE_B)      // 81920

__device__ __forceinline__ uint32_t smem_u32(const void* p) {
    uint32_t a;
    asm("{ .reg .u64 t; cvta.to.shared.u64 t, %1; cvt.u32.u64 %0, t; }" : "=r"(a) : "l"(p));
    return a;
}
__device__ __forceinline__ void cp16(uint32_t s, const void* g) {
    asm volatile("cp.async.cg.shared.global [%0], [%1], 16;" :: "r"(s), "l"(g));
}
__device__ __forceinline__ void cp_commit() {
    asm volatile("cp.async.commit_group;" ::: "memory");
}
template<int N>
__device__ __forceinline__ void cp_wait() {
    asm volatile("cp.async.wait_group %0;" :: "n"(N) : "memory");
}
__device__ __forceinline__ void ldsm4(uint32_t* r, uint32_t addr) {
    asm volatile("ldmatrix.sync.aligned.m8n8.x4.shared.b16 {%0,%1,%2,%3}, [%4];"
                 : "=r"(r[0]), "=r"(r[1]), "=r"(r[2]), "=r"(r[3]) : "r"(addr));
}
__device__ __forceinline__ void ldsm2(uint32_t* r, uint32_t addr) {
    asm volatile("ldmatrix.sync.aligned.m8n8.x2.shared.b16 {%0,%1}, [%2];"
                 : "=r"(r[0]), "=r"(r[1]) : "r"(addr));
}
__device__ __forceinline__ void mma_bf16(float* c, const uint32_t* a, const uint32_t* b) {
    asm volatile(
        "mma.sync.aligned.m16n8k16.row.col.f32.bf16.bf16.f32 "
        "{%0,%1,%2,%3}, {%4,%5,%6,%7}, {%8,%9}, {%0,%1,%2,%3};"
        : "+f"(c[0]), "+f"(c[1]), "+f"(c[2]), "+f"(c[3])
        : "r"(a[0]), "r"(a[1]), "r"(a[2]), "r"(a[3]), "r"(b[0]), "r"(b[1]));
}
__device__ __forceinline__ void mma_f16(float* c, const uint32_t* a, const uint32_t* b) {
    asm volatile(
        "mma.sync.aligned.m16n8k16.row.col.f32.f16.f16.f32 "
        "{%0,%1,%2,%3}, {%4,%5,%6,%7}, {%8,%9}, {%0,%1,%2,%3};"
        : "+f"(c[0]), "+f"(c[1]), "+f"(c[2]), "+f"(c[3])
        : "r"(a[0]), "r"(a[1]), "r"(a[2]), "r"(a[3]), "r"(b[0]), "r"(b[1]));
}

template<int WMODE>
__device__ __forceinline__ void split_store(float v, unsigned short& h, unsigned short& l) {
    if (WMODE == 2) {
        fp16 hh = __float2half(v);
        fp16 ll = __float2half(v - __half2float(hh));
        h = *(unsigned short*)&hh; l = *(unsigned short*)&ll;
    } else {
        bf16 hh = __float2bfloat16(v);
        bf16 ll = __float2bfloat16(v - __bfloat162float(hh));
        h = *(unsigned short*)&hh; l = *(unsigned short*)&ll;
    }
}

template<int WMODE, int AMODE>
__global__ void __launch_bounds__(512, 1) hmma_gemm(
    const bf16* __restrict__ Ah, const bf16* __restrict__ Al,
    const bf16* __restrict__ Bh, const bf16* __restrict__ Bl,
    float* __restrict__ Cf, unsigned short* __restrict__ Ch, unsigned short* __restrict__ Cl,
    int M, int N, int K, int Kchunk)
{
    extern __shared__ char smem[];
    const int tid = threadIdx.x, wid = tid >> 5, lid = tid & 31;
    const int wm = wid >> 2, wn = wid & 3;
    const int g = lid >> 2, t = lid & 3;
    const int n0 = blockIdx.x * 128, m0 = blockIdx.y * 128;
    const int kbeg = blockIdx.z * Kchunk;
    const int iters = Kchunk / 32;

    const uint32_t sb = smem_u32(smem);
    const bf16* srcs[4] = { Ah, Al, Bh, Bl };
    const int   rows[4] = { m0, m0, n0, n0 };

    const uint32_t a_off = (uint32_t)((wm*32 + (lid & 15)) * 80 + (lid >> 4) * 16);
    const uint32_t b_off = (uint32_t)((wn*32 + (lid & 7))  * 80 + ((lid >> 3) & 1) * 16);

    const int l_row = tid >> 2, l_ch = tid & 3;

    auto load_stage = [&](int stage, int k0) {
        uint32_t base = sb + stage * STAGE_B + l_row*80 + l_ch*16;
        size_t goff = (size_t)l_row * K + k0 + l_ch*8;
        #pragma unroll
        for (int tile = 0; tile < 4; tile++) {
            if (AMODE == 1 && tile == 1) continue;   // no A-lo tile
            cp16(base + tile*TILE_B, srcs[tile] + (size_t)rows[tile]*K + goff);
        }
    };

    float acc[2][4][4];
    #pragma unroll
    for (int a = 0; a < 2; a++)
        #pragma unroll
        for (int b = 0; b < 4; b++)
            #pragma unroll
            for (int c = 0; c < 4; c++) acc[a][b][c] = 0.f;

    load_stage(0, kbeg);
    cp_commit();

    for (int it = 0; it < iters; it++) {
        if (it + 1 < iters) load_stage((it + 1) & 1, kbeg + (it + 1) * 32);
        cp_commit();
        cp_wait<1>();
        __syncthreads();

        const uint32_t stb = sb + (it & 1) * STAGE_B;
        #pragma unroll
        for (int kb = 0; kb < 2; kb++) {
            const uint32_t ko = kb * 32;
            uint32_t ah[2][4], al[2][4], bh[4][2], bl[4][2];
            #pragma unroll
            for (int mf = 0; mf < 2; mf++) {
                ldsm4(ah[mf], stb + a_off + mf*(16*80) + ko);
                if (AMODE == 0) ldsm4(al[mf], stb + TILE_B + a_off + mf*(16*80) + ko);
            }
            #pragma unroll
            for (int nf = 0; nf < 4; nf++) {
                ldsm2(bh[nf], stb + 2*TILE_B + b_off + nf*(8*80) + ko);
                ldsm2(bl[nf], stb + 3*TILE_B + b_off + nf*(8*80) + ko);
            }
            // term-major: 8 independent accs between same-acc reuse
            #pragma unroll
            for (int mf = 0; mf < 2; mf++)
                #pragma unroll
                for (int nf = 0; nf < 4; nf++) {
                    if (AMODE == 0) mma_bf16(acc[mf][nf], ah[mf], bh[nf]);
                    else            mma_f16 (acc[mf][nf], ah[mf], bh[nf]);
                }
            #pragma unroll
            for (int mf = 0; mf < 2; mf++)
                #pragma unroll
                for (int nf = 0; nf < 4; nf++) {
                    if (AMODE == 0) mma_bf16(acc[mf][nf], ah[mf], bl[nf]);
                    else            mma_f16 (acc[mf][nf], ah[mf], bl[nf]);
                }
            if (AMODE == 0) {
                #pragma unroll
                for (int mf = 0; mf < 2; mf++)
                    #pragma unroll
                    for (int nf = 0; nf < 4; nf++)
                        mma_bf16(acc[mf][nf], al[mf], bh[nf]);
            }
        }
        __syncthreads();
    }

    #pragma unroll
    for (int mf = 0; mf < 2; mf++) {
        #pragma unroll
        for (int nf = 0; nf < 4; nf++) {
            int row0 = m0 + wm*32 + mf*16 + g;
            int col  = n0 + wn*32 + nf*8 + 2*t;
            float* c = acc[mf][nf];
            if (WMODE >= 1) {
                ushort2 u0, u1, v0, v1;
                split_store<WMODE>(c[0], u0.x, u1.x);
                split_store<WMODE>(c[1], u0.y, u1.y);
                split_store<WMODE>(c[2], v0.x, v1.x);
                split_store<WMODE>(c[3], v0.y, v1.y);
                *(ushort2*)&Ch[(size_t)row0 * N + col]     = u0;
                *(ushort2*)&Cl[(size_t)row0 * N + col]     = u1;
                *(ushort2*)&Ch[(size_t)(row0+8) * N + col] = v0;
                *(ushort2*)&Cl[(size_t)(row0+8) * N + col] = v1;
            } else {
                float* Co = Cf + (size_t)blockIdx.z * M * N;
                *(float2*)&Co[(size_t)row0 * N + col]     = make_float2(c[0], c[1]);
                *(float2*)&Co[(size_t)(row0+8) * N + col] = make_float2(c[2], c[3]);
            }
        }
    }
}

// ================= conversion kernel =================
__global__ void split_k(const float* __restrict__ in, bf16* __restrict__ hi,
                        bf16* __restrict__ lo, int n)
{
    int i = blockIdx.x * 256 + threadIdx.x;
    if (i < n) {
        float v = in[i];
        bf16 h = __float2bfloat16(v);
        hi[i] = h;
        lo[i] = __float2bfloat16(v - __bfloat162float(h));
    }
}

// ================= FFMA GEMMs (titan chain + W'T) =================
template<bool BIAS, bool RELU, bool DPRED>
__launch_bounds__(256)
__global__ void gemm_abT(const float* __restrict__ A, const float* __restrict__ Bm,
                         const float* __restrict__ bias, const float* __restrict__ Vm,
                         float dscale, float* __restrict__ C,
                         int M, int N, int K)
{
    __shared__ float As[16][64];
    __shared__ float Bs[16][64];
    const int t  = threadIdx.x;
    const int tx = t & 15, ty = t >> 4;
    const int m0 = blockIdx.y * 64, n0 = blockIdx.x * 64;
    const int lr = t >> 2;
    const int lc = (t & 3) << 2;
    float acc[4][4] = {};
    const float* Ag = A  + (size_t)(m0 + lr) * K + lc;
    const float* Bg = Bm + (size_t)(n0 + lr) * K + lc;
    for (int k0 = 0; k0 < K; k0 += 16) {
        float4 a4 = *(const float4*)(Ag + k0);
        float4 b4 = *(const float4*)(Bg + k0);
        As[lc+0][lr]=a4.x; As[lc+1][lr]=a4.y; As[lc+2][lr]=a4.z; As[lc+3][lr]=a4.w;
        Bs[lc+0][lr]=b4.x; Bs[lc+1][lr]=b4.y; Bs[lc+2][lr]=b4.z; Bs[lc+3][lr]=b4.w;
        __syncthreads();
        #pragma unroll
        for (int kk = 0; kk < 16; kk++) {
            float4 av = *(const float4*)&As[kk][ty<<2];
            float4 bv = *(const float4*)&Bs[kk][tx<<2];
            acc[0][0]+=av.x*bv.x; acc[0][1]+=av.x*bv.y; acc[0][2]+=av.x*bv.z; acc[0][3]+=av.x*bv.w;
            acc[1][0]+=av.y*bv.x; acc[1][1]+=av.y*bv.y; acc[1][2]+=av.y*bv.z; acc[1][3]+=av.y*bv.w;
            acc[2][0]+=av.z*bv.x; acc[2][1]+=av.z*bv.y; acc[2][2]+=av.z*bv.z; acc[2][3]+=av.z*bv.w;
            acc[3][0]+=av.w*bv.x; acc[3][1]+=av.w*bv.y; acc[3][2]+=av.w*bv.z; acc[3][3]+=av.w*bv.w;
        }
        __syncthreads();
    }
    #pragma unroll
    for (int u = 0; u < 4; u++) {
        const int m = m0 + (ty<<2) + u;
        float4 o;
        float* oc = (float*)&o;
        #pragma unroll
        for (int v = 0; v < 4; v++) {
            const int n = n0 + (tx<<2) + v;
            float val = acc[u][v];
            if (BIAS) val += bias[n];
            if (RELU) val = fmaxf(val, 0.f);
            if (DPRED) val = (val - Vm[(size_t)m * N + n]) * dscale;
            oc[v] = val;
        }
        *(float4*)&C[(size_t)m * N + n0 + (tx<<2)] = o;
    }
}

template<bool MASK>
__launch_bounds__(256)
__global__ void gemm_ab(const float* __restrict__ A, const float* __restrict__ Bm,
                        const float* __restrict__ mask, float* __restrict__ C,
                        int M, int N, int K, int Kchunk)
{
    __shared__ float As[16][64];
    __shared__ float Bs[16][64];
    const int t  = threadIdx.x;
    const int tx = t & 15, ty = t >> 4;
    const int m0 = blockIdx.y * 64, n0 = blockIdx.x * 64;
    const int kbeg = blockIdx.z * Kchunk, kend = kbeg + Kchunk;
    const int lrA = t >> 2,  lcA = (t & 3)  << 2;
    const int lrB = t >> 4,  lcB = (t & 15) << 2;
    float acc[4][4] = {};
    for (int k0 = kbeg; k0 < kend; k0 += 16) {
        float4 a4 = *(const float4*)&A [(size_t)(m0 + lrA) * K + k0 + lcA];
        float4 b4 = *(const float4*)&Bm[(size_t)(k0 + lrB) * N + n0 + lcB];
        As[lcA+0][lrA]=a4.x; As[lcA+1][lrA]=a4.y; As[lcA+2][lrA]=a4.z; As[lcA+3][lrA]=a4.w;
        *(float4*)&Bs[lrB][lcB] = b4;
        __syncthreads();
        #pragma unroll
        for (int kk = 0; kk < 16; kk++) {
            float4 av = *(const float4*)&As[kk][ty<<2];
            float4 bv = *(const float4*)&Bs[kk][tx<<2];
            acc[0][0]+=av.x*bv.x; acc[0][1]+=av.x*bv.y; acc[0][2]+=av.x*bv.z; acc[0][3]+=av.x*bv.w;
            acc[1][0]+=av.y*bv.x; acc[1][1]+=av.y*bv.y; acc[1][2]+=av.y*bv.z; acc[1][3]+=av.y*bv.w;
            acc[2][0]+=av.z*bv.x; acc[2][1]+=av.z*bv.y; acc[2][2]+=av.z*bv.z; acc[2][3]+=av.z*bv.w;
            acc[3][0]+=av.w*bv.x; acc[3][1]+=av.w*bv.y; acc[3][2]+=av.w*bv.z; acc[3][3]+=av.w*bv.w;
        }
        __syncthreads();
    }
    float* Co = C + (size_t)blockIdx.z * M * N;
    #pragma unroll
    for (int u = 0; u < 4; u++) {
        const int m = m0 + (ty<<2) + u;
        float4 o;
        float* oc = (float*)&o;
        #pragma unroll
        for (int v = 0; v < 4; v++) {
            float val = acc[u][v];
            if (MASK) val = (mask[(size_t)m * N + n0 + (tx<<2) + v] > 0.f) ? val : 0.f;
            oc[v] = val;
        }
        *(float4*)&Co[(size_t)m * N + n0 + (tx<<2)] = o;
    }
}

__launch_bounds__(256)
__global__ void gemm_aTb(const float* __restrict__ A, const float* __restrict__ Bm,
                         float* __restrict__ Cpart, int L, int M, int N, int Lchunk)
{
    __shared__ float As[16][64];
    __shared__ float Bs[16][64];
    const int t  = threadIdx.x;
    const int tx = t & 15, ty = t >> 4;
    const int m0 = blockIdx.y * 64, n0 = blockIdx.x * 64;
    const int l0b = blockIdx.z * Lchunk;
    const int lr = t >> 4, lc4 = (t & 15) << 2;
    float acc[4][4] = {};
    for (int l0 = l0b; l0 < l0b + Lchunk; l0 += 16) {
        *(float4*)&As[lr][lc4] = *(const float4*)&A [(size_t)(l0 + lr) * M + m0 + lc4];
        *(float4*)&Bs[lr][lc4] = *(const float4*)&Bm[(size_t)(l0 + lr) * N + n0 + lc4];
        __syncthreads();
        #pragma unroll
        for (int kk = 0; kk < 16; kk++) {
            float4 av = *(const float4*)&As[kk][ty<<2];
            float4 bv = *(const float4*)&Bs[kk][tx<<2];
            acc[0][0]+=av.x*bv.x; acc[0][1]+=av.x*bv.y; acc[0][2]+=av.x*bv.z; acc[0][3]+=av.x*bv.w;
            acc[1][0]+=av.y*bv.x; acc[1][1]+=av.y*bv.y; acc[1][2]+=av.y*bv.z; acc[1][3]+=av.y*bv.w;
            acc[2][0]+=av.z*bv.x; acc[2][1]+=av.z*bv.y; acc[2][2]+=av.z*bv.z; acc[2][3]+=av.z*bv.w;
            acc[3][0]+=av.w*bv.x; acc[3][1]+=av.w*bv.y; acc[3][2]+=av.w*bv.z; acc[3][3]+=av.w*bv.w;
        }
        __syncthreads();
    }
    float* Co = Cpart + (size_t)blockIdx.z * M * N;
    #pragma unroll
    for (int u = 0; u < 4; u++) {
        float4 o;
        float* oc = (float*)&o;
        #pragma unroll
        for (int v = 0; v < 4; v++) oc[v] = acc[u][v];
        *(float4*)&Co[(size_t)(m0 + (ty<<2) + u) * N + n0 + (tx<<2)] = o;
    }
}

// ================= small kernels =================
__global__ void combine_k(const float* __restrict__ parts, float* __restrict__ out,
                          int len, int np)
{
    int i = blockIdx.x * 256 + threadIdx.x;
    if (i < len) {
        float s = 0.f;
        for (int p = 0; p < np; p++) s += parts[(size_t)p * len + i];
        out[i] = s;
    }
}

__global__ void colsum_k(const float* __restrict__ A, float* __restrict__ out, int rows, int N)
{
    int c = threadIdx.x;
    float s = 0.f;
    for (int r = 0; r < rows; r++) s += A[(size_t)r * N + c];
    out[c] = s;
}

__global__ void surprise_k()
{
    __shared__ float red[256];
    int t = threadIdx.x;
    float s = 0.f;
    for (int i = t; i < NHD*NKD; i += 256) { float g = g_gW1[i]; s += g*g; }
    for (int i = t; i < NHD;     i += 256) { float g = g_gb1[i]; s += g*g; }
    for (int i = t; i < NVD*NHD; i += 256) { float g = g_gW2[i]; s += g*g; }
    for (int i = t; i < NVD;     i += 256) { float g = g_gb2[i]; s += g*g; }
    red[t] = s; __syncthreads();
    for (int st = 128; st > 0; st >>= 1) { if (t < st) red[t] += red[t+st]; __syncthreads(); }
    if (t == 0) {
        float avg = sqrtf(red[0] * 0.25f);
        g_theta[0] = 0.1f / (1.f + expf(-avg));
    }
}

__global__ void update_k(const float* __restrict__ mW1, const float* __restrict__ mb1,
                         const float* __restrict__ mW2, const float* __restrict__ mb2,
                         const float* __restrict__ bW1, const float* __restrict__ bb1,
                         const float* __restrict__ bW2, const float* __restrict__ bb2)
{
    int i = blockIdx.x * 256 + threadIdx.x;
    float et = g_theta[0];
    const int n1 = NHD*NKD, n2 = n1 + NHD, n3 = n2 + NVD*NHD, n4 = n3 + NVD;
    if (i < n1)       g_nW1[i]   = 0.9f*mW1[i]   + 0.9f*bW1[i]   - et*g_gW1[i];
    else if (i < n2) { int j=i-n1; g_nb1[j] = 0.9f*mb1[j] + 0.9f*bb1[j] - et*g_gb1[j]; }
    else if (i < n3) { int j=i-n2; g_nW2[j] = 0.9f*mW2[j] + 0.9f*bW2[j] - et*g_gW2[j]; }
    else if (i < n4) { int j=i-n3; g_nb2[j] = 0.9f*mb2[j] + 0.9f*bb2[j] - et*g_gb2[j]; }
}

// softmax over rows of g_S; emits P fp16 (unsplit)
__launch_bounds__(256)
__global__ void softmax_k()
{
    const float* row = g_S + (size_t)blockIdx.x * NH;
    fp16* op = g_attnP + (size_t)blockIdx.x * NH;
    const int t = threadIdx.x;
    float v[64];
    float m = -1e30f;
    #pragma unroll
    for (int j = 0; j < 64; j++) { v[j] = row[t + 256*j]; m = fmaxf(m, v[j]); }
    __shared__ float red[256];
    red[t] = m; __syncthreads();
    #pragma unroll
    for (int s = 128; s > 0; s >>= 1) { if (t < s) red[t] = fmaxf(red[t], red[t+s]); __syncthreads(); }
    m = red[0]; __syncthreads();
    float l = 0.f;
    #pragma unroll
    for (int j = 0; j < 64; j++) { v[j] = __expf(v[j] - m); l += v[j]; }
    red[t] = l; __syncthreads();
    #pragma unroll
    for (int s = 128; s > 0; s >>= 1) { if (t < s) red[t] += red[t+s]; __syncthreads(); }
    float inv = 1.f / red[0];
    #pragma unroll
    for (int j = 0; j < 64; j++)
        op[t + 256*j] = __float2half(v[j] * inv);
}

__global__ void entity_k(const float* __restrict__ ent, const float* __restrict__ Wep,
                         const float* __restrict__ bep, const float* __restrict__ Weg,
                         const float* __restrict__ beg)
{
    __shared__ float eavg[DIN];
    __shared__ float ectx[NVD];
    int t = threadIdx.x;
    float s = 0.f;
    for (int e = 0; e < NE; e++) s += ent[e*DIN + t];
    eavg[t] = s * (1.f / NE);
    __syncthreads();
    if (t < NVD) {
        float c = bep[t];
        for (int d = 0; d < DIN; d++) c += eavg[d] * Wep[t*DIN + d];
        ectx[t] = c; g_ectx[t] = c;
    }
    __syncthreads();
    if (t == 0) {
        float g = beg[0];
        for (int j = 0; j < NVD; j++) g += ectx[j] * Weg[j];
        g_eg[0] = 1.f / (1.f + expf(-g));
    }
}

__global__ void fuse_k(const float* __restrict__ kvec, const float* __restrict__ Wg,
                       const float* __restrict__ bg, const float* __restrict__ bst,
                       float* __restrict__ out)
{
    int b = blockIdx.x, i = threadIdx.x;
    float p = g_ctx[b*NVD + i] + kvec[i];
    float s = p * Wg[i];
    #pragma unroll
    for (int o = 16; o > 0; o >>= 1) s += __shfl_down_sync(0xffffffffu, s, o);
    __shared__ float wsum[4];
    __shared__ float gsh;
    if ((i & 31) == 0) wsum[i >> 5] = s;
    __syncthreads();
    if (i == 0) {
        float tot = wsum[0] + wsum[1] + wsum[2] + wsum[3] + bg[0];
        gsh = 1.f / (1.f + expf(-tot));
    }
    __syncthreads();
    float gate = gsh;
    float st = g_st[b*NVD + i] + bst[i];
    float f = gate * p + (1.f - gate) * st;
    float eg = g_eg[0];
    out[b*NVD + i] = eg * g_ectx[i] + (1.f - eg) * f;
}

// ================= host =================
extern "C" void kernel_launch(void* const* d_in, const int* in_sizes, int n_in,
                              void* d_out, int out_size)
{
    const float* x     = (const float*)d_in[0];
    const float* hist  = (const float*)d_in[1];
    const float* ent   = (const float*)d_in[2];
    const float* W_K   = (const float*)d_in[3];
    const float* W_V   = (const float*)d_in[4];
    const float* mW1   = (const float*)d_in[5];
    const float* mb1   = (const float*)d_in[6];
    const float* mW2   = (const float*)d_in[7];
    const float* mb2   = (const float*)d_in[8];
    const float* bufW1 = (const float*)d_in[9];
    const float* bufb1 = (const float*)d_in[10];
    const float* bufW2 = (const float*)d_in[11];
    const float* bufb2 = (const float*)d_in[12];
    const float* kvec  = (const float*)d_in[13];
    const float* Wq    = (const float*)d_in[14];
    const float* Wk    = (const float*)d_in[15];
    const float* Wst   = (const float*)d_in[16];
    const float* bst   = (const float*)d_in[17];
    const float* Wg    = (const float*)d_in[18];
    const float* bg    = (const float*)d_in[19];
    const float* Wep   = (const float*)d_in[24];
    const float* bep   = (const float*)d_in[25];
    const float* Weg   = (const float*)d_in[26];
    const float* beg   = (const float*)d_in[27];
    float* out = (float*)d_out;

    static bool init_done = false;
    static cudaStream_t s2, s3;
    static cudaEvent_t ev_fork, ev_join, ev_prep, ev_q, ev_hwt;
    if (!init_done) {
        cudaFuncSetAttribute((const void*)hmma_gemm<0,0>, cudaFuncAttributeMaxDynamicSharedMemorySize, HM_SMEM);
        cudaFuncSetAttribute((const void*)hmma_gemm<1,0>, cudaFuncAttributeMaxDynamicSharedMemorySize, HM_SMEM);
        cudaFuncSetAttribute((const void*)hmma_gemm<2,0>, cudaFuncAttributeMaxDynamicSharedMemorySize, HM_SMEM);
        cudaFuncSetAttribute((const void*)hmma_gemm<0,1>, cudaFuncAttributeMaxDynamicSharedMemorySize, HM_SMEM);
        cudaStreamCreateWithFlags(&s2, cudaStreamNonBlocking);
        cudaStreamCreateWithFlags(&s3, cudaStreamNonBlocking);
        cudaEventCreateWithFlags(&ev_fork, cudaEventDisableTiming);
        cudaEventCreateWithFlags(&ev_join, cudaEventDisableTiming);
        cudaEventCreateWithFlags(&ev_prep, cudaEventDisableTiming);
        cudaEventCreateWithFlags(&ev_q,    cudaEventDisableTiming);
        cudaEventCreateWithFlags(&ev_hwt,  cudaEventDisableTiming);
        init_done = true;
    }

    float *pk,*pv,*ph,*pdp,*pdh,*pgW1p,*pgW2p,*pgW1,*pgb1,*pgW2,*pgb2;
    float *pnW1,*pnb1,*pnW2,*pnb2,*ph2,*pctx,*pS,*paop,*pst,*pWT;
    bf16 *pxh,*pxl,*pWTh,*pWTl,*pWsth,*pWstl,*phh,*phl,*pqh,*pql;
    fp16 *phwTh,*phwTl,*pP;
    cudaGetSymbolAddress((void**)&pk,   g_k);
    cudaGetSymbolAddress((void**)&pv,   g_v);
    cudaGetSymbolAddress((void**)&ph,   g_h);
    cudaGetSymbolAddress((void**)&pdp,  g_dpred);
    cudaGetSymbolAddress((void**)&pdh,  g_dh);
    cudaGetSymbolAddress((void**)&pgW1p,g_gW1p);
    cudaGetSymbolAddress((void**)&pgW2p,g_gW2p);
    cudaGetSymbolAddress((void**)&pgW1, g_gW1);
    cudaGetSymbolAddress((void**)&pgb1, g_gb1);
    cudaGetSymbolAddress((void**)&pgW2, g_gW2);
    cudaGetSymbolAddress((void**)&pgb2, g_gb2);
    cudaGetSymbolAddress((void**)&pnW1, g_nW1);
    cudaGetSymbolAddress((void**)&pnb1, g_nb1);
    cudaGetSymbolAddress((void**)&pnW2, g_nW2);
    cudaGetSymbolAddress((void**)&pnb2, g_nb2);
    cudaGetSymbolAddress((void**)&ph2,  g_h2);
    cudaGetSymbolAddress((void**)&pctx, g_ctx);
    cudaGetSymbolAddress((void**)&pS,   g_S);
    cudaGetSymbolAddress((void**)&paop, g_aop);
    cudaGetSymbolAddress((void**)&pst,  g_st);
    cudaGetSymbolAddress((void**)&pWT,  g_WT);
    cudaGetSymbolAddress((void**)&pxh,  g_xh);
    cudaGetSymbolAddress((void**)&pxl,  g_xl);
    cudaGetSymbolAddress((void**)&pWTh, g_WTh);
    cudaGetSymbolAddress((void**)&pWTl, g_WTl);
    cudaGetSymbolAddress((void**)&pWsth,g_Wsth);
    cudaGetSymbolAddress((void**)&pWstl,g_Wstl);
    cudaGetSymbolAddress((void**)&phh,  g_histh);
    cudaGetSymbolAddress((void**)&phl,  g_histl);
    cudaGetSymbolAddress((void**)&phwTh,g_hwTh);
    cudaGetSymbolAddress((void**)&phwTl,g_hwTl);
    cudaGetSymbolAddress((void**)&pqh,  g_qh);
    cudaGetSymbolAddress((void**)&pql,  g_ql);
    cudaGetSymbolAddress((void**)&pP,   g_attnP);

    // fork streams
    cudaEventRecord(ev_fork, 0);
    cudaStreamWaitEvent(s2, ev_fork, 0);
    cudaStreamWaitEvent(s3, ev_fork, 0);

    // ===== stream s2: Titan memory chain + entity path (fp32 FFMA) =====
    gemm_abT<false,false,false><<<dim3(NKD/64, NB/64), 256, 0, s2>>>(
        x, W_K, nullptr, nullptr, 0.f, pk, NB, NKD, DIN);
    gemm_abT<false,false,false><<<dim3(NVD/64, NB/64), 256, 0, s2>>>(
        x, W_V, nullptr, nullptr, 0.f, pv, NB, NVD, DIN);
    gemm_abT<true,true,false><<<dim3(NHD/64, NB/64), 256, 0, s2>>>(
        pk, mW1, mb1, nullptr, 0.f, ph, NB, NHD, NKD);
    gemm_abT<true,false,true><<<dim3(NVD/64, NB/64), 256, 0, s2>>>(
        ph, mW2, mb2, pv, 2.f / (float)(NB*NVD), pdp, NB, NVD, NHD);
    gemm_aTb<<<dim3(NHD/64, NVD/64, NSPLIT_G), 256, 0, s2>>>(pdp, ph, pgW2p, NB, NVD, NHD, NB/NSPLIT_G);
    combine_k<<<(NVD*NHD + 255)/256, 256, 0, s2>>>(pgW2p, pgW2, NVD*NHD, NSPLIT_G);
    colsum_k<<<1, NVD, 0, s2>>>(pdp, pgb2, NB, NVD);
    gemm_ab<true><<<dim3(NHD/64, NB/64, 1), 256, 0, s2>>>(pdp, mW2, ph, pdh, NB, NHD, NVD, NVD);
    colsum_k<<<1, NHD, 0, s2>>>(pdh, pgb1, NB, NHD);
    gemm_aTb<<<dim3(NKD/64, NHD/64, NSPLIT_G), 256, 0, s2>>>(pdh, pk, pgW1p, NB, NHD, NKD, NB/NSPLIT_G);
    combine_k<<<(NHD*NKD + 255)/256, 256, 0, s2>>>(pgW1p, pgW1, NHD*NKD, NSPLIT_G);
    surprise_k<<<1, 256, 0, s2>>>();
    update_k<<<(NHD*NKD + NHD + NVD*NHD + NVD + 255)/256, 256, 0, s2>>>(
        mW1, mb1, mW2, mb2, bufW1, bufb1, bufW2, bufb2);
    gemm_abT<true,true,false><<<dim3(NHD/64, NB/64), 256, 0, s2>>>(
        pk, pnW1, pnb1, nullptr, 0.f, ph2, NB, NHD, NKD);
    gemm_abT<true,false,false><<<dim3(NVD/64, NB/64), 256, 0, s2>>>(
        ph2, pnW2, pnb2, nullptr, 0.f, pctx, NB, NVD, NHD);
    entity_k<<<1, DIN, 0, s2>>>(ent, Wep, bep, Weg, beg);
    cudaEventRecord(ev_join, s2);

    // ===== stream0: splits (x, Wst, hist) =====
    split_k<<<(NB*DIN + 255)/256, 256>>>(x,    pxh,  pxl,  NB*DIN);
    split_k<<<(NVD*DIN + 255)/256, 256>>>(Wst, pWsth,pWstl,NVD*DIN);
    split_k<<<(NH*DIN + 255)/256, 256>>>(hist, phh,  phl,  NH*DIN);
    cudaEventRecord(ev_prep, 0);

    // ===== stream s3: W' gemm + split, q', hwT (overlap with S) =====
    gemm_aTb<<<dim3(DIN/64, DIN/64, 1), 256, 0, s3>>>(Wk, Wq, pWT, DIN, DIN, DIN, DIN);
    split_k<<<(DIN*DIN + 255)/256, 256, 0, s3>>>(pWT, pWTh, pWTl, DIN*DIN);
    cudaStreamWaitEvent(s3, ev_prep, 0);
    // q' = x @ W'  -> split bf16
    hmma_gemm<1,0><<<dim3(DIN/128, NB/128, 1), 512, HM_SMEM, s3>>>(
        pxh, pxl, pWTh, pWTl, nullptr, (unsigned short*)pqh, (unsigned short*)pql, NB, DIN, DIN, DIN);
    cudaEventRecord(ev_q, s3);
    // hwT = Wst @ hist^T -> fp16 split, [NVD, NH]
    hmma_gemm<2,0><<<dim3(NH/128, NVD/128, 1), 512, HM_SMEM, s3>>>(
        pWsth, pWstl, phh, phl, nullptr, (unsigned short*)phwTh, (unsigned short*)phwTl, NVD, NH, DIN, DIN);
    cudaEventRecord(ev_hwt, s3);

    // ===== stream0: S = q' @ hist^T (bf16 3-term) =====
    cudaStreamWaitEvent(0, ev_q, 0);
    hmma_gemm<0,0><<<dim3(NH/128, NB/128, 1), 512, HM_SMEM>>>(
        pqh, pql, phh, phl, pS, nullptr, nullptr, NB, NH, DIN, DIN);
    softmax_k<<<NB, 256>>>();
    // st(raw) = P @ hwT^T (fp16 2-term, A unsplit), split-K slabs + combine
    cudaStreamWaitEvent(0, ev_hwt, 0);
    hmma_gemm<0,1><<<dim3(NVD/128, NB/128, NSPLIT_AH), 512, HM_SMEM>>>(
        (const bf16*)pP, (const bf16*)pP, (const bf16*)phwTh, (const bf16*)phwTl,
        paop, nullptr, nullptr, NB, NVD, NH, NH/NSPLIT_AH);
    combine_k<<<(NB*NVD + 255)/256, 256>>>(paop, pst, NB*NVD, NSPLIT_AH);

    // join + fuse
    cudaStreamWaitEvent(0, ev_join, 0);
    fuse_k<<<NB, NVD>>>(kvec, Wg, bg, bst, out);
}

// round 8
// speedup vs baseline: 3.1396x; 1.0121x over previous
#include <cuda_runtime.h>
#include <cuda_bf16.h>
#include <cuda_fp16.h>
#include <math.h>
#include <stdint.h>

// Problem dims
#define NB   2048
#define NH   16384
#define NE   64
#define DIN  384
#define NKD  128
#define NVD  128
#define NHD  256
#define NSPLIT_G 8
#define NSPLIT_AH 16

typedef __nv_bfloat16 bf16;
typedef __half fp16;

// ---------------- scratch (device globals) ----------------
__device__ float g_k[NB*NKD];
__device__ float g_v[NB*NVD];
__device__ float g_h[NB*NHD];
__device__ float g_dpred[NB*NVD];
__device__ float g_dh[NB*NHD];
__device__ float g_gW1p[NSPLIT_G*NHD*NKD];
__device__ float g_gW2p[NSPLIT_G*NVD*NHD];
__device__ float g_gW1[NHD*NKD];
__device__ float g_gb1[NHD];
__device__ float g_gW2[NVD*NHD];
__device__ float g_gb2[NVD];
__device__ float g_nW1[NHD*NKD];
__device__ float g_nb1[NHD];
__device__ float g_nW2[NVD*NHD];
__device__ float g_nb2[NVD];
__device__ float g_h2[NB*NHD];
__device__ float g_ctx[NB*NVD];
__device__ float g_S[33554432];            // 2048*16384 fp32
__device__ float g_aop[NSPLIT_AH*NB*NVD];
__device__ float g_st[NB*NVD];
__device__ float g_WT[DIN*DIN];            // W'^T = Wk^T @ Wq (fp32)
__device__ float g_theta[1];
__device__ float g_ectx[NVD];
__device__ float g_eg[1];
// split operands
__device__ bf16 g_xh[NB*DIN],   g_xl[NB*DIN];
__device__ bf16 g_WTh[DIN*DIN], g_WTl[DIN*DIN];
__device__ bf16 g_Wsth[NVD*DIN], g_Wstl[NVD*DIN];
__device__ bf16 g_histh[NH*DIN], g_histl[NH*DIN];
__device__ fp16 g_hwTh[(size_t)NVD*NH], g_hwTl[(size_t)NVD*NH];  // (Wst @ hist^T) fp16 split
__device__ bf16 g_qh[NB*DIN],   g_ql[NB*DIN];                    // q' = x @ W'
__device__ fp16 g_attnP[(size_t)NB*NH];                          // P fp16 (unsplit)

// ================= HMMA (mma.sync) GEMM =================
// AMODE 0: C = Ah@Bh^T + Ah@Bl^T + Al@Bh^T (bf16 3-term)
// AMODE 1: C = A@Bh^T + A@Bl^T            (fp16 2-term, A unsplit)
// WMODE 0: fp32 -> Cf + z*M*N; 1: bf16 hi/lo; 2: fp16 hi/lo
// CTA tile 128x128xK32, 512 threads (16 warps: 4m x 4n, warp tile 32x32),
// 3-stage cp.async, ONE __syncthreads per iter, ldmatrix, 80B padded rows,
// term-major MMA order (8 independent accumulators between same-acc reuse).

#define TILE_B   10240
#define STAGE_B  (4*TILE_B)
#define NSTAGE   3
#define HM_SMEM  (NSTAGE*STAGE_B)   // 122880

__device__ __forceinline__ uint32_t smem_u32(const void* p) {
    uint32_t a;
    asm("{ .reg .u64 t; cvta.to.shared.u64 t, %1; cvt.u32.u64 %0, t; }" : "=r"(a) : "l"(p));
    return a;
}
__device__ __forceinline__ void cp16(uint32_t s, const void* g) {
    asm volatile("cp.async.cg.shared.global [%0], [%1], 16;" :: "r"(s), "l"(g));
}
__device__ __forceinline__ void cp_commit() {
    asm volatile("cp.async.commit_group;" ::: "memory");
}
template<int N>
__device__ __forceinline__ void cp_wait() {
    asm volatile("cp.async.wait_group %0;" :: "n"(N) : "memory");
}
__device__ __forceinline__ void ldsm4(uint32_t* r, uint32_t addr) {
    asm volatile("ldmatrix.sync.aligned.m8n8.x4.shared.b16 {%0,%1,%2,%3}, [%4];"
                 : "=r"(r[0]), "=r"(r[1]), "=r"(r[2]), "=r"(r[3]) : "r"(addr));
}
__device__ __forceinline__ void ldsm2(uint32_t* r, uint32_t addr) {
    asm volatile("ldmatrix.sync.aligned.m8n8.x2.shared.b16 {%0,%1}, [%2];"
                 : "=r"(r[0]), "=r"(r[1]) : "r"(addr));
}
__device__ __forceinline__ void mma_bf16(float* c, const uint32_t* a, const uint32_t* b) {
    asm volatile(
        "mma.sync.aligned.m16n8k16.row.col.f32.bf16.bf16.f32 "
        "{%0,%1,%2,%3}, {%4,%5,%6,%7}, {%8,%9}, {%0,%1,%2,%3};"
        : "+f"(c[0]), "+f"(c[1]), "+f"(c[2]), "+f"(c[3])
        : "r"(a[0]), "r"(a[1]), "r"(a[2]), "r"(a[3]), "r"(b[0]), "r"(b[1]));
}
__device__ __forceinline__ void mma_f16(float* c, const uint32_t* a, const uint32_t* b) {
    asm volatile(
        "mma.sync.aligned.m16n8k16.row.col.f32.f16.f16.f32 "
        "{%0,%1,%2,%3}, {%4,%5,%6,%7}, {%8,%9}, {%0,%1,%2,%3};"
        : "+f"(c[0]), "+f"(c[1]), "+f"(c[2]), "+f"(c[3])
        : "r"(a[0]), "r"(a[1]), "r"(a[2]), "r"(a[3]), "r"(b[0]), "r"(b[1]));
}

template<int WMODE>
__device__ __forceinline__ void split_store(float v, unsigned short& h, unsigned short& l) {
    if (WMODE == 2) {
        fp16 hh = __float2half(v);
        fp16 ll = __float2half(v - __half2float(hh));
        h = *(unsigned short*)&hh; l = *(unsigned short*)&ll;
    } else {
        bf16 hh = __float2bfloat16(v);
        bf16 ll = __float2bfloat16(v - __bfloat162float(hh));
        h = *(unsigned short*)&hh; l = *(unsigned short*)&ll;
    }
}

template<int WMODE, int AMODE>
__global__ void __launch_bounds__(512, 1) hmma_gemm(
    const bf16* __restrict__ Ah, const bf16* __restrict__ Al,
    const bf16* __restrict__ Bh, const bf16* __restrict__ Bl,
    float* __restrict__ Cf, unsigned short* __restrict__ Ch, unsigned short* __restrict__ Cl,
    int M, int N, int K, int Kchunk)
{
    extern __shared__ char smem[];
    const int tid = threadIdx.x, wid = tid >> 5, lid = tid & 31;
    const int wm = wid >> 2, wn = wid & 3;
    const int g = lid >> 2, t = lid & 3;
    const int n0 = blockIdx.x * 128, m0 = blockIdx.y * 128;
    const int kbeg = blockIdx.z * Kchunk;
    const int iters = Kchunk / 32;

    const uint32_t sb = smem_u32(smem);
    const bf16* srcs[4] = { Ah, Al, Bh, Bl };
    const int   rows[4] = { m0, m0, n0, n0 };

    const uint32_t a_off = (uint32_t)((wm*32 + (lid & 15)) * 80 + (lid >> 4) * 16);
    const uint32_t b_off = (uint32_t)((wn*32 + (lid & 7))  * 80 + ((lid >> 3) & 1) * 16);

    const int l_row = tid >> 2, l_ch = tid & 3;

    auto load_stage = [&](int stage, int k0) {
        uint32_t base = sb + stage * STAGE_B + l_row*80 + l_ch*16;
        size_t goff = (size_t)l_row * K + k0 + l_ch*8;
        #pragma unroll
        for (int tile = 0; tile < 4; tile++) {
            if (AMODE == 1 && tile == 1) continue;   // no A-lo tile
            cp16(base + tile*TILE_B, srcs[tile] + (size_t)rows[tile]*K + goff);
        }
    };

    float acc[2][4][4];
    #pragma unroll
    for (int a = 0; a < 2; a++)
        #pragma unroll
        for (int b = 0; b < 4; b++)
            #pragma unroll
            for (int c = 0; c < 4; c++) acc[a][b][c] = 0.f;

    // prologue: fill stages 0,1
    load_stage(0, kbeg);
    cp_commit();
    if (iters > 1) load_stage(1, kbeg + 32);
    cp_commit();

    for (int it = 0; it < iters; it++) {
        cp_wait<1>();
        __syncthreads();                       // the ONLY barrier per iter
        // prefetch stage it+2 (target buffer was read at iter it-1; safe after sync)
        if (it + 2 < iters) load_stage((it + 2) % NSTAGE, kbeg + (it + 2) * 32);
        cp_commit();                           // always commit: keeps group count aligned

        const uint32_t stb = sb + (it % NSTAGE) * STAGE_B;
        #pragma unroll
        for (int kb = 0; kb < 2; kb++) {
            const uint32_t ko = kb * 32;
            uint32_t ah[2][4], al[2][4], bh[4][2], bl[4][2];
            #pragma unroll
            for (int mf = 0; mf < 2; mf++) {
                ldsm4(ah[mf], stb + a_off + mf*(16*80) + ko);
                if (AMODE == 0) ldsm4(al[mf], stb + TILE_B + a_off + mf*(16*80) + ko);
            }
            #pragma unroll
            for (int nf = 0; nf < 4; nf++) {
                ldsm2(bh[nf], stb + 2*TILE_B + b_off + nf*(8*80) + ko);
                ldsm2(bl[nf], stb + 3*TILE_B + b_off + nf*(8*80) + ko);
            }
            #pragma unroll
            for (int mf = 0; mf < 2; mf++)
                #pragma unroll
                for (int nf = 0; nf < 4; nf++) {
                    if (AMODE == 0) mma_bf16(acc[mf][nf], ah[mf], bh[nf]);
                    else            mma_f16 (acc[mf][nf], ah[mf], bh[nf]);
                }
            #pragma unroll
            for (int mf = 0; mf < 2; mf++)
                #pragma unroll
                for (int nf = 0; nf < 4; nf++) {
                    if (AMODE == 0) mma_bf16(acc[mf][nf], ah[mf], bl[nf]);
                    else            mma_f16 (acc[mf][nf], ah[mf], bl[nf]);
                }
            if (AMODE == 0) {
                #pragma unroll
                for (int mf = 0; mf < 2; mf++)
                    #pragma unroll
                    for (int nf = 0; nf < 4; nf++)
                        mma_bf16(acc[mf][nf], al[mf], bh[nf]);
            }
        }
    }

    #pragma unroll
    for (int mf = 0; mf < 2; mf++) {
        #pragma unroll
        for (int nf = 0; nf < 4; nf++) {
            int row0 = m0 + wm*32 + mf*16 + g;
            int col  = n0 + wn*32 + nf*8 + 2*t;
            float* c = acc[mf][nf];
            if (WMODE >= 1) {
                ushort2 u0, u1, v0, v1;
                split_store<WMODE>(c[0], u0.x, u1.x);
                split_store<WMODE>(c[1], u0.y, u1.y);
                split_store<WMODE>(c[2], v0.x, v1.x);
                split_store<WMODE>(c[3], v0.y, v1.y);
                *(ushort2*)&Ch[(size_t)row0 * N + col]     = u0;
                *(ushort2*)&Cl[(size_t)row0 * N + col]     = u1;
                *(ushort2*)&Ch[(size_t)(row0+8) * N + col] = v0;
                *(ushort2*)&Cl[(size_t)(row0+8) * N + col] = v1;
            } else {
                float* Co = Cf + (size_t)blockIdx.z * M * N;
                *(float2*)&Co[(size_t)row0 * N + col]     = make_float2(c[0], c[1]);
                *(float2*)&Co[(size_t)(row0+8) * N + col] = make_float2(c[2], c[3]);
            }
        }
    }
}

// ================= conversion kernel =================
__global__ void split_k(const float* __restrict__ in, bf16* __restrict__ hi,
                        bf16* __restrict__ lo, int n)
{
    int i = blockIdx.x * 256 + threadIdx.x;
    if (i < n) {
        float v = in[i];
        bf16 h = __float2bfloat16(v);
        hi[i] = h;
        lo[i] = __float2bfloat16(v - __bfloat162float(h));
    }
}

// ================= FFMA GEMMs (titan chain + W'T) =================
template<bool BIAS, bool RELU, bool DPRED>
__launch_bounds__(256)
__global__ void gemm_abT(const float* __restrict__ A, const float* __restrict__ Bm,
                         const float* __restrict__ bias, const float* __restrict__ Vm,
                         float dscale, float* __restrict__ C,
                         int M, int N, int K)
{
    __shared__ float As[16][64];
    __shared__ float Bs[16][64];
    const int t  = threadIdx.x;
    const int tx = t & 15, ty = t >> 4;
    const int m0 = blockIdx.y * 64, n0 = blockIdx.x * 64;
    const int lr = t >> 2;
    const int lc = (t & 3) << 2;
    float acc[4][4] = {};
    const float* Ag = A  + (size_t)(m0 + lr) * K + lc;
    const float* Bg = Bm + (size_t)(n0 + lr) * K + lc;
    for (int k0 = 0; k0 < K; k0 += 16) {
        float4 a4 = *(const float4*)(Ag + k0);
        float4 b4 = *(const float4*)(Bg + k0);
        As[lc+0][lr]=a4.x; As[lc+1][lr]=a4.y; As[lc+2][lr]=a4.z; As[lc+3][lr]=a4.w;
        Bs[lc+0][lr]=b4.x; Bs[lc+1][lr]=b4.y; Bs[lc+2][lr]=b4.z; Bs[lc+3][lr]=b4.w;
        __syncthreads();
        #pragma unroll
        for (int kk = 0; kk < 16; kk++) {
            float4 av = *(const float4*)&As[kk][ty<<2];
            float4 bv = *(const float4*)&Bs[kk][tx<<2];
            acc[0][0]+=av.x*bv.x; acc[0][1]+=av.x*bv.y; acc[0][2]+=av.x*bv.z; acc[0][3]+=av.x*bv.w;
            acc[1][0]+=av.y*bv.x; acc[1][1]+=av.y*bv.y; acc[1][2]+=av.y*bv.z; acc[1][3]+=av.y*bv.w;
            acc[2][0]+=av.z*bv.x; acc[2][1]+=av.z*bv.y; acc[2][2]+=av.z*bv.z; acc[2][3]+=av.z*bv.w;
            acc[3][0]+=av.w*bv.x; acc[3][1]+=av.w*bv.y; acc[3][2]+=av.w*bv.z; acc[3][3]+=av.w*bv.w;
        }
        __syncthreads();
    }
    #pragma unroll
    for (int u = 0; u < 4; u++) {
        const int m = m0 + (ty<<2) + u;
        float4 o;
        float* oc = (float*)&o;
        #pragma unroll
        for (int v = 0; v < 4; v++) {
            const int n = n0 + (tx<<2) + v;
            float val = acc[u][v];
            if (BIAS) val += bias[n];
            if (RELU) val = fmaxf(val, 0.f);
            if (DPRED) val = (val - Vm[(size_t)m * N + n]) * dscale;
            oc[v] = val;
        }
        *(float4*)&C[(size_t)m * N + n0 + (tx<<2)] = o;
    }
}

template<bool MASK>
__launch_bounds__(256)
__global__ void gemm_ab(const float* __restrict__ A, const float* __restrict__ Bm,
                        const float* __restrict__ mask, float* __restrict__ C,
                        int M, int N, int K, int Kchunk)
{
    __shared__ float As[16][64];
    __shared__ float Bs[16][64];
    const int t  = threadIdx.x;
    const int tx = t & 15, ty = t >> 4;
    const int m0 = blockIdx.y * 64, n0 = blockIdx.x * 64;
    const int kbeg = blockIdx.z * Kchunk, kend = kbeg + Kchunk;
    const int lrA = t >> 2,  lcA = (t & 3)  << 2;
    const int lrB = t >> 4,  lcB = (t & 15) << 2;
    float acc[4][4] = {};
    for (int k0 = kbeg; k0 < kend; k0 += 16) {
        float4 a4 = *(const float4*)&A [(size_t)(m0 + lrA) * K + k0 + lcA];
        float4 b4 = *(const float4*)&Bm[(size_t)(k0 + lrB) * N + n0 + lcB];
        As[lcA+0][lrA]=a4.x; As[lcA+1][lrA]=a4.y; As[lcA+2][lrA]=a4.z; As[lcA+3][lrA]=a4.w;
        *(float4*)&Bs[lrB][lcB] = b4;
        __syncthreads();
        #pragma unroll
        for (int kk = 0; kk < 16; kk++) {
            float4 av = *(const float4*)&As[kk][ty<<2];
            float4 bv = *(const float4*)&Bs[kk][tx<<2];
            acc[0][0]+=av.x*bv.x; acc[0][1]+=av.x*bv.y; acc[0][2]+=av.x*bv.z; acc[0][3]+=av.x*bv.w;
            acc[1][0]+=av.y*bv.x; acc[1][1]+=av.y*bv.y; acc[1][2]+=av.y*bv.z; acc[1][3]+=av.y*bv.w;
            acc[2][0]+=av.z*bv.x; acc[2][1]+=av.z*bv.y; acc[2][2]+=av.z*bv.z; acc[2][3]+=av.z*bv.w;
            acc[3][0]+=av.w*bv.x; acc[3][1]+=av.w*bv.y; acc[3][2]+=av.w*bv.z; acc[3][3]+=av.w*bv.w;
        }
        __syncthreads();
    }
    float* Co = C + (size_t)blockIdx.z * M * N;
    #pragma unroll
    for (int u = 0; u < 4; u++) {
        const int m = m0 + (ty<<2) + u;
        float4 o;
        float* oc = (float*)&o;
        #pragma unroll
        for (int v = 0; v < 4; v++) {
            float val = acc[u][v];
            if (MASK) val = (mask[(size_t)m * N + n0 + (tx<<2) + v] > 0.f) ? val : 0.f;
            oc[v] = val;
        }
        *(float4*)&Co[(size_t)m * N + n0 + (tx<<2)] = o;
    }
}

__launch_bounds__(256)
__global__ void gemm_aTb(const float* __restrict__ A, const float* __restrict__ Bm,
                         float* __restrict__ Cpart, int L, int M, int N, int Lchunk)
{
    __shared__ float As[16][64];
    __shared__ float Bs[16][64];
    const int t  = threadIdx.x;
    const int tx = t & 15, ty = t >> 4;
    const int m0 = blockIdx.y * 64, n0 = blockIdx.x * 64;
    const int l0b = blockIdx.z * Lchunk;
    const int lr = t >> 4, lc4 = (t & 15) << 2;
    float acc[4][4] = {};
    for (int l0 = l0b; l0 < l0b + Lchunk; l0 += 16) {
        *(float4*)&As[lr][lc4] = *(const float4*)&A [(size_t)(l0 + lr) * M + m0 + lc4];
        *(float4*)&Bs[lr][lc4] = *(const float4*)&Bm[(size_t)(l0 + lr) * N + n0 + lc4];
        __syncthreads();
        #pragma unroll
        for (int kk = 0; kk < 16; kk++) {
            float4 av = *(const float4*)&As[kk][ty<<2];
            float4 bv = *(const float4*)&Bs[kk][tx<<2];
            acc[0][0]+=av.x*bv.x; acc[0][1]+=av.x*bv.y; acc[0][2]+=av.x*bv.z; acc[0][3]+=av.x*bv.w;
            acc[1][0]+=av.y*bv.x; acc[1][1]+=av.y*bv.y; acc[1][2]+=av.y*bv.z; acc[1][3]+=av.y*bv.w;
            acc[2][0]+=av.z*bv.x; acc[2][1]+=av.z*bv.y; acc[2][2]+=av.z*bv.z; acc[2][3]+=av.z*bv.w;
            acc[3][0]+=av.w*bv.x; acc[3][1]+=av.w*bv.y; acc[3][2]+=av.w*bv.z; acc[3][3]+=av.w*bv.w;
        }
        __syncthreads();
    }
    float* Co = Cpart + (size_t)blockIdx.z * M * N;
    #pragma unroll
    for (int u = 0; u < 4; u++) {
        float4 o;
        float* oc = (float*)&o;
        #pragma unroll
        for (int v = 0; v < 4; v++) oc[v] = acc[u][v];
        *(float4*)&Co[(size_t)(m0 + (ty<<2) + u) * N + n0 + (tx<<2)] = o;
    }
}

// ================= small kernels =================
__global__ void combine_k(const float* __restrict__ parts, float* __restrict__ out,
                          int len, int np)
{
    int i = blockIdx.x * 256 + threadIdx.x;
    if (i < len) {
        float s = 0.f;
        for (int p = 0; p < np; p++) s += parts[(size_t)p * len + i];
        out[i] = s;
    }
}

__global__ void colsum_k(const float* __restrict__ A, float* __restrict__ out, int rows, int N)
{
    int c = threadIdx.x;
    float s = 0.f;
    for (int r = 0; r < rows; r++) s += A[(size_t)r * N + c];
    out[c] = s;
}

__global__ void surprise_k()
{
    __shared__ float red[256];
    int t = threadIdx.x;
    float s = 0.f;
    for (int i = t; i < NHD*NKD; i += 256) { float g = g_gW1[i]; s += g*g; }
    for (int i = t; i < NHD;     i += 256) { float g = g_gb1[i]; s += g*g; }
    for (int i = t; i < NVD*NHD; i += 256) { float g = g_gW2[i]; s += g*g; }
    for (int i = t; i < NVD;     i += 256) { float g = g_gb2[i]; s += g*g; }
    red[t] = s; __syncthreads();
    for (int st = 128; st > 0; st >>= 1) { if (t < st) red[t] += red[t+st]; __syncthreads(); }
    if (t == 0) {
        float avg = sqrtf(red[0] * 0.25f);
        g_theta[0] = 0.1f / (1.f + expf(-avg));
    }
}

__global__ void update_k(const float* __restrict__ mW1, const float* __restrict__ mb1,
                         const float* __restrict__ mW2, const float* __restrict__ mb2,
                         const float* __restrict__ bW1, const float* __restrict__ bb1,
                         const float* __restrict__ bW2, const float* __restrict__ bb2)
{
    int i = blockIdx.x * 256 + threadIdx.x;
    float et = g_theta[0];
    const int n1 = NHD*NKD, n2 = n1 + NHD, n3 = n2 + NVD*NHD, n4 = n3 + NVD;
    if (i < n1)       g_nW1[i]   = 0.9f*mW1[i]   + 0.9f*bW1[i]   - et*g_gW1[i];
    else if (i < n2) { int j=i-n1; g_nb1[j] = 0.9f*mb1[j] + 0.9f*bb1[j] - et*g_gb1[j]; }
    else if (i < n3) { int j=i-n2; g_nW2[j] = 0.9f*mW2[j] + 0.9f*bW2[j] - et*g_gW2[j]; }
    else if (i < n4) { int j=i-n3; g_nb2[j] = 0.9f*mb2[j] + 0.9f*bb2[j] - et*g_gb2[j]; }
}

// softmax over rows of g_S; emits P fp16 (unsplit)
__launch_bounds__(256)
__global__ void softmax_k()
{
    const float* row = g_S + (size_t)blockIdx.x * NH;
    fp16* op = g_attnP + (size_t)blockIdx.x * NH;
    const int t = threadIdx.x;
    float v[64];
    float m = -1e30f;
    #pragma unroll
    for (int j = 0; j < 64; j++) { v[j] = row[t + 256*j]; m = fmaxf(m, v[j]); }
    __shared__ float red[256];
    red[t] = m; __syncthreads();
    #pragma unroll
    for (int s = 128; s > 0; s >>= 1) { if (t < s) red[t] = fmaxf(red[t], red[t+s]); __syncthreads(); }
    m = red[0]; __syncthreads();
    float l = 0.f;
    #pragma unroll
    for (int j = 0; j < 64; j++) { v[j] = __expf(v[j] - m); l += v[j]; }
    red[t] = l; __syncthreads();
    #pragma unroll
    for (int s = 128; s > 0; s >>= 1) { if (t < s) red[t] += red[t+s]; __syncthreads(); }
    float inv = 1.f / red[0];
    #pragma unroll
    for (int j = 0; j < 64; j++)
        op[t + 256*j] = __float2half(v[j] * inv);
}

__global__ void entity_k(const float* __restrict__ ent, const float* __restrict__ Wep,
                         const float* __restrict__ bep, const float* __restrict__ Weg,
                         const float* __restrict__ beg)
{
    __shared__ float eavg[DIN];
    __shared__ float ectx[NVD];
    int t = threadIdx.x;
    float s = 0.f;
    for (int e = 0; e < NE; e++) s += ent[e*DIN + t];
    eavg[t] = s * (1.f / NE);
    __syncthreads();
    if (t < NVD) {
        float c = bep[t];
        for (int d = 0; d < DIN; d++) c += eavg[d] * Wep[t*DIN + d];
        ectx[t] = c; g_ectx[t] = c;
    }
    __syncthreads();
    if (t == 0) {
        float g = beg[0];
        for (int j = 0; j < NVD; j++) g += ectx[j] * Weg[j];
        g_eg[0] = 1.f / (1.f + expf(-g));
    }
}

__global__ void fuse_k(const float* __restrict__ kvec, const float* __restrict__ Wg,
                       const float* __restrict__ bg, const float* __restrict__ bst,
                       float* __restrict__ out)
{
    int b = blockIdx.x, i = threadIdx.x;
    float p = g_ctx[b*NVD + i] + kvec[i];
    float s = p * Wg[i];
    #pragma unroll
    for (int o = 16; o > 0; o >>= 1) s += __shfl_down_sync(0xffffffffu, s, o);
    __shared__ float wsum[4];
    __shared__ float gsh;
    if ((i & 31) == 0) wsum[i >> 5] = s;
    __syncthreads();
    if (i == 0) {
        float tot = wsum[0] + wsum[1] + wsum[2] + wsum[3] + bg[0];
        gsh = 1.f / (1.f + expf(-tot));
    }
    __syncthreads();
    float gate = gsh;
    float st = g_st[b*NVD + i] + bst[i];
    float f = gate * p + (1.f - gate) * st;
    float eg = g_eg[0];
    out[b*NVD + i] = eg * g_ectx[i] + (1.f - eg) * f;
}

// ================= host =================
extern "C" void kernel_launch(void* const* d_in, const int* in_sizes, int n_in,
                              void* d_out, int out_size)
{
    const float* x     = (const float*)d_in[0];
    const float* hist  = (const float*)d_in[1];
    const float* ent   = (const float*)d_in[2];
    const float* W_K   = (const float*)d_in[3];
    const float* W_V   = (const float*)d_in[4];
    const float* mW1   = (const float*)d_in[5];
    const float* mb1   = (const float*)d_in[6];
    const float* mW2   = (const float*)d_in[7];
    const float* mb2   = (const float*)d_in[8];
    const float* bufW1 = (const float*)d_in[9];
    const float* bufb1 = (const float*)d_in[10];
    const float* bufW2 = (const float*)d_in[11];
    const float* bufb2 = (const float*)d_in[12];
    const float* kvec  = (const float*)d_in[13];
    const float* Wq    = (const float*)d_in[14];
    const float* Wk    = (const float*)d_in[15];
    const float* Wst   = (const float*)d_in[16];
    const float* bst   = (const float*)d_in[17];
    const float* Wg    = (const float*)d_in[18];
    const float* bg    = (const float*)d_in[19];
    const float* Wep   = (const float*)d_in[24];
    const float* bep   = (const float*)d_in[25];
    const float* Weg   = (const float*)d_in[26];
    const float* beg   = (const float*)d_in[27];
    float* out = (float*)d_out;

    static bool init_done = false;
    static cudaStream_t s2, s3;
    static cudaEvent_t ev_fork, ev_join, ev_prep, ev_q, ev_hwt;
    if (!init_done) {
        cudaFuncSetAttribute((const void*)hmma_gemm<0,0>, cudaFuncAttributeMaxDynamicSharedMemorySize, HM_SMEM);
        cudaFuncSetAttribute((const void*)hmma_gemm<1,0>, cudaFuncAttributeMaxDynamicSharedMemorySize, HM_SMEM);
        cudaFuncSetAttribute((const void*)hmma_gemm<2,0>, cudaFuncAttributeMaxDynamicSharedMemorySize, HM_SMEM);
        cudaFuncSetAttribute((const void*)hmma_gemm<0,1>, cudaFuncAttributeMaxDynamicSharedMemorySize, HM_SMEM);
        cudaStreamCreateWithFlags(&s2, cudaStreamNonBlocking);
        cudaStreamCreateWithFlags(&s3, cudaStreamNonBlocking);
        cudaEventCreateWithFlags(&ev_fork, cudaEventDisableTiming);
        cudaEventCreateWithFlags(&ev_join, cudaEventDisableTiming);
        cudaEventCreateWithFlags(&ev_prep, cudaEventDisableTiming);
        cudaEventCreateWithFlags(&ev_q,    cudaEventDisableTiming);
        cudaEventCreateWithFlags(&ev_hwt,  cudaEventDisableTiming);
        init_done = true;
    }

    float *pk,*pv,*ph,*pdp,*pdh,*pgW1p,*pgW2p,*pgW1,*pgb1,*pgW2,*pgb2;
    float *pnW1,*pnb1,*pnW2,*pnb2,*ph2,*pctx,*pS,*paop,*pst,*pWT;
    bf16 *pxh,*pxl,*pWTh,*pWTl,*pWsth,*pWstl,*phh,*phl,*pqh,*pql;
    fp16 *phwTh,*phwTl,*pP;
    cudaGetSymbolAddress((void**)&pk,   g_k);
    cudaGetSymbolAddress((void**)&pv,   g_v);
    cudaGetSymbolAddress((void**)&ph,   g_h);
    cudaGetSymbolAddress((void**)&pdp,  g_dpred);
    cudaGetSymbolAddress((void**)&pdh,  g_dh);
    cudaGetSymbolAddress((void**)&pgW1p,g_gW1p);
    cudaGetSymbolAddress((void**)&pgW2p,g_gW2p);
    cudaGetSymbolAddress((void**)&pgW1, g_gW1);
    cudaGetSymbolAddress((void**)&pgb1, g_gb1);
    cudaGetSymbolAddress((void**)&pgW2, g_gW2);
    cudaGetSymbolAddress((void**)&pgb2, g_gb2);
    cudaGetSymbolAddress((void**)&pnW1, g_nW1);
    cudaGetSymbolAddress((void**)&pnb1, g_nb1);
    cudaGetSymbolAddress((void**)&pnW2, g_nW2);
    cudaGetSymbolAddress((void**)&pnb2, g_nb2);
    cudaGetSymbolAddress((void**)&ph2,  g_h2);
    cudaGetSymbolAddress((void**)&pctx, g_ctx);
    cudaGetSymbolAddress((void**)&pS,   g_S);
    cudaGetSymbolAddress((void**)&paop, g_aop);
    cudaGetSymbolAddress((void**)&pst,  g_st);
    cudaGetSymbolAddress((void**)&pWT,  g_WT);
    cudaGetSymbolAddress((void**)&pxh,  g_xh);
    cudaGetSymbolAddress((void**)&pxl,  g_xl);
    cudaGetSymbolAddress((void**)&pWTh, g_WTh);
    cudaGetSymbolAddress((void**)&pWTl, g_WTl);
    cudaGetSymbolAddress((void**)&pWsth,g_Wsth);
    cudaGetSymbolAddress((void**)&pWstl,g_Wstl);
    cudaGetSymbolAddress((void**)&phh,  g_histh);
    cudaGetSymbolAddress((void**)&phl,  g_histl);
    cudaGetSymbolAddress((void**)&phwTh,g_hwTh);
    cudaGetSymbolAddress((void**)&phwTl,g_hwTl);
    cudaGetSymbolAddress((void**)&pqh,  g_qh);
    cudaGetSymbolAddress((void**)&pql,  g_ql);
    cudaGetSymbolAddress((void**)&pP,   g_attnP);

    // fork streams
    cudaEventRecord(ev_fork, 0);
    cudaStreamWaitEvent(s2, ev_fork, 0);
    cudaStreamWaitEvent(s3, ev_fork, 0);

    // ===== stream s2: Titan memory chain + entity path (fp32 FFMA) =====
    gemm_abT<false,false,false><<<dim3(NKD/64, NB/64), 256, 0, s2>>>(
        x, W_K, nullptr, nullptr, 0.f, pk, NB, NKD, DIN);
    gemm_abT<false,false,false><<<dim3(NVD/64, NB/64), 256, 0, s2>>>(
        x, W_V, nullptr, nullptr, 0.f, pv, NB, NVD, DIN);
    gemm_abT<true,true,false><<<dim3(NHD/64, NB/64), 256, 0, s2>>>(
        pk, mW1, mb1, nullptr, 0.f, ph, NB, NHD, NKD);
    gemm_abT<true,false,true><<<dim3(NVD/64, NB/64), 256, 0, s2>>>(
        ph, mW2, mb2, pv, 2.f / (float)(NB*NVD), pdp, NB, NVD, NHD);
    gemm_aTb<<<dim3(NHD/64, NVD/64, NSPLIT_G), 256, 0, s2>>>(pdp, ph, pgW2p, NB, NVD, NHD, NB/NSPLIT_G);
    combine_k<<<(NVD*NHD + 255)/256, 256, 0, s2>>>(pgW2p, pgW2, NVD*NHD, NSPLIT_G);
    colsum_k<<<1, NVD, 0, s2>>>(pdp, pgb2, NB, NVD);
    gemm_ab<true><<<dim3(NHD/64, NB/64, 1), 256, 0, s2>>>(pdp, mW2, ph, pdh, NB, NHD, NVD, NVD);
    colsum_k<<<1, NHD, 0, s2>>>(pdh, pgb1, NB, NHD);
    gemm_aTb<<<dim3(NKD/64, NHD/64, NSPLIT_G), 256, 0, s2>>>(pdh, pk, pgW1p, NB, NHD, NKD, NB/NSPLIT_G);
    combine_k<<<(NHD*NKD + 255)/256, 256, 0, s2>>>(pgW1p, pgW1, NHD*NKD, NSPLIT_G);
    surprise_k<<<1, 256, 0, s2>>>();
    update_k<<<(NHD*NKD + NHD + NVD*NHD + NVD + 255)/256, 256, 0, s2>>>(
        mW1, mb1, mW2, mb2, bufW1, bufb1, bufW2, bufb2);
    gemm_abT<true,true,false><<<dim3(NHD/64, NB/64), 256, 0, s2>>>(
        pk, pnW1, pnb1, nullptr, 0.f, ph2, NB, NHD, NKD);
    gemm_abT<true,false,false><<<dim3(NVD/64, NB/64), 256, 0, s2>>>(
        ph2, pnW2, pnb2, nullptr, 0.f, pctx, NB, NVD, NHD);
    entity_k<<<1, DIN, 0, s2>>>(ent, Wep, bep, Weg, beg);
    cudaEventRecord(ev_join, s2);

    // ===== stream0: splits (x, Wst, hist) =====
    split_k<<<(NB*DIN + 255)/256, 256>>>(x,    pxh,  pxl,  NB*DIN);
    split_k<<<(NVD*DIN + 255)/256, 256>>>(Wst, pWsth,pWstl,NVD*DIN);
    split_k<<<(NH*DIN + 255)/256, 256>>>(hist, phh,  phl,  NH*DIN);
    cudaEventRecord(ev_prep, 0);

    // ===== stream s3: W' gemm + split, q', hwT (overlap with S) =====
    gemm_aTb<<<dim3(DIN/64, DIN/64, 1), 256, 0, s3>>>(Wk, Wq, pWT, DIN, DIN, DIN, DIN);
    split_k<<<(DIN*DIN + 255)/256, 256, 0, s3>>>(pWT, pWTh, pWTl, DIN*DIN);
    cudaStreamWaitEvent(s3, ev_prep, 0);
    // q' = x @ W'  -> split bf16
    hmma_gemm<1,0><<<dim3(DIN/128, NB/128, 1), 512, HM_SMEM, s3>>>(
        pxh, pxl, pWTh, pWTl, nullptr, (unsigned short*)pqh, (unsigned short*)pql, NB, DIN, DIN, DIN);
    cudaEventRecord(ev_q, s3);
    // hwT = Wst @ hist^T -> fp16 split, [NVD, NH]
    hmma_gemm<2,0><<<dim3(NH/128, NVD/128, 1), 512, HM_SMEM, s3>>>(
        pWsth, pWstl, phh, phl, nullptr, (unsigned short*)phwTh, (unsigned short*)phwTl, NVD, NH, DIN, DIN);
    cudaEventRecord(ev_hwt, s3);

    // ===== stream0: S = q' @ hist^T (bf16 3-term) =====
    cudaStreamWaitEvent(0, ev_q, 0);
    hmma_gemm<0,0><<<dim3(NH/128, NB/128, 1), 512, HM_SMEM>>>(
        pqh, pql, phh, phl, pS, nullptr, nullptr, NB, NH, DIN, DIN);
    softmax_k<<<NB, 256>>>();
    // st(raw) = P @ hwT^T (fp16 2-term, A unsplit), split-K slabs + combine
    cudaStreamWaitEvent(0, ev_hwt, 0);
    hmma_gemm<0,1><<<dim3(NVD/128, NB/128, NSPLIT_AH), 512, HM_SMEM>>>(
        (const bf16*)pP, (const bf16*)pP, (const bf16*)phwTh, (const bf16*)phwTl,
        paop, nullptr, nullptr, NB, NVD, NH, NH/NSPLIT_AH);
    combine_k<<<(NB*NVD + 255)/256, 256>>>(paop, pst, NB*NVD, NSPLIT_AH);

    // join + fuse
    cudaStreamWaitEvent(0, ev_join, 0);
    fuse_k<<<NB, NVD>>>(kvec, Wg, bg, bst, out);
}